// round 14
// baseline (speedup 1.0000x reference)
#include <cuda_runtime.h>
#include <cuda_fp16.h>
#include <cstdint>
#include <math.h>

#define NN     10000
#define EE     320000
#define NE     (EE + NN)     // with self loops
#define NFEAT  512
#define NHID1  256
#define NHID2  64
#define H1     128           // 2*nhid2
#define NEG_SLOPE 0.2f
#define BN_EPS 1e-5f

// output layout (flattened tuple: emb, re_x, readj, mu, logvar)
#define EMB_OFF   ((size_t)0)
#define REX_OFF   ((size_t)NN * NHID2)
#define READJ_OFF (REX_OFF + (size_t)NN * NFEAT)
#define MU_OFF    (READJ_OFF + (size_t)NN * NN)
#define LV_OFF    (MU_OFF + (size_t)NN * NHID2)

typedef unsigned long long u64;

// ---------------- warp MMA helpers (baseline PTX, works on sm_103) --------
__device__ __forceinline__ uint32_t smem_u32(const void* p) {
    uint32_t a;
    asm("{ .reg .u64 t; cvta.to.shared.u64 t, %1; cvt.u32.u64 %0, t; }" : "=r"(a) : "l"(p));
    return a;
}
__device__ __forceinline__ void ldsm_x4(uint32_t& r0, uint32_t& r1, uint32_t& r2, uint32_t& r3, uint32_t addr) {
    asm volatile("ldmatrix.sync.aligned.m8n8.x4.shared.b16 {%0,%1,%2,%3}, [%4];"
                 : "=r"(r0), "=r"(r1), "=r"(r2), "=r"(r3) : "r"(addr));
}
__device__ __forceinline__ void ldsm_x2(uint32_t& r0, uint32_t& r1, uint32_t addr) {
    asm volatile("ldmatrix.sync.aligned.m8n8.x2.shared.b16 {%0,%1}, [%2];"
                 : "=r"(r0), "=r"(r1) : "r"(addr));
}
__device__ __forceinline__ void mma_f16(float* d, uint32_t a0, uint32_t a1, uint32_t a2, uint32_t a3,
                                        uint32_t b0, uint32_t b1) {
    asm volatile("mma.sync.aligned.m16n8k16.row.col.f32.f16.f16.f32 "
                 "{%0,%1,%2,%3}, {%4,%5,%6,%7}, {%8,%9}, {%0,%1,%2,%3};"
                 : "+f"(d[0]), "+f"(d[1]), "+f"(d[2]), "+f"(d[3])
                 : "r"(a0), "r"(a1), "r"(a2), "r"(a3), "r"(b0), "r"(b1));
}
__device__ __forceinline__ void f16split(float v, uint16_t& h, uint16_t& l) {
    __half hb = __float2half_rn(v);
    __half lb = __float2half_rn(v - __half2float(hb));
    h = __half_as_ushort(hb);
    l = __half_as_ushort(lb);
}
__device__ __forceinline__ uint16_t f16h(float v) {
    return __half_as_ushort(__float2half_rn(v));
}
__device__ __forceinline__ float4 h4_to_f4(uint2 u) {
    __half2 a = *(__half2*)&u.x;
    __half2 b = *(__half2*)&u.y;
    float2 fa = __half22float2(a);
    float2 fb = __half22float2(b);
    return make_float4(fa.x, fa.y, fb.x, fb.y);
}

// ---------------- scratch (device globals; no allocation allowed) ----------
__device__ uint16_t g_xl1h[NN * H1];    // fp16 layer-1 outputs (GAT1 only)
__device__ uint16_t g_xr1h[NN * H1];
__device__ float g_h  [NN * H1];
__device__ uint16_t g_x23h[NN * 256];   // fp16 packed: xl2|xr2|xl3|xr3
__device__ float g_d  [NN * NHID1];
__device__ int   g_deg[NN];
__device__ int   g_rowptr[NN + 1];
__device__ int   g_cursor[NN];
__device__ int   g_srclist[NE];
__device__ float g_mean[NHID1];
__device__ float g_rstd[NHID1];
__device__ float g_bias23[256];
// emb fp16 hi/lo (pre-split for gram + decoder GEMM)
__device__ uint16_t g_ebh[NN * NHID2], g_ebl[NN * NHID2];
// transposed fp16 weights [Nc][K]
__device__ uint16_t g_w1lh[H1 * NFEAT];
__device__ uint16_t g_w1rh[H1 * NFEAT];
__device__ uint16_t g_w23h[256 * H1];
__device__ uint16_t g_dw1h[NHID1 * NHID2];
__device__ uint16_t g_dw2h[NFEAT * NHID1];

// ---------------- CSR build ----------------
__global__ void k_zero_counts() {
    int i = blockIdx.x * blockDim.x + threadIdx.x;
    if (i < NN) { g_deg[i] = 0; g_cursor[i] = 0; }
}

__global__ void k_count_deg(const int* __restrict__ edge_index) {
    int i = blockIdx.x * blockDim.x + threadIdx.x;
    if (i >= NE) return;
    int tgt = (i < EE) ? edge_index[EE + i] : (i - EE);
    atomicAdd(&g_deg[tgt], 1);
}

__global__ void k_scan_deg() {
    __shared__ int wsum[32];
    __shared__ int sc;
    int tid = threadIdx.x, lane = tid & 31, w = tid >> 5;
    if (tid == 0) { sc = 0; g_rowptr[0] = 0; }
    __syncthreads();
    for (int base = 0; base < NN; base += 1024) {
        int i = base + tid;
        int v = (i < NN) ? g_deg[i] : 0;
        int x = v;
#pragma unroll
        for (int o = 1; o < 32; o <<= 1) {
            int t = __shfl_up_sync(0xffffffffu, x, o);
            if (lane >= o) x += t;
        }
        if (lane == 31) wsum[w] = x;
        __syncthreads();
        if (w == 0) {
            int y = wsum[lane];
#pragma unroll
            for (int o = 1; o < 32; o <<= 1) {
                int t = __shfl_up_sync(0xffffffffu, y, o);
                if (lane >= o) y += t;
            }
            wsum[lane] = y;
        }
        __syncthreads();
        int pre = (w > 0) ? wsum[w - 1] : 0;
        int c = sc;
        if (i < NN) g_rowptr[i + 1] = c + pre + x;
        int total = wsum[31];
        __syncthreads();
        if (tid == 0) sc = c + total;
        __syncthreads();
    }
}

__global__ void k_fill_list(const int* __restrict__ edge_index) {
    int i = blockIdx.x * blockDim.x + threadIdx.x;
    if (i >= NE) return;
    int src, tgt;
    if (i < EE) { src = edge_index[i]; tgt = edge_index[EE + i]; }
    else        { src = i - EE;        tgt = i - EE; }
    int pos = atomicAdd(&g_cursor[tgt], 1);
    g_srclist[g_rowptr[tgt] + pos] = src;
}

// ---------------- fused prep: all weight transposes + bias pack -----------
#define P_S01 (H1 * NFEAT)
#define P_S2  (256 * H1)
#define P_S3  (NHID1 * NHID2)
#define P_S4  (NFEAT * NHID1)
#define P_TOT (P_S01 + P_S2 + P_S3 + P_S4 + 256)

__global__ void k_prep(const float* __restrict__ w1l, const float* __restrict__ w1r,
                       const float* __restrict__ w2l, const float* __restrict__ w2r,
                       const float* __restrict__ w3l, const float* __restrict__ w3r,
                       const float* __restrict__ dw1, const float* __restrict__ dw2,
                       const float* __restrict__ b2l, const float* __restrict__ b2r,
                       const float* __restrict__ b3l, const float* __restrict__ b3r) {
    int i = blockIdx.x * blockDim.x + threadIdx.x;
    if (i < P_S01) {
        int n = i / NFEAT, k = i - n * NFEAT;
        g_w1lh[i] = f16h(w1l[(size_t)k * H1 + n]);
        g_w1rh[i] = f16h(w1r[(size_t)k * H1 + n]);
        return;
    }
    i -= P_S01;
    if (i < P_S2) {
        int np = i >> 7, k = i & 127;
        int jj = np >> 6, n = np & 63;
        const float* W = (jj == 0) ? w2l : (jj == 1) ? w2r : (jj == 2) ? w3l : w3r;
        g_w23h[i] = f16h(W[(size_t)k * 64 + n]);
        return;
    }
    i -= P_S2;
    if (i < P_S3) {
        int n = i / NHID2, k = i - n * NHID2;
        g_dw1h[i] = f16h(dw1[(size_t)k * NHID1 + n]);
        return;
    }
    i -= P_S3;
    if (i < P_S4) {
        int n = i / NHID1, k = i - n * NHID1;
        g_dw2h[i] = f16h(dw2[(size_t)k * NFEAT + n]);
        return;
    }
    i -= P_S4;
    if (i < 256) {
        int jj = i >> 6, n = i & 63;
        const float* b = (jj == 0) ? b2l : (jj == 1) ? b2r : (jj == 2) ? b3l : b3r;
        g_bias23[i] = b[n];
    }
}

// ---------------- GEMM job plumbing ----------------
struct TJob  { const uint16_t* Bh; const float* bias; float* C; };
struct TJobs { TJob j[2]; };

// ---------------- gemmT: fp16 2-pass HMMA GEMM, 128x128 tile, fp32 out ---
__global__ __launch_bounds__(256)
void gemmT(const float* __restrict__ A, TJobs jobs, int M, int K, int Nc,
           const float* __restrict__ bnG, const float* __restrict__ bnB) {
    const TJob jb = jobs.j[blockIdx.z];
    __shared__ __align__(16) uint16_t Ah[128][40], Al[128][40];
    __shared__ __align__(16) uint16_t Bh[128][40];
    int tid = threadIdx.x, lane = tid & 31, warp = tid >> 5;
    int row0 = blockIdx.y * 128, col0 = blockIdx.x * 128;
    int wm = (warp & 1) * 64, wn = (warp >> 1) * 32;
    int grp = lane >> 3, rl = lane & 7;
    float c[4][4][4];
#pragma unroll
    for (int mi = 0; mi < 4; mi++)
#pragma unroll
        for (int ni = 0; ni < 4; ni++)
#pragma unroll
            for (int e = 0; e < 4; e++) c[mi][ni][e] = 0.f;

    int ar = tid >> 1, kh = (tid & 1) * 16;
    int r = row0 + ar;
    bool va = r < M;

    for (int k0 = 0; k0 < K; k0 += 32) {
        const float* pa = A + (size_t)r * K + k0 + kh;
#pragma unroll
        for (int q = 0; q < 4; q++) {
            float4 v = va ? *(const float4*)(pa + q * 4) : make_float4(0.f, 0.f, 0.f, 0.f);
            if (bnG) {
                int ch = k0 + kh + q * 4;
                float4 mm = *(const float4*)(g_mean + ch);
                float4 rs = *(const float4*)(g_rstd + ch);
                float4 gg = *(const float4*)(bnG + ch);
                float4 bb = *(const float4*)(bnB + ch);
                v.x = fmaxf((v.x - mm.x) * rs.x * gg.x + bb.x, 0.f);
                v.y = fmaxf((v.y - mm.y) * rs.y * gg.y + bb.y, 0.f);
                v.z = fmaxf((v.z - mm.z) * rs.z * gg.z + bb.z, 0.f);
                v.w = fmaxf((v.w - mm.w) * rs.w * gg.w + bb.w, 0.f);
            }
            uint16_t h0, l0, h1, l1, h2, l2, h3, l3;
            f16split(v.x, h0, l0); f16split(v.y, h1, l1);
            f16split(v.z, h2, l2); f16split(v.w, h3, l3);
            *(uint32_t*)&Ah[ar][kh + q * 4]     = (uint32_t)h0 | ((uint32_t)h1 << 16);
            *(uint32_t*)&Ah[ar][kh + q * 4 + 2] = (uint32_t)h2 | ((uint32_t)h3 << 16);
            *(uint32_t*)&Al[ar][kh + q * 4]     = (uint32_t)l0 | ((uint32_t)l1 << 16);
            *(uint32_t*)&Al[ar][kh + q * 4 + 2] = (uint32_t)l2 | ((uint32_t)l3 << 16);
        }
        {
            const uint16_t* pbh = jb.Bh + (size_t)(col0 + ar) * K + k0 + kh;
            *(uint4*)&Bh[ar][kh]     = *(const uint4*)pbh;
            *(uint4*)&Bh[ar][kh + 8] = *(const uint4*)(pbh + 8);
        }
        __syncthreads();
#pragma unroll
        for (int pass = 0; pass < 2; pass++) {
            const uint16_t (*Aq)[40] = (pass == 1) ? Al : Ah;
#pragma unroll
            for (int k1 = 0; k1 < 32; k1 += 16) {
                uint32_t af[4][4], bf[4][2];
#pragma unroll
                for (int mi = 0; mi < 4; mi++) {
                    int arow = wm + mi * 16 + (grp & 1) * 8 + rl;
                    int acol = k1 + (grp >> 1) * 8;
                    ldsm_x4(af[mi][0], af[mi][1], af[mi][2], af[mi][3],
                            smem_u32(&Aq[arow][acol]));
                }
#pragma unroll
                for (int ni = 0; ni < 4; ni++) {
                    int brow = wn + ni * 8 + rl;
                    int bcol = k1 + (grp & 1) * 8;
                    ldsm_x2(bf[ni][0], bf[ni][1], smem_u32(&Bh[brow][bcol]));
                }
#pragma unroll
                for (int mi = 0; mi < 4; mi++)
#pragma unroll
                    for (int ni = 0; ni < 4; ni++)
                        mma_f16(c[mi][ni], af[mi][0], af[mi][1], af[mi][2], af[mi][3],
                                bf[ni][0], bf[ni][1]);
            }
        }
        __syncthreads();
    }
    int qr = lane >> 2, qc = 2 * (lane & 3);
#pragma unroll
    for (int mi = 0; mi < 4; mi++) {
#pragma unroll
        for (int half = 0; half < 2; half++) {
            int row = wm + mi * 16 + qr + half * 8;
            int rr = row0 + row;
            if (rr < M) {
                float* Crow = jb.C + (size_t)rr * Nc;
#pragma unroll
                for (int ni = 0; ni < 4; ni++) {
                    int cc = col0 + wn + ni * 8 + qc;
                    float2 p;
                    p.x = c[mi][ni][2 * half]     + __ldg(&jb.bias[cc]);
                    p.y = c[mi][ni][2 * half + 1] + __ldg(&jb.bias[cc + 1]);
                    *(float2*)&Crow[cc] = p;
                }
            }
        }
    }
}

// ---------------- gemmTh: same but fp16 OUTPUT (for x23) ------------------
__global__ __launch_bounds__(256)
void gemmTh(const float* __restrict__ A, TJobs jobs, int M, int K, int Nc,
            const float* __restrict__ bnG, const float* __restrict__ bnB) {
    const TJob jb = jobs.j[blockIdx.z];
    __shared__ __align__(16) uint16_t Ah[128][40], Al[128][40];
    __shared__ __align__(16) uint16_t Bh[128][40];
    int tid = threadIdx.x, lane = tid & 31, warp = tid >> 5;
    int row0 = blockIdx.y * 128, col0 = blockIdx.x * 128;
    int wm = (warp & 1) * 64, wn = (warp >> 1) * 32;
    int grp = lane >> 3, rl = lane & 7;
    float c[4][4][4];
#pragma unroll
    for (int mi = 0; mi < 4; mi++)
#pragma unroll
        for (int ni = 0; ni < 4; ni++)
#pragma unroll
            for (int e = 0; e < 4; e++) c[mi][ni][e] = 0.f;

    int ar = tid >> 1, kh = (tid & 1) * 16;
    int r = row0 + ar;
    bool va = r < M;

    for (int k0 = 0; k0 < K; k0 += 32) {
        const float* pa = A + (size_t)r * K + k0 + kh;
#pragma unroll
        for (int q = 0; q < 4; q++) {
            float4 v = va ? *(const float4*)(pa + q * 4) : make_float4(0.f, 0.f, 0.f, 0.f);
            if (bnG) {
                int ch = k0 + kh + q * 4;
                float4 mm = *(const float4*)(g_mean + ch);
                float4 rs = *(const float4*)(g_rstd + ch);
                float4 gg = *(const float4*)(bnG + ch);
                float4 bb = *(const float4*)(bnB + ch);
                v.x = fmaxf((v.x - mm.x) * rs.x * gg.x + bb.x, 0.f);
                v.y = fmaxf((v.y - mm.y) * rs.y * gg.y + bb.y, 0.f);
                v.z = fmaxf((v.z - mm.z) * rs.z * gg.z + bb.z, 0.f);
                v.w = fmaxf((v.w - mm.w) * rs.w * gg.w + bb.w, 0.f);
            }
            uint16_t h0, l0, h1, l1, h2, l2, h3, l3;
            f16split(v.x, h0, l0); f16split(v.y, h1, l1);
            f16split(v.z, h2, l2); f16split(v.w, h3, l3);
            *(uint32_t*)&Ah[ar][kh + q * 4]     = (uint32_t)h0 | ((uint32_t)h1 << 16);
            *(uint32_t*)&Ah[ar][kh + q * 4 + 2] = (uint32_t)h2 | ((uint32_t)h3 << 16);
            *(uint32_t*)&Al[ar][kh + q * 4]     = (uint32_t)l0 | ((uint32_t)l1 << 16);
            *(uint32_t*)&Al[ar][kh + q * 4 + 2] = (uint32_t)l2 | ((uint32_t)l3 << 16);
        }
        {
            const uint16_t* pbh = jb.Bh + (size_t)(col0 + ar) * K + k0 + kh;
            *(uint4*)&Bh[ar][kh]     = *(const uint4*)pbh;
            *(uint4*)&Bh[ar][kh + 8] = *(const uint4*)(pbh + 8);
        }
        __syncthreads();
#pragma unroll
        for (int pass = 0; pass < 2; pass++) {
            const uint16_t (*Aq)[40] = (pass == 1) ? Al : Ah;
#pragma unroll
            for (int k1 = 0; k1 < 32; k1 += 16) {
                uint32_t af[4][4], bf[4][2];
#pragma unroll
                for (int mi = 0; mi < 4; mi++) {
                    int arow = wm + mi * 16 + (grp & 1) * 8 + rl;
                    int acol = k1 + (grp >> 1) * 8;
                    ldsm_x4(af[mi][0], af[mi][1], af[mi][2], af[mi][3],
                            smem_u32(&Aq[arow][acol]));
                }
#pragma unroll
                for (int ni = 0; ni < 4; ni++) {
                    int brow = wn + ni * 8 + rl;
                    int bcol = k1 + (grp & 1) * 8;
                    ldsm_x2(bf[ni][0], bf[ni][1], smem_u32(&Bh[brow][bcol]));
                }
#pragma unroll
                for (int mi = 0; mi < 4; mi++)
#pragma unroll
                    for (int ni = 0; ni < 4; ni++)
                        mma_f16(c[mi][ni], af[mi][0], af[mi][1], af[mi][2], af[mi][3],
                                bf[ni][0], bf[ni][1]);
            }
        }
        __syncthreads();
    }
    int qr = lane >> 2, qc = 2 * (lane & 3);
#pragma unroll
    for (int mi = 0; mi < 4; mi++) {
#pragma unroll
        for (int half = 0; half < 2; half++) {
            int row = wm + mi * 16 + qr + half * 8;
            int rr = row0 + row;
            if (rr < M) {
                uint16_t* Crow = (uint16_t*)jb.C + (size_t)rr * Nc;
#pragma unroll
                for (int ni = 0; ni < 4; ni++) {
                    int cc = col0 + wn + ni * 8 + qc;
                    uint16_t p0 = f16h(c[mi][ni][2 * half]     + __ldg(&jb.bias[cc]));
                    uint16_t p1 = f16h(c[mi][ni][2 * half + 1] + __ldg(&jb.bias[cc + 1]));
                    *(uint32_t*)&Crow[cc] = (uint32_t)p0 | ((uint32_t)p1 << 16);
                }
            }
        }
    }
}

// ---------------- gemmT64h: 64x128 tile, fp16 OUTPUT (for GAT1 operands) --
__global__ __launch_bounds__(256)
void gemmT64h(const float* __restrict__ A, TJobs jobs, int M, int K, int Nc) {
    const TJob jb = jobs.j[blockIdx.z];
    __shared__ __align__(16) uint16_t Ah[64][40], Al[64][40];
    __shared__ __align__(16) uint16_t Bh[128][40];
    int tid = threadIdx.x, lane = tid & 31, warp = tid >> 5;
    int row0 = blockIdx.y * 64, col0 = blockIdx.x * 128;
    int wm = (warp & 1) * 32, wn = (warp >> 1) * 32;
    int grp = lane >> 3, rl = lane & 7;
    float c[2][4][4];
#pragma unroll
    for (int mi = 0; mi < 2; mi++)
#pragma unroll
        for (int ni = 0; ni < 4; ni++)
#pragma unroll
            for (int e = 0; e < 4; e++) c[mi][ni][e] = 0.f;

    int ar = tid >> 2, ks = (tid & 3) * 8;
    int br = tid >> 1, kb = (tid & 1) * 16;
    int r = row0 + ar;
    bool va = r < M;

    for (int k0 = 0; k0 < K; k0 += 32) {
        const float* pa = A + (size_t)r * K + k0 + ks;
#pragma unroll
        for (int q = 0; q < 2; q++) {
            float4 v = va ? *(const float4*)(pa + q * 4) : make_float4(0.f, 0.f, 0.f, 0.f);
            uint16_t h0, l0, h1, l1, h2, l2, h3, l3;
            f16split(v.x, h0, l0); f16split(v.y, h1, l1);
            f16split(v.z, h2, l2); f16split(v.w, h3, l3);
            *(uint32_t*)&Ah[ar][ks + q * 4]     = (uint32_t)h0 | ((uint32_t)h1 << 16);
            *(uint32_t*)&Ah[ar][ks + q * 4 + 2] = (uint32_t)h2 | ((uint32_t)h3 << 16);
            *(uint32_t*)&Al[ar][ks + q * 4]     = (uint32_t)l0 | ((uint32_t)l1 << 16);
            *(uint32_t*)&Al[ar][ks + q * 4 + 2] = (uint32_t)l2 | ((uint32_t)l3 << 16);
        }
        {
            const uint16_t* pbh = jb.Bh + (size_t)(col0 + br) * K + k0 + kb;
            *(uint4*)&Bh[br][kb]     = *(const uint4*)pbh;
            *(uint4*)&Bh[br][kb + 8] = *(const uint4*)(pbh + 8);
        }
        __syncthreads();
#pragma unroll
        for (int pass = 0; pass < 2; pass++) {
            const uint16_t (*Aq)[40] = (pass == 1) ? Al : Ah;
#pragma unroll
            for (int k1 = 0; k1 < 32; k1 += 16) {
                uint32_t af[2][4], bf[4][2];
#pragma unroll
                for (int mi = 0; mi < 2; mi++) {
                    int arow = wm + mi * 16 + (grp & 1) * 8 + rl;
                    int acol = k1 + (grp >> 1) * 8;
                    ldsm_x4(af[mi][0], af[mi][1], af[mi][2], af[mi][3],
                            smem_u32(&Aq[arow][acol]));
                }
#pragma unroll
                for (int ni = 0; ni < 4; ni++) {
                    int brow = wn + ni * 8 + rl;
                    int bcol = k1 + (grp & 1) * 8;
                    ldsm_x2(bf[ni][0], bf[ni][1], smem_u32(&Bh[brow][bcol]));
                }
#pragma unroll
                for (int mi = 0; mi < 2; mi++)
#pragma unroll
                    for (int ni = 0; ni < 4; ni++)
                        mma_f16(c[mi][ni], af[mi][0], af[mi][1], af[mi][2], af[mi][3],
                                bf[ni][0], bf[ni][1]);
            }
        }
        __syncthreads();
    }
    int qr = lane >> 2, qc = 2 * (lane & 3);
#pragma unroll
    for (int mi = 0; mi < 2; mi++) {
#pragma unroll
        for (int half = 0; half < 2; half++) {
            int row = wm + mi * 16 + qr + half * 8;
            int rr = row0 + row;
            if (rr < M) {
                uint16_t* Crow = (uint16_t*)jb.C + (size_t)rr * Nc;
#pragma unroll
                for (int ni = 0; ni < 4; ni++) {
                    int cc = col0 + wn + ni * 8 + qc;
                    uint16_t p0 = f16h(c[mi][ni][2 * half]     + __ldg(&jb.bias[cc]));
                    uint16_t p1 = f16h(c[mi][ni][2 * half + 1] + __ldg(&jb.bias[cc + 1]));
                    *(uint32_t*)&Crow[cc] = (uint32_t)p0 | ((uint32_t)p1 << 16);
                }
            }
        }
    }
}

// ---------------- gemmP: pre-split fp16 A (hi/lo), 128x128 tile ----------
__global__ __launch_bounds__(256)
void gemmP(const uint16_t* __restrict__ Ahg, const uint16_t* __restrict__ Alg,
           const uint16_t* __restrict__ Bhg, const float* __restrict__ bias,
           float* __restrict__ C, int M, int K, int Nc) {
    __shared__ __align__(16) uint16_t Ah[128][40], Al[128][40];
    __shared__ __align__(16) uint16_t Bh[128][40];
    int tid = threadIdx.x, lane = tid & 31, warp = tid >> 5;
    int row0 = blockIdx.y * 128, col0 = blockIdx.x * 128;
    int wm = (warp & 1) * 64, wn = (warp >> 1) * 32;
    int grp = lane >> 3, rl = lane & 7;
    float c[4][4][4];
#pragma unroll
    for (int mi = 0; mi < 4; mi++)
#pragma unroll
        for (int ni = 0; ni < 4; ni++)
#pragma unroll
            for (int e = 0; e < 4; e++) c[mi][ni][e] = 0.f;

    int ar = tid >> 1, kh = (tid & 1) * 16;
    int r = row0 + ar;
    bool va = r < M;
    uint4 z4 = make_uint4(0, 0, 0, 0);

    for (int k0 = 0; k0 < K; k0 += 32) {
        {
            const uint16_t* ph = Ahg + (size_t)r * K + k0 + kh;
            const uint16_t* pl = Alg + (size_t)r * K + k0 + kh;
            *(uint4*)&Ah[ar][kh]     = va ? *(const uint4*)ph : z4;
            *(uint4*)&Ah[ar][kh + 8] = va ? *(const uint4*)(ph + 8) : z4;
            *(uint4*)&Al[ar][kh]     = va ? *(const uint4*)pl : z4;
            *(uint4*)&Al[ar][kh + 8] = va ? *(const uint4*)(pl + 8) : z4;
        }
        {
            const uint16_t* pbh = Bhg + (size_t)(col0 + ar) * K + k0 + kh;
            *(uint4*)&Bh[ar][kh]     = *(const uint4*)pbh;
            *(uint4*)&Bh[ar][kh + 8] = *(const uint4*)(pbh + 8);
        }
        __syncthreads();
#pragma unroll
        for (int pass = 0; pass < 2; pass++) {
            const uint16_t (*Aq)[40] = (pass == 1) ? Al : Ah;
#pragma unroll
            for (int k1 = 0; k1 < 32; k1 += 16) {
                uint32_t af[4][4], bf[4][2];
#pragma unroll
                for (int mi = 0; mi < 4; mi++) {
                    int arow = wm + mi * 16 + (grp & 1) * 8 + rl;
                    int acol = k1 + (grp >> 1) * 8;
                    ldsm_x4(af[mi][0], af[mi][1], af[mi][2], af[mi][3],
                            smem_u32(&Aq[arow][acol]));
                }
#pragma unroll
                for (int ni = 0; ni < 4; ni++) {
                    int brow = wn + ni * 8 + rl;
                    int bcol = k1 + (grp & 1) * 8;
                    ldsm_x2(bf[ni][0], bf[ni][1], smem_u32(&Bh[brow][bcol]));
                }
#pragma unroll
                for (int mi = 0; mi < 4; mi++)
#pragma unroll
                    for (int ni = 0; ni < 4; ni++)
                        mma_f16(c[mi][ni], af[mi][0], af[mi][1], af[mi][2], af[mi][3],
                                bf[ni][0], bf[ni][1]);
            }
        }
        __syncthreads();
    }
    int qr = lane >> 2, qc = 2 * (lane & 3);
#pragma unroll
    for (int mi = 0; mi < 4; mi++) {
#pragma unroll
        for (int half = 0; half < 2; half++) {
            int row = wm + mi * 16 + qr + half * 8;
            int rr = row0 + row;
            if (rr < M) {
                float* Crow = C + (size_t)rr * Nc;
#pragma unroll
                for (int ni = 0; ni < 4; ni++) {
                    int cc = col0 + wn + ni * 8 + qc;
                    float2 p;
                    p.x = c[mi][ni][2 * half]     + __ldg(&bias[cc]);
                    p.y = c[mi][ni][2 * half + 1] + __ldg(&bias[cc + 1]);
                    *(float2*)&Crow[cc] = p;
                }
            }
        }
    }
}

// ---------------- GAT layer 1: fused online-softmax, fp16 operands --------
__global__ void gat1_fused(const uint16_t* __restrict__ xlh,
                           const uint16_t* __restrict__ xrh,
                           const float* __restrict__ att, const float* __restrict__ bias,
                           float* __restrict__ out) {
    int t = blockIdx.x;
    int tid = threadIdx.x, lane = tid & 31, warp = tid >> 5;

    __shared__ float4 s_xr4[32], s_att4[32];
    __shared__ float  s_m[4], s_s[4];
    __shared__ float4 s_acc[4][32];
    if (tid < 32) {
        uint2 u = *(const uint2*)(xrh + (size_t)t * H1 + tid * 4);
        s_xr4[tid]  = h4_to_f4(u);
        s_att4[tid] = *(const float4*)(att + tid * 4);
    }
    int beg = g_rowptr[t];
    int deg = g_rowptr[t + 1] - beg;
    __syncthreads();

    float4 xr4 = s_xr4[lane];
    float4 at4 = s_att4[lane];

    float m0 = -1e30f, z0 = 0.f;
    float m1 = -1e30f, z1 = 0.f;
    float4 a0 = make_float4(0.f, 0.f, 0.f, 0.f), a1 = a0;

    int j = warp;
    for (; j + 4 < deg; j += 8) {
        int sA = g_srclist[beg + j];
        int sB = g_srclist[beg + j + 4];
        float4 vA = h4_to_f4(*(const uint2*)(xlh + (size_t)sA * H1 + lane * 4));
        float4 vB = h4_to_f4(*(const uint2*)(xlh + (size_t)sB * H1 + lane * 4));
        float pA, pB;
        {
            float a = vA.x + xr4.x; a = fmaxf(a, NEG_SLOPE * a);
            float b = vA.y + xr4.y; b = fmaxf(b, NEG_SLOPE * b);
            float c = vA.z + xr4.z; c = fmaxf(c, NEG_SLOPE * c);
            float d = vA.w + xr4.w; d = fmaxf(d, NEG_SLOPE * d);
            pA = at4.x * a + at4.y * b + at4.z * c + at4.w * d;
            a = vB.x + xr4.x; a = fmaxf(a, NEG_SLOPE * a);
            b = vB.y + xr4.y; b = fmaxf(b, NEG_SLOPE * b);
            c = vB.z + xr4.z; c = fmaxf(c, NEG_SLOPE * c);
            d = vB.w + xr4.w; d = fmaxf(d, NEG_SLOPE * d);
            pB = at4.x * a + at4.y * b + at4.z * c + at4.w * d;
        }
#pragma unroll
        for (int o = 16; o; o >>= 1) {
            pA += __shfl_xor_sync(0xffffffffu, pA, o);
            pB += __shfl_xor_sync(0xffffffffu, pB, o);
        }
        float mn0 = fmaxf(m0, pA);
        float sc0 = __expf(m0 - mn0);
        float w0  = __expf(pA - mn0);
        z0 = z0 * sc0 + w0;
        a0.x = a0.x * sc0 + w0 * vA.x;
        a0.y = a0.y * sc0 + w0 * vA.y;
        a0.z = a0.z * sc0 + w0 * vA.z;
        a0.w = a0.w * sc0 + w0 * vA.w;
        m0 = mn0;
        float mn1 = fmaxf(m1, pB);
        float sc1 = __expf(m1 - mn1);
        float w1  = __expf(pB - mn1);
        z1 = z1 * sc1 + w1;
        a1.x = a1.x * sc1 + w1 * vB.x;
        a1.y = a1.y * sc1 + w1 * vB.y;
        a1.z = a1.z * sc1 + w1 * vB.z;
        a1.w = a1.w * sc1 + w1 * vB.w;
        m1 = mn1;
    }
    if (j < deg) {
        int sA = g_srclist[beg + j];
        float4 vA = h4_to_f4(*(const uint2*)(xlh + (size_t)sA * H1 + lane * 4));
        float a = vA.x + xr4.x; a = fmaxf(a, NEG_SLOPE * a);
        float b = vA.y + xr4.y; b = fmaxf(b, NEG_SLOPE * b);
        float c = vA.z + xr4.z; c = fmaxf(c, NEG_SLOPE * c);
        float d = vA.w + xr4.w; d = fmaxf(d, NEG_SLOPE * d);
        float pA = at4.x * a + at4.y * b + at4.z * c + at4.w * d;
#pragma unroll
        for (int o = 16; o; o >>= 1) pA += __shfl_xor_sync(0xffffffffu, pA, o);
        float mn0 = fmaxf(m0, pA);
        float sc0 = __expf(m0 - mn0);
        float w0  = __expf(pA - mn0);
        z0 = z0 * sc0 + w0;
        a0.x = a0.x * sc0 + w0 * vA.x;
        a0.y = a0.y * sc0 + w0 * vA.y;
        a0.z = a0.z * sc0 + w0 * vA.z;
        a0.w = a0.w * sc0 + w0 * vA.w;
        m0 = mn0;
    }
    {
        float M = fmaxf(m0, m1);
        float e0 = __expf(m0 - M), e1 = __expf(m1 - M);
        z0 = z0 * e0 + z1 * e1;
        a0.x = a0.x * e0 + a1.x * e1;
        a0.y = a0.y * e0 + a1.y * e1;
        a0.z = a0.z * e0 + a1.z * e1;
        a0.w = a0.w * e0 + a1.w * e1;
        m0 = M;
    }
    if (lane == 0) { s_m[warp] = m0; s_s[warp] = z0; }
    s_acc[warp][lane] = a0;
    __syncthreads();

    if (tid < 32) {
        float M = s_m[0];
#pragma unroll
        for (int g = 1; g < 4; g++) M = fmaxf(M, s_m[g]);
        float zt = 0.f;
        float4 at = make_float4(0.f, 0.f, 0.f, 0.f);
#pragma unroll
        for (int g = 0; g < 4; g++) {
            float f = __expf(s_m[g] - M);
            zt += s_s[g] * f;
            float4 q = s_acc[g][tid];
            at.x += q.x * f; at.y += q.y * f; at.z += q.z * f; at.w += q.w * f;
        }
        float inv = 1.f / zt;
        float4 b4 = *(const float4*)(bias + tid * 4);
        float4 o4;
        o4.x = at.x * inv + b4.x;
        o4.y = at.y * inv + b4.y;
        o4.z = at.z * inv + b4.z;
        o4.w = at.w * inv + b4.w;
        *(float4*)(out + (size_t)t * H1 + tid * 4) = o4;
    }
}

// ---------------- GAT layers 2+3 merged + reparam, fp16 x23 ---------------
__global__ void gat23_fused(const uint16_t* __restrict__ x23,
                            const float* __restrict__ a2, const float* __restrict__ bias2,
                            const float* __restrict__ a3, const float* __restrict__ bias3,
                            const float* __restrict__ eps,
                            float* __restrict__ mu, float* __restrict__ lv,
                            float* __restrict__ emb) {
    int t = blockIdx.x;
    int tid = threadIdx.x, lane = tid & 31, warp = tid >> 5;
    int half = lane >> 4, lg = lane & 15;

    __shared__ float4 s_xr4[2][16], s_att4[2][16];
    __shared__ float  s_m[2][4], s_s[2][4];
    __shared__ float4 s_acc[2][4][16];
    if (tid < 32) {
        int h = tid >> 4, q = tid & 15;
        s_xr4[h][q]  = h4_to_f4(*(const uint2*)(x23 + (size_t)t * 256 + h * 128 + 64 + q * 4));
        s_att4[h][q] = *(const float4*)((h ? a3 : a2) + q * 4);
    }
    int beg = g_rowptr[t];
    int deg = g_rowptr[t + 1] - beg;
    __syncthreads();

    float4 xr4 = s_xr4[half][lg];
    float4 at4 = s_att4[half][lg];
    int coff = half * 128 + lg * 4;

    float m0 = -1e30f, z0 = 0.f;
    float m1 = -1e30f, z1 = 0.f;
    float4 a0 = make_float4(0.f, 0.f, 0.f, 0.f), a1 = a0;

    int j = warp;
    for (; j + 4 < deg; j += 8) {
        int sA = g_srclist[beg + j];
        int sB = g_srclist[beg + j + 4];
        float4 vA = h4_to_f4(*(const uint2*)(x23 + (size_t)sA * 256 + coff));
        float4 vB = h4_to_f4(*(const uint2*)(x23 + (size_t)sB * 256 + coff));
        float pA, pB;
        {
            float a = vA.x + xr4.x; a = fmaxf(a, NEG_SLOPE * a);
            float b = vA.y + xr4.y; b = fmaxf(b, NEG_SLOPE * b);
            float c = vA.z + xr4.z; c = fmaxf(c, NEG_SLOPE * c);
            float d = vA.w + xr4.w; d = fmaxf(d, NEG_SLOPE * d);
            pA = at4.x * a + at4.y * b + at4.z * c + at4.w * d;
            a = vB.x + xr4.x; a = fmaxf(a, NEG_SLOPE * a);
            b = vB.y + xr4.y; b = fmaxf(b, NEG_SLOPE * b);
            c = vB.z + xr4.z; c = fmaxf(c, NEG_SLOPE * c);
            d = vB.w + xr4.w; d = fmaxf(d, NEG_SLOPE * d);
            pB = at4.x * a + at4.y * b + at4.z * c + at4.w * d;
        }
#pragma unroll
        for (int o = 8; o; o >>= 1) {
            pA += __shfl_xor_sync(0xffffffffu, pA, o);
            pB += __shfl_xor_sync(0xffffffffu, pB, o);
        }
        float mn0 = fmaxf(m0, pA);
        float sc0 = __expf(m0 - mn0);
        float w0  = __expf(pA - mn0);
        z0 = z0 * sc0 + w0;
        a0.x = a0.x * sc0 + w0 * vA.x;
        a0.y = a0.y * sc0 + w0 * vA.y;
        a0.z = a0.z * sc0 + w0 * vA.z;
        a0.w = a0.w * sc0 + w0 * vA.w;
        m0 = mn0;
        float mn1 = fmaxf(m1, pB);
        float sc1 = __expf(m1 - mn1);
        float w1  = __expf(pB - mn1);
        z1 = z1 * sc1 + w1;
        a1.x = a1.x * sc1 + w1 * vB.x;
        a1.y = a1.y * sc1 + w1 * vB.y;
        a1.z = a1.z * sc1 + w1 * vB.z;
        a1.w = a1.w * sc1 + w1 * vB.w;
        m1 = mn1;
    }
    if (j < deg) {
        int sA = g_srclist[beg + j];
        float4 vA = h4_to_f4(*(const uint2*)(x23 + (size_t)sA * 256 + coff));
        float a = vA.x + xr4.x; a = fmaxf(a, NEG_SLOPE * a);
        float b = vA.y + xr4.y; b = fmaxf(b, NEG_SLOPE * b);
        float c = vA.z + xr4.z; c = fmaxf(c, NEG_SLOPE * c);
        float d = vA.w + xr4.w; d = fmaxf(d, NEG_SLOPE * d);
        float pA = at4.x * a + at4.y * b + at4.z * c + at4.w * d;
#pragma unroll
        for (int o = 8; o; o >>= 1) pA += __shfl_xor_sync(0xffffffffu, pA, o);
        float mn0 = fmaxf(m0, pA);
        float sc0 = __expf(m0 - mn0);
        float w0  = __expf(pA - mn0);
        z0 = z0 * sc0 + w0;
        a0.x = a0.x * sc0 + w0 * vA.x;
        a0.y = a0.y * sc0 + w0 * vA.y;
        a0.z = a0.z * sc0 + w0 * vA.z;
        a0.w = a0.w * sc0 + w0 * vA.w;
        m0 = mn0;
    }
    {
        float M = fmaxf(m0, m1);
        float e0 = __expf(m0 - M), e1 = __expf(m1 - M);
        z0 = z0 * e0 + z1 * e1;
        a0.x = a0.x * e0 + a1.x * e1;
        a0.y = a0.y * e0 + a1.y * e1;
        a0.z = a0.z * e0 + a1.z * e1;
        a0.w = a0.w * e0 + a1.w * e1;
        m0 = M;
    }
    if (lg == 0) { s_m[half][warp] = m0; s_s[half][warp] = z0; }
    s_acc[half][warp][lg] = a0;
    __syncthreads();

    if (tid < 32) {
        int h = tid >> 4, q = tid & 15;
        float M = s_m[h][0];
#pragma unroll
        for (int g = 1; g < 4; g++) M = fmaxf(M, s_m[h][g]);
        float zt = 0.f;
        float4 at = make_float4(0.f, 0.f, 0.f, 0.f);
#pragma unroll
        for (int g = 0; g < 4; g++) {
            float f = __expf(s_m[h][g] - M);
            zt += s_s[h][g] * f;
            float4 qq = s_acc[h][g][q];
            at.x += qq.x * f; at.y += qq.y * f; at.z += qq.z * f; at.w += qq.w * f;
        }
        float inv = 1.f / zt;
        float4 b4 = *(const float4*)((h ? bias3 : bias2) + q * 4);
        float4 o4;
        o4.x = at.x * inv + b4.x;
        o4.y = at.y * inv + b4.y;
        o4.z = at.z * inv + b4.z;
        o4.w = at.w * inv + b4.w;
        float* op = h ? lv : mu;
        *(float4*)(op + (size_t)t * 64 + q * 4) = o4;
        s_att4[h][q] = o4;
        __syncwarp();
        if (h == 0) {
            float4 mu4 = s_att4[0][q];
            float4 lv4 = s_att4[1][q];
            float4 e4 = *(const float4*)(eps + (size_t)t * 64 + q * 4);
            float4 em;
            em.x = e4.x * __expf(lv4.x) + mu4.x;
            em.y = e4.y * __expf(lv4.y) + mu4.y;
            em.z = e4.z * __expf(lv4.z) + mu4.z;
            em.w = e4.w * __expf(lv4.w) + mu4.w;
            *(float4*)(emb + (size_t)t * 64 + q * 4) = em;
            uint16_t hh, ll;
            ushort4 vh, vl;
            f16split(em.x, hh, ll); vh.x = hh; vl.x = ll;
            f16split(em.y, hh, ll); vh.y = hh; vl.y = ll;
            f16split(em.z, hh, ll); vh.z = hh; vl.z = ll;
            f16split(em.w, hh, ll); vh.w = hh; vl.w = ll;
            *(ushort4*)(g_ebh + (size_t)t * 64 + q * 4) = vh;
            *(ushort4*)(g_ebl + (size_t)t * 64 + q * 4) = vl;
        }
    }
}

// ---------------- batch norm stats ----------------
template <int C>
__global__ void bn_stats(const float* __restrict__ h) {
    int c = blockIdx.x;
    int tid = threadIdx.x;
    float s = 0.f, s2 = 0.f;
    for (int r = tid; r < NN; r += 256) {
        float v = h[(size_t)r * C + c];
        s += v; s2 += v * v;
    }
    __shared__ float sh[8], sh2[8];
#pragma unroll
    for (int o = 16; o; o >>= 1) {
        s  += __shfl_xor_sync(0xffffffffu, s,  o);
        s2 += __shfl_xor_sync(0xffffffffu, s2, o);
    }
    if ((tid & 31) == 0) { sh[tid >> 5] = s; sh2[tid >> 5] = s2; }
    __syncthreads();
    if (tid == 0) {
        float ts = 0.f, ts2 = 0.f;
        for (int w = 0; w < 8; w++) { ts += sh[w]; ts2 += sh2[w]; }
        float mean = ts / NN;
        float var = ts2 / NN - mean * mean;
        g_mean[c] = mean;
        g_rstd[c] = rsqrtf(var + BN_EPS);
    }
}

// ---------------- readj = sigmoid(emb @ emb^T), fp16 2-pass HMMA ----------
#define GP 72
#define G_AHI 0
#define G_ALO (G_AHI + 128 * GP * 2)
#define G_BHI (G_ALO + 128 * GP * 2)
#define G_SMEM 65536
#define MTG 79

__global__ __launch_bounds__(256)
void gram_hmma(const uint16_t* __restrict__ Eh, const uint16_t* __restrict__ El,
               float* __restrict__ out) {
    int bid = blockIdx.x;
    int by = (int)(0.5f * (2.f * MTG + 1.f) -
                   sqrtf((2.f * MTG + 1.f) * (2.f * MTG + 1.f) * 0.25f - 2.f * (float)bid));
    if (by < 0) by = 0;
    if (by > MTG - 1) by = MTG - 1;
    int start = by * MTG - (by * (by - 1)) / 2;
    while (start > bid) { by--; start = by * MTG - (by * (by - 1)) / 2; }
    while (bid >= start + (MTG - by)) { by++; start = by * MTG - (by * (by - 1)) / 2; }
    int bx = by + (bid - start);

    extern __shared__ __align__(16) char smem[];
    uint32_t sb = smem_u32(smem);
    int tid = threadIdx.x, lane = tid & 31, warp = tid >> 5;
    int row0 = by * 128, col0 = bx * 128;

    {
        int rrow = tid & 127;
        uint4 z = make_uint4(0, 0, 0, 0);
        if (tid < 128) {
            int rA = row0 + rrow;
            bool va = rA < NN;
            const uint4* ph = (const uint4*)(Eh + (size_t)rA * 64);
            const uint4* pl = (const uint4*)(El + (size_t)rA * 64);
#pragma unroll
            for (int q = 0; q < 8; q++) {
                uint32_t off = (rrow * GP + q * 8) * 2;
                *(uint4*)(smem + G_AHI + off) = va ? ph[q] : z;
                *(uint4*)(smem + G_ALO + off) = va ? pl[q] : z;
            }
        } else {
            int rB = col0 + rrow;
            bool vb = rB < NN;
            const uint4* ph = (const uint4*)(Eh + (size_t)rB * 64);
#pragma unroll
            for (int q = 0; q < 8; q++) {
                uint32_t off = (rrow * GP + q * 8) * 2;
                *(uint4*)(smem + G_BHI + off) = vb ? ph[q] : z;
            }
        }
    }
    __syncthreads();

    int wm = (warp & 1) * 64;
    int wn = (warp >> 1) * 32;
    float c[4][4][4];
#pragma unroll
    for (int mi = 0; mi < 4; mi++)
#pragma unroll
        for (int ni = 0; ni < 4; ni++)
#pragma unroll
            for (int e = 0; e < 4; e++) c[mi][ni][e] = 0.f;

    int grp = lane >> 3, rl = lane & 7;
#pragma unroll
    for (int pass = 0; pass < 2; pass++) {
        uint32_t aBase = sb + ((pass == 1) ? G_ALO : G_AHI);
        uint32_t bBase = sb + G_BHI;
#pragma unroll
        for (int k0 = 0; k0 < 64; k0 += 16) {
            uint32_t af[4][4], bf[4][2];
#pragma unroll
            for (int mi = 0; mi < 4; mi++) {
                int arow = wm + mi * 16 + (grp & 1) * 8 + rl;
                int acol = k0 + (grp >> 1) * 8;
                ldsm_x4(af[mi][0], af[mi][1], af[mi][2], af[mi][3],
                        aBase + (arow * GP + acol) * 2);
            }
#pragma unroll
            for (int ni = 0; ni < 4; ni++) {
                int brow = wn + ni * 8 + rl;
                int bcol = k0 + (grp & 1) * 8;
                ldsm_x2(bf[ni][0], bf[ni][1], bBase + (brow * GP + bcol) * 2);
            }
#pragma unroll
            for (int mi = 0; mi < 4; mi++)
#pragma unroll
                for (int ni = 0; ni < 4; ni++)
                    mma_f16(c[mi][ni], af[mi][0], af[mi][1], af[mi][2], af[mi][3],
                            bf[ni][0], bf[ni][1]);
        }
    }
    __syncthreads();

    float* stag = (float*)smem;
    bool diag = (bx == by);
    int qr = lane >> 2, qc = 2 * (lane & 3);
#pragma unroll
    for (int mi = 0; mi < 4; mi++) {
#pragma unroll
        for (int ni = 0; ni < 4; ni++) {
#pragma unroll
            for (int half = 0; half < 2; half++) {
                int row = wm + mi * 16 + qr + half * 8;
                int col = wn + ni * 8 + qc;
                float v0 = 1.f / (1.f + __expf(-c[mi][ni][2 * half]));
                float v1 = 1.f / (1.f + __expf(-c[mi][ni][2 * half + 1]));
                int r = row0 + row, cc = col0 + col;
                if (r < NN && cc < NN)
                    *(float2*)(out + (size_t)r * NN + cc) = make_float2(v0, v1);
                if (!diag) {
                    int s = row & 31;
                    stag[row * 128 + (col ^ s)] = v0;
                    stag[row * 128 + ((col + 1) ^ s)] = v1;
                }
            }
        }
    }
    if (diag) return;
    __syncthreads();

    for (int cc = warp; cc < 128; cc += 8) {
        int cgl = col0 + cc;
        if (cgl >= NN) continue;
        float* mrow = out + (size_t)cgl * NN + row0;
#pragma unroll
        for (int ib = 0; ib < 128; ib += 32) {
            int i = ib + lane;
            if (row0 + i < NN)
                mrow[i] = stag[i * 128 + (cc ^ (i & 31))];
        }
    }
}

// ---------------- launch ----------------
extern "C" void kernel_launch(void* const* d_in, const int* in_sizes, int n_in,
                              void* d_out, int out_size) {
    const float* x   = (const float*)d_in[0];
    const int*   ei  = (const int*)  d_in[1];
    const float* eps = (const float*)d_in[2];
    const float* w1l = (const float*)d_in[3];
    const float* b1l = (const float*)d_in[4];
    const float* w1r = (const float*)d_in[5];
    const float* b1r = (const float*)d_in[6];
    const float* a1  = (const float*)d_in[7];
    const float* bias1 = (const float*)d_in[8];
    const float* bn1_g = (const float*)d_in[9];
    const float* bn1_b = (const float*)d_in[10];
    const float* w2l = (const float*)d_in[11];
    const float* b2l = (const float*)d_in[12];
    const float* w2r = (const float*)d_in[13];
    const float* b2r = (const float*)d_in[14];
    const float* a2  = (const float*)d_in[15];
    const float* bias2 = (const float*)d_in[16];
    const float* w3l = (const float*)d_in[17];
    const float* b3l = (const float*)d_in[18];
    const float* w3r = (const float*)d_in[19];
    const float* b3r = (const float*)d_in[20];
    const float* a3  = (const float*)d_in[21];
    const float* bias3 = (const float*)d_in[22];
    const float* dw1 = (const float*)d_in[23];
    const float* db1 = (const float*)d_in[24];
    const float* dbn_g = (const float*)d_in[25];
    const float* dbn_b = (const float*)d_in[26];
    const float* dw2 = (const float*)d_in[27];
    const float* db2 = (const float*)d_in[28];
    float* out = (float*)d_out;

    float *p_h, *p_d, *p_b23;
    cudaGetSymbolAddress((void**)&p_h,   g_h);
    cudaGetSymbolAddress((void**)&p_d,   g_d);
    cudaGetSymbolAddress((void**)&p_b23, g_bias23);
    uint16_t *p_xl1h, *p_xr1h, *p_x23h, *p_w1lh, *p_w1rh, *p_w23h, *p_dw1h, *p_dw2h, *p_ebh, *p_ebl;
    cudaGetSymbolAddress((void**)&p_xl1h, g_xl1h);
    cudaGetSymbolAddress((void**)&p_xr1h, g_xr1h);
    cudaGetSymbolAddress((void**)&p_x23h, g_x23h);
    cudaGetSymbolAddress((void**)&p_w1lh, g_w1lh);
    cudaGetSymbolAddress((void**)&p_w1rh, g_w1rh);
    cudaGetSymbolAddress((void**)&p_w23h, g_w23h);
    cudaGetSymbolAddress((void**)&p_dw1h, g_dw1h);
    cudaGetSymbolAddress((void**)&p_dw2h, g_dw2h);
    cudaGetSymbolAddress((void**)&p_ebh,  g_ebh);
    cudaGetSymbolAddress((void**)&p_ebl,  g_ebl);

    cudaFuncSetAttribute(gram_hmma, cudaFuncAttributeMaxDynamicSharedMemorySize, G_SMEM);

    static cudaStream_t s_side = nullptr;
    static cudaEvent_t evA = nullptr, evB = nullptr, evC = nullptr, evD = nullptr;
    if (!s_side) {
        cudaStreamCreateWithFlags(&s_side, cudaStreamNonBlocking);
        cudaEventCreateWithFlags(&evA, cudaEventDisableTiming);
        cudaEventCreateWithFlags(&evB, cudaEventDisableTiming);
        cudaEventCreateWithFlags(&evC, cudaEventDisableTiming);
        cudaEventCreateWithFlags(&evD, cudaEventDisableTiming);
    }

    const int MT  = (NN + 127) / 128;   // 79
    const int MT64 = (NN + 63) / 64;    // 157

    // ---- fork: CSR build on side stream ----
    cudaEventRecord(evA, 0);
    cudaStreamWaitEvent(s_side, evA, 0);
    k_zero_counts<<<(NN + 255) / 256, 256, 0, s_side>>>();
    k_count_deg<<<(NE + 255) / 256, 256, 0, s_side>>>(ei);
    k_scan_deg<<<1, 1024, 0, s_side>>>();
    k_fill_list<<<(NE + 255) / 256, 256, 0, s_side>>>(ei);
    cudaEventRecord(evB, s_side);

    // ---- main: fused prep + layer-1 GEMM (fp16 output) ----
    k_prep<<<(P_TOT + 255) / 256, 256>>>(w1l, w1r, w2l, w2r, w3l, w3r, dw1, dw2,
                                         b2l, b2r, b3l, b3r);
    {
        TJobs j1 = {{ { p_w1lh, b1l, (float*)p_xl1h }, { p_w1rh, b1r, (float*)p_xr1h } }};
        gemmT64h<<<dim3(1, MT64, 2), 256>>>(x, j1, NN, NFEAT, H1);
    }
    cudaStreamWaitEvent(0, evB, 0);   // join CSR

    // ---- GAT layer 1 (fp16 gather, fused online softmax) -> BN stats ----
    gat1_fused<<<NN, 128>>>(p_xl1h, p_xr1h, a1, bias1, p_h);
    bn_stats<H1><<<H1, 256>>>(p_h);

    // ---- layers 2 & 3 packed GEMM (BN+ReLU fused, fp16 output) ----
    {
        TJobs j2 = {{ { p_w23h, p_b23, (float*)p_x23h }, {} }};
        gemmTh<<<dim3(2, MT, 1), 256>>>(p_h, j2, NN, H1, 256, bn1_g, bn1_b);
    }

    // ---- GAT layers 2+3 merged + fused reparameterize (fp16 gather) ----
    gat23_fused<<<NN, 128>>>(p_x23h, a2, bias2, a3, bias3, eps,
                             out + MU_OFF, out + LV_OFF, out + EMB_OFF);

    // ---- fork: decoder MLP on side stream, gram on main ----
    cudaEventRecord(evC, 0);
    cudaStreamWaitEvent(s_side, evC, 0);
    gemmP<<<dim3(2, MT, 1), 256, 0, s_side>>>(p_ebh, p_ebl, p_dw1h, db1, p_d,
                                              NN, NHID2, NHID1);
    bn_stats<NHID1><<<NHID1, 256, 0, s_side>>>(p_d);
    {
        TJobs jd = {{ { p_dw2h, db2, out + REX_OFF }, {} }};
        gemmT<<<dim3(4, MT, 1), 256, 0, s_side>>>(p_d, jd, NN, NHID1, NFEAT,
                                                  dbn_g, dbn_b);
    }
    cudaEventRecord(evD, s_side);

    gram_hmma<<<MT * (MT + 1) / 2, 256, G_SMEM>>>(p_ebh, p_ebl, out + READJ_OFF);

    cudaStreamWaitEvent(0, evD, 0);   // join decoder
}

// round 15
// speedup vs baseline: 1.1865x; 1.1865x over previous
#include <cuda_runtime.h>
#include <cuda_fp16.h>
#include <cstdint>
#include <math.h>

#define NN     10000
#define EE     320000
#define NE     (EE + NN)     // with self loops
#define NFEAT  512
#define NHID1  256
#define NHID2  64
#define H1     128           // 2*nhid2
#define NEG_SLOPE 0.2f
#define BN_EPS 1e-5f

// output layout (flattened tuple: emb, re_x, readj, mu, logvar)
#define EMB_OFF   ((size_t)0)
#define REX_OFF   ((size_t)NN * NHID2)
#define READJ_OFF (REX_OFF + (size_t)NN * NFEAT)
#define MU_OFF    (READJ_OFF + (size_t)NN * NN)
#define LV_OFF    (MU_OFF + (size_t)NN * NHID2)

typedef unsigned long long u64;

// ---------------- warp MMA helpers (baseline PTX, works on sm_103) --------
__device__ __forceinline__ uint32_t smem_u32(const void* p) {
    uint32_t a;
    asm("{ .reg .u64 t; cvta.to.shared.u64 t, %1; cvt.u32.u64 %0, t; }" : "=r"(a) : "l"(p));
    return a;
}
__device__ __forceinline__ void ldsm_x4(uint32_t& r0, uint32_t& r1, uint32_t& r2, uint32_t& r3, uint32_t addr) {
    asm volatile("ldmatrix.sync.aligned.m8n8.x4.shared.b16 {%0,%1,%2,%3}, [%4];"
                 : "=r"(r0), "=r"(r1), "=r"(r2), "=r"(r3) : "r"(addr));
}
__device__ __forceinline__ void ldsm_x2(uint32_t& r0, uint32_t& r1, uint32_t addr) {
    asm volatile("ldmatrix.sync.aligned.m8n8.x2.shared.b16 {%0,%1}, [%2];"
                 : "=r"(r0), "=r"(r1) : "r"(addr));
}
__device__ __forceinline__ void mma_f16(float* d, uint32_t a0, uint32_t a1, uint32_t a2, uint32_t a3,
                                        uint32_t b0, uint32_t b1) {
    asm volatile("mma.sync.aligned.m16n8k16.row.col.f32.f16.f16.f32 "
                 "{%0,%1,%2,%3}, {%4,%5,%6,%7}, {%8,%9}, {%0,%1,%2,%3};"
                 : "+f"(d[0]), "+f"(d[1]), "+f"(d[2]), "+f"(d[3])
                 : "r"(a0), "r"(a1), "r"(a2), "r"(a3), "r"(b0), "r"(b1));
}
__device__ __forceinline__ void f16split(float v, uint16_t& h, uint16_t& l) {
    __half hb = __float2half_rn(v);
    __half lb = __float2half_rn(v - __half2float(hb));
    h = __half_as_ushort(hb);
    l = __half_as_ushort(lb);
}
__device__ __forceinline__ uint16_t f16h(float v) {
    return __half_as_ushort(__float2half_rn(v));
}
__device__ __forceinline__ float4 h4_to_f4(uint2 u) {
    __half2 a = *(__half2*)&u.x;
    __half2 b = *(__half2*)&u.y;
    float2 fa = __half22float2(a);
    float2 fb = __half22float2(b);
    return make_float4(fa.x, fa.y, fb.x, fb.y);
}

// ---------------- scratch (device globals; no allocation allowed) ----------
__device__ uint16_t g_xl1h[NN * H1];    // fp16 layer-1 outputs (GAT1 only)
__device__ uint16_t g_xr1h[NN * H1];
__device__ float g_h  [NN * H1];
__device__ uint16_t g_x23h[NN * 256];   // fp16 packed: xl2|xr2|xl3|xr3
__device__ float g_d  [NN * NHID1];
__device__ int   g_deg[NN];
__device__ int   g_rowptr[NN + 1];
__device__ int   g_cursor[NN];
__device__ int   g_srclist[NE];
__device__ float g_mean[NHID1];
__device__ float g_rstd[NHID1];
__device__ float g_bias23[256];
// emb fp16 hi/lo (pre-split for gram + decoder GEMM)
__device__ uint16_t g_ebh[NN * NHID2], g_ebl[NN * NHID2];
// transposed fp16 weights [Nc][K]
__device__ uint16_t g_w1lh[H1 * NFEAT];
__device__ uint16_t g_w1rh[H1 * NFEAT];
__device__ uint16_t g_w23h[256 * H1];
__device__ uint16_t g_dw1h[NHID1 * NHID2];
__device__ uint16_t g_dw2h[NFEAT * NHID1];

// ---------------- CSR build ----------------
__global__ void k_zero_counts() {
    int i = blockIdx.x * blockDim.x + threadIdx.x;
    if (i < NN) { g_deg[i] = 0; g_cursor[i] = 0; }
}

__global__ void k_count_deg(const int* __restrict__ edge_index) {
    int i = blockIdx.x * blockDim.x + threadIdx.x;
    if (i >= NE) return;
    int tgt = (i < EE) ? edge_index[EE + i] : (i - EE);
    atomicAdd(&g_deg[tgt], 1);
}

__global__ void k_scan_deg() {
    __shared__ int wsum[32];
    __shared__ int sc;
    int tid = threadIdx.x, lane = tid & 31, w = tid >> 5;
    if (tid == 0) { sc = 0; g_rowptr[0] = 0; }
    __syncthreads();
    for (int base = 0; base < NN; base += 1024) {
        int i = base + tid;
        int v = (i < NN) ? g_deg[i] : 0;
        int x = v;
#pragma unroll
        for (int o = 1; o < 32; o <<= 1) {
            int t = __shfl_up_sync(0xffffffffu, x, o);
            if (lane >= o) x += t;
        }
        if (lane == 31) wsum[w] = x;
        __syncthreads();
        if (w == 0) {
            int y = wsum[lane];
#pragma unroll
            for (int o = 1; o < 32; o <<= 1) {
                int t = __shfl_up_sync(0xffffffffu, y, o);
                if (lane >= o) y += t;
            }
            wsum[lane] = y;
        }
        __syncthreads();
        int pre = (w > 0) ? wsum[w - 1] : 0;
        int c = sc;
        if (i < NN) g_rowptr[i + 1] = c + pre + x;
        int total = wsum[31];
        __syncthreads();
        if (tid == 0) sc = c + total;
        __syncthreads();
    }
}

__global__ void k_fill_list(const int* __restrict__ edge_index) {
    int i = blockIdx.x * blockDim.x + threadIdx.x;
    if (i >= NE) return;
    int src, tgt;
    if (i < EE) { src = edge_index[i]; tgt = edge_index[EE + i]; }
    else        { src = i - EE;        tgt = i - EE; }
    int pos = atomicAdd(&g_cursor[tgt], 1);
    g_srclist[g_rowptr[tgt] + pos] = src;
}

// ---------------- fused prep: all weight transposes + bias pack -----------
#define P_S01 (H1 * NFEAT)
#define P_S2  (256 * H1)
#define P_S3  (NHID1 * NHID2)
#define P_S4  (NFEAT * NHID1)
#define P_TOT (P_S01 + P_S2 + P_S3 + P_S4 + 256)

__global__ void k_prep(const float* __restrict__ w1l, const float* __restrict__ w1r,
                       const float* __restrict__ w2l, const float* __restrict__ w2r,
                       const float* __restrict__ w3l, const float* __restrict__ w3r,
                       const float* __restrict__ dw1, const float* __restrict__ dw2,
                       const float* __restrict__ b2l, const float* __restrict__ b2r,
                       const float* __restrict__ b3l, const float* __restrict__ b3r) {
    int i = blockIdx.x * blockDim.x + threadIdx.x;
    if (i < P_S01) {
        int n = i / NFEAT, k = i - n * NFEAT;
        g_w1lh[i] = f16h(w1l[(size_t)k * H1 + n]);
        g_w1rh[i] = f16h(w1r[(size_t)k * H1 + n]);
        return;
    }
    i -= P_S01;
    if (i < P_S2) {
        int np = i >> 7, k = i & 127;
        int jj = np >> 6, n = np & 63;
        const float* W = (jj == 0) ? w2l : (jj == 1) ? w2r : (jj == 2) ? w3l : w3r;
        g_w23h[i] = f16h(W[(size_t)k * 64 + n]);
        return;
    }
    i -= P_S2;
    if (i < P_S3) {
        int n = i / NHID2, k = i - n * NHID2;
        g_dw1h[i] = f16h(dw1[(size_t)k * NHID1 + n]);
        return;
    }
    i -= P_S3;
    if (i < P_S4) {
        int n = i / NHID1, k = i - n * NHID1;
        g_dw2h[i] = f16h(dw2[(size_t)k * NFEAT + n]);
        return;
    }
    i -= P_S4;
    if (i < 256) {
        int jj = i >> 6, n = i & 63;
        const float* b = (jj == 0) ? b2l : (jj == 1) ? b2r : (jj == 2) ? b3l : b3r;
        g_bias23[i] = b[n];
    }
}

// ---------------- GEMM job plumbing ----------------
struct TJob  { const uint16_t* Bh; const float* bias; float* C; };
struct TJobs { TJob j[2]; };

// ---------------- gemmT: fp16 2-pass HMMA GEMM, 128x128 tile, fp32 out ---
__global__ __launch_bounds__(256)
void gemmT(const float* __restrict__ A, TJobs jobs, int M, int K, int Nc,
           const float* __restrict__ bnG, const float* __restrict__ bnB) {
    const TJob jb = jobs.j[blockIdx.z];
    __shared__ __align__(16) uint16_t Ah[128][40], Al[128][40];
    __shared__ __align__(16) uint16_t Bh[128][40];
    int tid = threadIdx.x, lane = tid & 31, warp = tid >> 5;
    int row0 = blockIdx.y * 128, col0 = blockIdx.x * 128;
    int wm = (warp & 1) * 64, wn = (warp >> 1) * 32;
    int grp = lane >> 3, rl = lane & 7;
    float c[4][4][4];
#pragma unroll
    for (int mi = 0; mi < 4; mi++)
#pragma unroll
        for (int ni = 0; ni < 4; ni++)
#pragma unroll
            for (int e = 0; e < 4; e++) c[mi][ni][e] = 0.f;

    int ar = tid >> 1, kh = (tid & 1) * 16;
    int r = row0 + ar;
    bool va = r < M;

    for (int k0 = 0; k0 < K; k0 += 32) {
        const float* pa = A + (size_t)r * K + k0 + kh;
#pragma unroll
        for (int q = 0; q < 4; q++) {
            float4 v = va ? *(const float4*)(pa + q * 4) : make_float4(0.f, 0.f, 0.f, 0.f);
            if (bnG) {
                int ch = k0 + kh + q * 4;
                float4 mm = *(const float4*)(g_mean + ch);
                float4 rs = *(const float4*)(g_rstd + ch);
                float4 gg = *(const float4*)(bnG + ch);
                float4 bb = *(const float4*)(bnB + ch);
                v.x = fmaxf((v.x - mm.x) * rs.x * gg.x + bb.x, 0.f);
                v.y = fmaxf((v.y - mm.y) * rs.y * gg.y + bb.y, 0.f);
                v.z = fmaxf((v.z - mm.z) * rs.z * gg.z + bb.z, 0.f);
                v.w = fmaxf((v.w - mm.w) * rs.w * gg.w + bb.w, 0.f);
            }
            uint16_t h0, l0, h1, l1, h2, l2, h3, l3;
            f16split(v.x, h0, l0); f16split(v.y, h1, l1);
            f16split(v.z, h2, l2); f16split(v.w, h3, l3);
            *(uint32_t*)&Ah[ar][kh + q * 4]     = (uint32_t)h0 | ((uint32_t)h1 << 16);
            *(uint32_t*)&Ah[ar][kh + q * 4 + 2] = (uint32_t)h2 | ((uint32_t)h3 << 16);
            *(uint32_t*)&Al[ar][kh + q * 4]     = (uint32_t)l0 | ((uint32_t)l1 << 16);
            *(uint32_t*)&Al[ar][kh + q * 4 + 2] = (uint32_t)l2 | ((uint32_t)l3 << 16);
        }
        {
            const uint16_t* pbh = jb.Bh + (size_t)(col0 + ar) * K + k0 + kh;
            *(uint4*)&Bh[ar][kh]     = *(const uint4*)pbh;
            *(uint4*)&Bh[ar][kh + 8] = *(const uint4*)(pbh + 8);
        }
        __syncthreads();
#pragma unroll
        for (int pass = 0; pass < 2; pass++) {
            const uint16_t (*Aq)[40] = (pass == 1) ? Al : Ah;
#pragma unroll
            for (int k1 = 0; k1 < 32; k1 += 16) {
                uint32_t af[4][4], bf[4][2];
#pragma unroll
                for (int mi = 0; mi < 4; mi++) {
                    int arow = wm + mi * 16 + (grp & 1) * 8 + rl;
                    int acol = k1 + (grp >> 1) * 8;
                    ldsm_x4(af[mi][0], af[mi][1], af[mi][2], af[mi][3],
                            smem_u32(&Aq[arow][acol]));
                }
#pragma unroll
                for (int ni = 0; ni < 4; ni++) {
                    int brow = wn + ni * 8 + rl;
                    int bcol = k1 + (grp & 1) * 8;
                    ldsm_x2(bf[ni][0], bf[ni][1], smem_u32(&Bh[brow][bcol]));
                }
#pragma unroll
                for (int mi = 0; mi < 4; mi++)
#pragma unroll
                    for (int ni = 0; ni < 4; ni++)
                        mma_f16(c[mi][ni], af[mi][0], af[mi][1], af[mi][2], af[mi][3],
                                bf[ni][0], bf[ni][1]);
            }
        }
        __syncthreads();
    }
    int qr = lane >> 2, qc = 2 * (lane & 3);
#pragma unroll
    for (int mi = 0; mi < 4; mi++) {
#pragma unroll
        for (int half = 0; half < 2; half++) {
            int row = wm + mi * 16 + qr + half * 8;
            int rr = row0 + row;
            if (rr < M) {
                float* Crow = jb.C + (size_t)rr * Nc;
#pragma unroll
                for (int ni = 0; ni < 4; ni++) {
                    int cc = col0 + wn + ni * 8 + qc;
                    float2 p;
                    p.x = c[mi][ni][2 * half]     + __ldg(&jb.bias[cc]);
                    p.y = c[mi][ni][2 * half + 1] + __ldg(&jb.bias[cc + 1]);
                    *(float2*)&Crow[cc] = p;
                }
            }
        }
    }
}

// ---------------- gemmTh: same but fp16 OUTPUT (for x23) ------------------
__global__ __launch_bounds__(256)
void gemmTh(const float* __restrict__ A, TJobs jobs, int M, int K, int Nc,
            const float* __restrict__ bnG, const float* __restrict__ bnB) {
    const TJob jb = jobs.j[blockIdx.z];
    __shared__ __align__(16) uint16_t Ah[128][40], Al[128][40];
    __shared__ __align__(16) uint16_t Bh[128][40];
    int tid = threadIdx.x, lane = tid & 31, warp = tid >> 5;
    int row0 = blockIdx.y * 128, col0 = blockIdx.x * 128;
    int wm = (warp & 1) * 64, wn = (warp >> 1) * 32;
    int grp = lane >> 3, rl = lane & 7;
    float c[4][4][4];
#pragma unroll
    for (int mi = 0; mi < 4; mi++)
#pragma unroll
        for (int ni = 0; ni < 4; ni++)
#pragma unroll
            for (int e = 0; e < 4; e++) c[mi][ni][e] = 0.f;

    int ar = tid >> 1, kh = (tid & 1) * 16;
    int r = row0 + ar;
    bool va = r < M;

    for (int k0 = 0; k0 < K; k0 += 32) {
        const float* pa = A + (size_t)r * K + k0 + kh;
#pragma unroll
        for (int q = 0; q < 4; q++) {
            float4 v = va ? *(const float4*)(pa + q * 4) : make_float4(0.f, 0.f, 0.f, 0.f);
            if (bnG) {
                int ch = k0 + kh + q * 4;
                float4 mm = *(const float4*)(g_mean + ch);
                float4 rs = *(const float4*)(g_rstd + ch);
                float4 gg = *(const float4*)(bnG + ch);
                float4 bb = *(const float4*)(bnB + ch);
                v.x = fmaxf((v.x - mm.x) * rs.x * gg.x + bb.x, 0.f);
                v.y = fmaxf((v.y - mm.y) * rs.y * gg.y + bb.y, 0.f);
                v.z = fmaxf((v.z - mm.z) * rs.z * gg.z + bb.z, 0.f);
                v.w = fmaxf((v.w - mm.w) * rs.w * gg.w + bb.w, 0.f);
            }
            uint16_t h0, l0, h1, l1, h2, l2, h3, l3;
            f16split(v.x, h0, l0); f16split(v.y, h1, l1);
            f16split(v.z, h2, l2); f16split(v.w, h3, l3);
            *(uint32_t*)&Ah[ar][kh + q * 4]     = (uint32_t)h0 | ((uint32_t)h1 << 16);
            *(uint32_t*)&Ah[ar][kh + q * 4 + 2] = (uint32_t)h2 | ((uint32_t)h3 << 16);
            *(uint32_t*)&Al[ar][kh + q * 4]     = (uint32_t)l0 | ((uint32_t)l1 << 16);
            *(uint32_t*)&Al[ar][kh + q * 4 + 2] = (uint32_t)l2 | ((uint32_t)l3 << 16);
        }
        {
            const uint16_t* pbh = jb.Bh + (size_t)(col0 + ar) * K + k0 + kh;
            *(uint4*)&Bh[ar][kh]     = *(const uint4*)pbh;
            *(uint4*)&Bh[ar][kh + 8] = *(const uint4*)(pbh + 8);
        }
        __syncthreads();
#pragma unroll
        for (int pass = 0; pass < 2; pass++) {
            const uint16_t (*Aq)[40] = (pass == 1) ? Al : Ah;
#pragma unroll
            for (int k1 = 0; k1 < 32; k1 += 16) {
                uint32_t af[4][4], bf[4][2];
#pragma unroll
                for (int mi = 0; mi < 4; mi++) {
                    int arow = wm + mi * 16 + (grp & 1) * 8 + rl;
                    int acol = k1 + (grp >> 1) * 8;
                    ldsm_x4(af[mi][0], af[mi][1], af[mi][2], af[mi][3],
                            smem_u32(&Aq[arow][acol]));
                }
#pragma unroll
                for (int ni = 0; ni < 4; ni++) {
                    int brow = wn + ni * 8 + rl;
                    int bcol = k1 + (grp & 1) * 8;
                    ldsm_x2(bf[ni][0], bf[ni][1], smem_u32(&Bh[brow][bcol]));
                }
#pragma unroll
                for (int mi = 0; mi < 4; mi++)
#pragma unroll
                    for (int ni = 0; ni < 4; ni++)
                        mma_f16(c[mi][ni], af[mi][0], af[mi][1], af[mi][2], af[mi][3],
                                bf[ni][0], bf[ni][1]);
            }
        }
        __syncthreads();
    }
    int qr = lane >> 2, qc = 2 * (lane & 3);
#pragma unroll
    for (int mi = 0; mi < 4; mi++) {
#pragma unroll
        for (int half = 0; half < 2; half++) {
            int row = wm + mi * 16 + qr + half * 8;
            int rr = row0 + row;
            if (rr < M) {
                uint16_t* Crow = (uint16_t*)jb.C + (size_t)rr * Nc;
#pragma unroll
                for (int ni = 0; ni < 4; ni++) {
                    int cc = col0 + wn + ni * 8 + qc;
                    uint16_t p0 = f16h(c[mi][ni][2 * half]     + __ldg(&jb.bias[cc]));
                    uint16_t p1 = f16h(c[mi][ni][2 * half + 1] + __ldg(&jb.bias[cc + 1]));
                    *(uint32_t*)&Crow[cc] = (uint32_t)p0 | ((uint32_t)p1 << 16);
                }
            }
        }
    }
}

// ---------------- gemmT64h: 64x128 tile, fp16 OUTPUT (for GAT1 operands) --
__global__ __launch_bounds__(256)
void gemmT64h(const float* __restrict__ A, TJobs jobs, int M, int K, int Nc) {
    const TJob jb = jobs.j[blockIdx.z];
    __shared__ __align__(16) uint16_t Ah[64][40], Al[64][40];
    __shared__ __align__(16) uint16_t Bh[128][40];
    int tid = threadIdx.x, lane = tid & 31, warp = tid >> 5;
    int row0 = blockIdx.y * 64, col0 = blockIdx.x * 128;
    int wm = (warp & 1) * 32, wn = (warp >> 1) * 32;
    int grp = lane >> 3, rl = lane & 7;
    float c[2][4][4];
#pragma unroll
    for (int mi = 0; mi < 2; mi++)
#pragma unroll
        for (int ni = 0; ni < 4; ni++)
#pragma unroll
            for (int e = 0; e < 4; e++) c[mi][ni][e] = 0.f;

    int ar = tid >> 2, ks = (tid & 3) * 8;
    int br = tid >> 1, kb = (tid & 1) * 16;
    int r = row0 + ar;
    bool va = r < M;

    for (int k0 = 0; k0 < K; k0 += 32) {
        const float* pa = A + (size_t)r * K + k0 + ks;
#pragma unroll
        for (int q = 0; q < 2; q++) {
            float4 v = va ? *(const float4*)(pa + q * 4) : make_float4(0.f, 0.f, 0.f, 0.f);
            uint16_t h0, l0, h1, l1, h2, l2, h3, l3;
            f16split(v.x, h0, l0); f16split(v.y, h1, l1);
            f16split(v.z, h2, l2); f16split(v.w, h3, l3);
            *(uint32_t*)&Ah[ar][ks + q * 4]     = (uint32_t)h0 | ((uint32_t)h1 << 16);
            *(uint32_t*)&Ah[ar][ks + q * 4 + 2] = (uint32_t)h2 | ((uint32_t)h3 << 16);
            *(uint32_t*)&Al[ar][ks + q * 4]     = (uint32_t)l0 | ((uint32_t)l1 << 16);
            *(uint32_t*)&Al[ar][ks + q * 4 + 2] = (uint32_t)l2 | ((uint32_t)l3 << 16);
        }
        {
            const uint16_t* pbh = jb.Bh + (size_t)(col0 + br) * K + k0 + kb;
            *(uint4*)&Bh[br][kb]     = *(const uint4*)pbh;
            *(uint4*)&Bh[br][kb + 8] = *(const uint4*)(pbh + 8);
        }
        __syncthreads();
#pragma unroll
        for (int pass = 0; pass < 2; pass++) {
            const uint16_t (*Aq)[40] = (pass == 1) ? Al : Ah;
#pragma unroll
            for (int k1 = 0; k1 < 32; k1 += 16) {
                uint32_t af[2][4], bf[4][2];
#pragma unroll
                for (int mi = 0; mi < 2; mi++) {
                    int arow = wm + mi * 16 + (grp & 1) * 8 + rl;
                    int acol = k1 + (grp >> 1) * 8;
                    ldsm_x4(af[mi][0], af[mi][1], af[mi][2], af[mi][3],
                            smem_u32(&Aq[arow][acol]));
                }
#pragma unroll
                for (int ni = 0; ni < 4; ni++) {
                    int brow = wn + ni * 8 + rl;
                    int bcol = k1 + (grp & 1) * 8;
                    ldsm_x2(bf[ni][0], bf[ni][1], smem_u32(&Bh[brow][bcol]));
                }
#pragma unroll
                for (int mi = 0; mi < 2; mi++)
#pragma unroll
                    for (int ni = 0; ni < 4; ni++)
                        mma_f16(c[mi][ni], af[mi][0], af[mi][1], af[mi][2], af[mi][3],
                                bf[ni][0], bf[ni][1]);
            }
        }
        __syncthreads();
    }
    int qr = lane >> 2, qc = 2 * (lane & 3);
#pragma unroll
    for (int mi = 0; mi < 2; mi++) {
#pragma unroll
        for (int half = 0; half < 2; half++) {
            int row = wm + mi * 16 + qr + half * 8;
            int rr = row0 + row;
            if (rr < M) {
                uint16_t* Crow = (uint16_t*)jb.C + (size_t)rr * Nc;
#pragma unroll
                for (int ni = 0; ni < 4; ni++) {
                    int cc = col0 + wn + ni * 8 + qc;
                    uint16_t p0 = f16h(c[mi][ni][2 * half]     + __ldg(&jb.bias[cc]));
                    uint16_t p1 = f16h(c[mi][ni][2 * half + 1] + __ldg(&jb.bias[cc + 1]));
                    *(uint32_t*)&Crow[cc] = (uint32_t)p0 | ((uint32_t)p1 << 16);
                }
            }
        }
    }
}

// ---------------- gemmP: pre-split fp16 A (hi/lo), 128x128 tile ----------
__global__ __launch_bounds__(256)
void gemmP(const uint16_t* __restrict__ Ahg, const uint16_t* __restrict__ Alg,
           const uint16_t* __restrict__ Bhg, const float* __restrict__ bias,
           float* __restrict__ C, int M, int K, int Nc) {
    __shared__ __align__(16) uint16_t Ah[128][40], Al[128][40];
    __shared__ __align__(16) uint16_t Bh[128][40];
    int tid = threadIdx.x, lane = tid & 31, warp = tid >> 5;
    int row0 = blockIdx.y * 128, col0 = blockIdx.x * 128;
    int wm = (warp & 1) * 64, wn = (warp >> 1) * 32;
    int grp = lane >> 3, rl = lane & 7;
    float c[4][4][4];
#pragma unroll
    for (int mi = 0; mi < 4; mi++)
#pragma unroll
        for (int ni = 0; ni < 4; ni++)
#pragma unroll
            for (int e = 0; e < 4; e++) c[mi][ni][e] = 0.f;

    int ar = tid >> 1, kh = (tid & 1) * 16;
    int r = row0 + ar;
    bool va = r < M;
    uint4 z4 = make_uint4(0, 0, 0, 0);

    for (int k0 = 0; k0 < K; k0 += 32) {
        {
            const uint16_t* ph = Ahg + (size_t)r * K + k0 + kh;
            const uint16_t* pl = Alg + (size_t)r * K + k0 + kh;
            *(uint4*)&Ah[ar][kh]     = va ? *(const uint4*)ph : z4;
            *(uint4*)&Ah[ar][kh + 8] = va ? *(const uint4*)(ph + 8) : z4;
            *(uint4*)&Al[ar][kh]     = va ? *(const uint4*)pl : z4;
            *(uint4*)&Al[ar][kh + 8] = va ? *(const uint4*)(pl + 8) : z4;
        }
        {
            const uint16_t* pbh = Bhg + (size_t)(col0 + ar) * K + k0 + kh;
            *(uint4*)&Bh[ar][kh]     = *(const uint4*)pbh;
            *(uint4*)&Bh[ar][kh + 8] = *(const uint4*)(pbh + 8);
        }
        __syncthreads();
#pragma unroll
        for (int pass = 0; pass < 2; pass++) {
            const uint16_t (*Aq)[40] = (pass == 1) ? Al : Ah;
#pragma unroll
            for (int k1 = 0; k1 < 32; k1 += 16) {
                uint32_t af[4][4], bf[4][2];
#pragma unroll
                for (int mi = 0; mi < 4; mi++) {
                    int arow = wm + mi * 16 + (grp & 1) * 8 + rl;
                    int acol = k1 + (grp >> 1) * 8;
                    ldsm_x4(af[mi][0], af[mi][1], af[mi][2], af[mi][3],
                            smem_u32(&Aq[arow][acol]));
                }
#pragma unroll
                for (int ni = 0; ni < 4; ni++) {
                    int brow = wn + ni * 8 + rl;
                    int bcol = k1 + (grp & 1) * 8;
                    ldsm_x2(bf[ni][0], bf[ni][1], smem_u32(&Bh[brow][bcol]));
                }
#pragma unroll
                for (int mi = 0; mi < 4; mi++)
#pragma unroll
                    for (int ni = 0; ni < 4; ni++)
                        mma_f16(c[mi][ni], af[mi][0], af[mi][1], af[mi][2], af[mi][3],
                                bf[ni][0], bf[ni][1]);
            }
        }
        __syncthreads();
    }
    int qr = lane >> 2, qc = 2 * (lane & 3);
#pragma unroll
    for (int mi = 0; mi < 4; mi++) {
#pragma unroll
        for (int half = 0; half < 2; half++) {
            int row = wm + mi * 16 + qr + half * 8;
            int rr = row0 + row;
            if (rr < M) {
                float* Crow = C + (size_t)rr * Nc;
#pragma unroll
                for (int ni = 0; ni < 4; ni++) {
                    int cc = col0 + wn + ni * 8 + qc;
                    float2 p;
                    p.x = c[mi][ni][2 * half]     + __ldg(&bias[cc]);
                    p.y = c[mi][ni][2 * half + 1] + __ldg(&bias[cc + 1]);
                    *(float2*)&Crow[cc] = p;
                }
            }
        }
    }
}

// ---------------- GAT layer 1: fused online-softmax, fp16 operands --------
__global__ void gat1_fused(const uint16_t* __restrict__ xlh,
                           const uint16_t* __restrict__ xrh,
                           const float* __restrict__ att, const float* __restrict__ bias,
                           float* __restrict__ out) {
    int t = blockIdx.x;
    int tid = threadIdx.x, lane = tid & 31, warp = tid >> 5;

    __shared__ float4 s_xr4[32], s_att4[32];
    __shared__ float  s_m[4], s_s[4];
    __shared__ float4 s_acc[4][32];
    if (tid < 32) {
        uint2 u = *(const uint2*)(xrh + (size_t)t * H1 + tid * 4);
        s_xr4[tid]  = h4_to_f4(u);
        s_att4[tid] = *(const float4*)(att + tid * 4);
    }
    int beg = g_rowptr[t];
    int deg = g_rowptr[t + 1] - beg;
    __syncthreads();

    float4 xr4 = s_xr4[lane];
    float4 at4 = s_att4[lane];

    float m0 = -1e30f, z0 = 0.f;
    float m1 = -1e30f, z1 = 0.f;
    float4 a0 = make_float4(0.f, 0.f, 0.f, 0.f), a1 = a0;

    int j = warp;
    for (; j + 4 < deg; j += 8) {
        int sA = g_srclist[beg + j];
        int sB = g_srclist[beg + j + 4];
        float4 vA = h4_to_f4(*(const uint2*)(xlh + (size_t)sA * H1 + lane * 4));
        float4 vB = h4_to_f4(*(const uint2*)(xlh + (size_t)sB * H1 + lane * 4));
        float pA, pB;
        {
            float a = vA.x + xr4.x; a = fmaxf(a, NEG_SLOPE * a);
            float b = vA.y + xr4.y; b = fmaxf(b, NEG_SLOPE * b);
            float c = vA.z + xr4.z; c = fmaxf(c, NEG_SLOPE * c);
            float d = vA.w + xr4.w; d = fmaxf(d, NEG_SLOPE * d);
            pA = at4.x * a + at4.y * b + at4.z * c + at4.w * d;
            a = vB.x + xr4.x; a = fmaxf(a, NEG_SLOPE * a);
            b = vB.y + xr4.y; b = fmaxf(b, NEG_SLOPE * b);
            c = vB.z + xr4.z; c = fmaxf(c, NEG_SLOPE * c);
            d = vB.w + xr4.w; d = fmaxf(d, NEG_SLOPE * d);
            pB = at4.x * a + at4.y * b + at4.z * c + at4.w * d;
        }
#pragma unroll
        for (int o = 16; o; o >>= 1) {
            pA += __shfl_xor_sync(0xffffffffu, pA, o);
            pB += __shfl_xor_sync(0xffffffffu, pB, o);
        }
        float mn0 = fmaxf(m0, pA);
        float sc0 = __expf(m0 - mn0);
        float w0  = __expf(pA - mn0);
        z0 = z0 * sc0 + w0;
        a0.x = a0.x * sc0 + w0 * vA.x;
        a0.y = a0.y * sc0 + w0 * vA.y;
        a0.z = a0.z * sc0 + w0 * vA.z;
        a0.w = a0.w * sc0 + w0 * vA.w;
        m0 = mn0;
        float mn1 = fmaxf(m1, pB);
        float sc1 = __expf(m1 - mn1);
        float w1  = __expf(pB - mn1);
        z1 = z1 * sc1 + w1;
        a1.x = a1.x * sc1 + w1 * vB.x;
        a1.y = a1.y * sc1 + w1 * vB.y;
        a1.z = a1.z * sc1 + w1 * vB.z;
        a1.w = a1.w * sc1 + w1 * vB.w;
        m1 = mn1;
    }
    if (j < deg) {
        int sA = g_srclist[beg + j];
        float4 vA = h4_to_f4(*(const uint2*)(xlh + (size_t)sA * H1 + lane * 4));
        float a = vA.x + xr4.x; a = fmaxf(a, NEG_SLOPE * a);
        float b = vA.y + xr4.y; b = fmaxf(b, NEG_SLOPE * b);
        float c = vA.z + xr4.z; c = fmaxf(c, NEG_SLOPE * c);
        float d = vA.w + xr4.w; d = fmaxf(d, NEG_SLOPE * d);
        float pA = at4.x * a + at4.y * b + at4.z * c + at4.w * d;
#pragma unroll
        for (int o = 16; o; o >>= 1) pA += __shfl_xor_sync(0xffffffffu, pA, o);
        float mn0 = fmaxf(m0, pA);
        float sc0 = __expf(m0 - mn0);
        float w0  = __expf(pA - mn0);
        z0 = z0 * sc0 + w0;
        a0.x = a0.x * sc0 + w0 * vA.x;
        a0.y = a0.y * sc0 + w0 * vA.y;
        a0.z = a0.z * sc0 + w0 * vA.z;
        a0.w = a0.w * sc0 + w0 * vA.w;
        m0 = mn0;
    }
    {
        float M = fmaxf(m0, m1);
        float e0 = __expf(m0 - M), e1 = __expf(m1 - M);
        z0 = z0 * e0 + z1 * e1;
        a0.x = a0.x * e0 + a1.x * e1;
        a0.y = a0.y * e0 + a1.y * e1;
        a0.z = a0.z * e0 + a1.z * e1;
        a0.w = a0.w * e0 + a1.w * e1;
        m0 = M;
    }
    if (lane == 0) { s_m[warp] = m0; s_s[warp] = z0; }
    s_acc[warp][lane] = a0;
    __syncthreads();

    if (tid < 32) {
        float M = s_m[0];
#pragma unroll
        for (int g = 1; g < 4; g++) M = fmaxf(M, s_m[g]);
        float zt = 0.f;
        float4 at = make_float4(0.f, 0.f, 0.f, 0.f);
#pragma unroll
        for (int g = 0; g < 4; g++) {
            float f = __expf(s_m[g] - M);
            zt += s_s[g] * f;
            float4 q = s_acc[g][tid];
            at.x += q.x * f; at.y += q.y * f; at.z += q.z * f; at.w += q.w * f;
        }
        float inv = 1.f / zt;
        float4 b4 = *(const float4*)(bias + tid * 4);
        float4 o4;
        o4.x = at.x * inv + b4.x;
        o4.y = at.y * inv + b4.y;
        o4.z = at.z * inv + b4.z;
        o4.w = at.w * inv + b4.w;
        *(float4*)(out + (size_t)t * H1 + tid * 4) = o4;
    }
}

// ---------------- GAT layers 2+3 merged + reparam, fp16 x23 ---------------
__global__ void gat23_fused(const uint16_t* __restrict__ x23,
                            const float* __restrict__ a2, const float* __restrict__ bias2,
                            const float* __restrict__ a3, const float* __restrict__ bias3,
                            const float* __restrict__ eps,
                            float* __restrict__ mu, float* __restrict__ lv,
                            float* __restrict__ emb) {
    int t = blockIdx.x;
    int tid = threadIdx.x, lane = tid & 31, warp = tid >> 5;
    int half = lane >> 4, lg = lane & 15;

    __shared__ float4 s_xr4[2][16], s_att4[2][16];
    __shared__ float  s_m[2][4], s_s[2][4];
    __shared__ float4 s_acc[2][4][16];
    if (tid < 32) {
        int h = tid >> 4, q = tid & 15;
        s_xr4[h][q]  = h4_to_f4(*(const uint2*)(x23 + (size_t)t * 256 + h * 128 + 64 + q * 4));
        s_att4[h][q] = *(const float4*)((h ? a3 : a2) + q * 4);
    }
    int beg = g_rowptr[t];
    int deg = g_rowptr[t + 1] - beg;
    __syncthreads();

    float4 xr4 = s_xr4[half][lg];
    float4 at4 = s_att4[half][lg];
    int coff = half * 128 + lg * 4;

    float m0 = -1e30f, z0 = 0.f;
    float m1 = -1e30f, z1 = 0.f;
    float4 a0 = make_float4(0.f, 0.f, 0.f, 0.f), a1 = a0;

    int j = warp;
    for (; j + 4 < deg; j += 8) {
        int sA = g_srclist[beg + j];
        int sB = g_srclist[beg + j + 4];
        float4 vA = h4_to_f4(*(const uint2*)(x23 + (size_t)sA * 256 + coff));
        float4 vB = h4_to_f4(*(const uint2*)(x23 + (size_t)sB * 256 + coff));
        float pA, pB;
        {
            float a = vA.x + xr4.x; a = fmaxf(a, NEG_SLOPE * a);
            float b = vA.y + xr4.y; b = fmaxf(b, NEG_SLOPE * b);
            float c = vA.z + xr4.z; c = fmaxf(c, NEG_SLOPE * c);
            float d = vA.w + xr4.w; d = fmaxf(d, NEG_SLOPE * d);
            pA = at4.x * a + at4.y * b + at4.z * c + at4.w * d;
            a = vB.x + xr4.x; a = fmaxf(a, NEG_SLOPE * a);
            b = vB.y + xr4.y; b = fmaxf(b, NEG_SLOPE * b);
            c = vB.z + xr4.z; c = fmaxf(c, NEG_SLOPE * c);
            d = vB.w + xr4.w; d = fmaxf(d, NEG_SLOPE * d);
            pB = at4.x * a + at4.y * b + at4.z * c + at4.w * d;
        }
#pragma unroll
        for (int o = 8; o; o >>= 1) {
            pA += __shfl_xor_sync(0xffffffffu, pA, o);
            pB += __shfl_xor_sync(0xffffffffu, pB, o);
        }
        float mn0 = fmaxf(m0, pA);
        float sc0 = __expf(m0 - mn0);
        float w0  = __expf(pA - mn0);
        z0 = z0 * sc0 + w0;
        a0.x = a0.x * sc0 + w0 * vA.x;
        a0.y = a0.y * sc0 + w0 * vA.y;
        a0.z = a0.z * sc0 + w0 * vA.z;
        a0.w = a0.w * sc0 + w0 * vA.w;
        m0 = mn0;
        float mn1 = fmaxf(m1, pB);
        float sc1 = __expf(m1 - mn1);
        float w1  = __expf(pB - mn1);
        z1 = z1 * sc1 + w1;
        a1.x = a1.x * sc1 + w1 * vB.x;
        a1.y = a1.y * sc1 + w1 * vB.y;
        a1.z = a1.z * sc1 + w1 * vB.z;
        a1.w = a1.w * sc1 + w1 * vB.w;
        m1 = mn1;
    }
    if (j < deg) {
        int sA = g_srclist[beg + j];
        float4 vA = h4_to_f4(*(const uint2*)(x23 + (size_t)sA * 256 + coff));
        float a = vA.x + xr4.x; a = fmaxf(a, NEG_SLOPE * a);
        float b = vA.y + xr4.y; b = fmaxf(b, NEG_SLOPE * b);
        float c = vA.z + xr4.z; c = fmaxf(c, NEG_SLOPE * c);
        float d = vA.w + xr4.w; d = fmaxf(d, NEG_SLOPE * d);
        float pA = at4.x * a + at4.y * b + at4.z * c + at4.w * d;
#pragma unroll
        for (int o = 8; o; o >>= 1) pA += __shfl_xor_sync(0xffffffffu, pA, o);
        float mn0 = fmaxf(m0, pA);
        float sc0 = __expf(m0 - mn0);
        float w0  = __expf(pA - mn0);
        z0 = z0 * sc0 + w0;
        a0.x = a0.x * sc0 + w0 * vA.x;
        a0.y = a0.y * sc0 + w0 * vA.y;
        a0.z = a0.z * sc0 + w0 * vA.z;
        a0.w = a0.w * sc0 + w0 * vA.w;
        m0 = mn0;
    }
    {
        float M = fmaxf(m0, m1);
        float e0 = __expf(m0 - M), e1 = __expf(m1 - M);
        z0 = z0 * e0 + z1 * e1;
        a0.x = a0.x * e0 + a1.x * e1;
        a0.y = a0.y * e0 + a1.y * e1;
        a0.z = a0.z * e0 + a1.z * e1;
        a0.w = a0.w * e0 + a1.w * e1;
        m0 = M;
    }
    if (lg == 0) { s_m[half][warp] = m0; s_s[half][warp] = z0; }
    s_acc[half][warp][lg] = a0;
    __syncthreads();

    if (tid < 32) {
        int h = tid >> 4, q = tid & 15;
        float M = s_m[h][0];
#pragma unroll
        for (int g = 1; g < 4; g++) M = fmaxf(M, s_m[h][g]);
        float zt = 0.f;
        float4 at = make_float4(0.f, 0.f, 0.f, 0.f);
#pragma unroll
        for (int g = 0; g < 4; g++) {
            float f = __expf(s_m[h][g] - M);
            zt += s_s[h][g] * f;
            float4 qq = s_acc[h][g][q];
            at.x += qq.x * f; at.y += qq.y * f; at.z += qq.z * f; at.w += qq.w * f;
        }
        float inv = 1.f / zt;
        float4 b4 = *(const float4*)((h ? bias3 : bias2) + q * 4);
        float4 o4;
        o4.x = at.x * inv + b4.x;
        o4.y = at.y * inv + b4.y;
        o4.z = at.z * inv + b4.z;
        o4.w = at.w * inv + b4.w;
        float* op = h ? lv : mu;
        *(float4*)(op + (size_t)t * 64 + q * 4) = o4;
        s_att4[h][q] = o4;
        __syncwarp();
        if (h == 0) {
            float4 mu4 = s_att4[0][q];
            float4 lv4 = s_att4[1][q];
            float4 e4 = *(const float4*)(eps + (size_t)t * 64 + q * 4);
            float4 em;
            em.x = e4.x * __expf(lv4.x) + mu4.x;
            em.y = e4.y * __expf(lv4.y) + mu4.y;
            em.z = e4.z * __expf(lv4.z) + mu4.z;
            em.w = e4.w * __expf(lv4.w) + mu4.w;
            *(float4*)(emb + (size_t)t * 64 + q * 4) = em;
            uint16_t hh, ll;
            ushort4 vh, vl;
            f16split(em.x, hh, ll); vh.x = hh; vl.x = ll;
            f16split(em.y, hh, ll); vh.y = hh; vl.y = ll;
            f16split(em.z, hh, ll); vh.z = hh; vl.z = ll;
            f16split(em.w, hh, ll); vh.w = hh; vl.w = ll;
            *(ushort4*)(g_ebh + (size_t)t * 64 + q * 4) = vh;
            *(ushort4*)(g_ebl + (size_t)t * 64 + q * 4) = vl;
        }
    }
}

// ---------------- batch norm stats ----------------
template <int C>
__global__ void bn_stats(const float* __restrict__ h) {
    int c = blockIdx.x;
    int tid = threadIdx.x;
    float s = 0.f, s2 = 0.f;
    for (int r = tid; r < NN; r += 256) {
        float v = h[(size_t)r * C + c];
        s += v; s2 += v * v;
    }
    __shared__ float sh[8], sh2[8];
#pragma unroll
    for (int o = 16; o; o >>= 1) {
        s  += __shfl_xor_sync(0xffffffffu, s,  o);
        s2 += __shfl_xor_sync(0xffffffffu, s2, o);
    }
    if ((tid & 31) == 0) { sh[tid >> 5] = s; sh2[tid >> 5] = s2; }
    __syncthreads();
    if (tid == 0) {
        float ts = 0.f, ts2 = 0.f;
        for (int w = 0; w < 8; w++) { ts += sh[w]; ts2 += sh2[w]; }
        float mean = ts / NN;
        float var = ts2 / NN - mean * mean;
        g_mean[c] = mean;
        g_rstd[c] = rsqrtf(var + BN_EPS);
    }
}

// ---------------- readj = sigmoid(emb @ emb^T), fp16 SINGLE-pass HMMA -----
// smem: Ahi [128][GP] + Bhi [128][GP] fp16 (36.9KB); staging reuses the same
// region in two 64-row halves (32KB each).
#define GP 72
#define G_AHI 0
#define G_BHI (G_AHI + 128 * GP * 2)
#define G_SMEM (G_BHI + 128 * GP * 2)   // 36864
#define MTG 79

__global__ __launch_bounds__(256)
void gram_hmma(const uint16_t* __restrict__ Eh, float* __restrict__ out) {
    int bid = blockIdx.x;
    int by = (int)(0.5f * (2.f * MTG + 1.f) -
                   sqrtf((2.f * MTG + 1.f) * (2.f * MTG + 1.f) * 0.25f - 2.f * (float)bid));
    if (by < 0) by = 0;
    if (by > MTG - 1) by = MTG - 1;
    int start = by * MTG - (by * (by - 1)) / 2;
    while (start > bid) { by--; start = by * MTG - (by * (by - 1)) / 2; }
    while (bid >= start + (MTG - by)) { by++; start = by * MTG - (by * (by - 1)) / 2; }
    int bx = by + (bid - start);

    extern __shared__ __align__(16) char smem[];
    uint32_t sb = smem_u32(smem);
    int tid = threadIdx.x, lane = tid & 31, warp = tid >> 5;
    int row0 = by * 128, col0 = bx * 128;

    // fill: tid<128 -> A row hi; tid>=128 -> B row hi
    {
        int rrow = tid & 127;
        uint4 z = make_uint4(0, 0, 0, 0);
        uint32_t base = (tid < 128) ? G_AHI : G_BHI;
        int rr = ((tid < 128) ? row0 : col0) + rrow;
        bool vr = rr < NN;
        const uint4* ph = (const uint4*)(Eh + (size_t)rr * 64);
#pragma unroll
        for (int q = 0; q < 8; q++) {
            uint32_t off = base + (rrow * GP + q * 8) * 2;
            *(uint4*)(smem + off) = vr ? ph[q] : z;
        }
    }
    __syncthreads();

    int wm = (warp & 1) * 64;
    int wn = (warp >> 1) * 32;
    float c[4][4][4];
#pragma unroll
    for (int mi = 0; mi < 4; mi++)
#pragma unroll
        for (int ni = 0; ni < 4; ni++)
#pragma unroll
            for (int e = 0; e < 4; e++) c[mi][ni][e] = 0.f;

    int grp = lane >> 3, rl = lane & 7;
#pragma unroll
    for (int k0 = 0; k0 < 64; k0 += 16) {
        uint32_t af[4][4], bf[4][2];
#pragma unroll
        for (int mi = 0; mi < 4; mi++) {
            int arow = wm + mi * 16 + (grp & 1) * 8 + rl;
            int acol = k0 + (grp >> 1) * 8;
            ldsm_x4(af[mi][0], af[mi][1], af[mi][2], af[mi][3],
                    sb + G_AHI + (arow * GP + acol) * 2);
        }
#pragma unroll
        for (int ni = 0; ni < 4; ni++) {
            int brow = wn + ni * 8 + rl;
            int bcol = k0 + (grp & 1) * 8;
            ldsm_x2(bf[ni][0], bf[ni][1], sb + G_BHI + (brow * GP + bcol) * 2);
        }
#pragma unroll
        for (int mi = 0; mi < 4; mi++)
#pragma unroll
            for (int ni = 0; ni < 4; ni++)
                mma_f16(c[mi][ni], af[mi][0], af[mi][1], af[mi][2], af[mi][3],
                        bf[ni][0], bf[ni][1]);
    }
    __syncthreads();

    // sigmoid + direct write (store sigmoid back into c for reuse)
    bool diag = (bx == by);
    int qr = lane >> 2, qc = 2 * (lane & 3);
#pragma unroll
    for (int mi = 0; mi < 4; mi++) {
#pragma unroll
        for (int ni = 0; ni < 4; ni++) {
#pragma unroll
            for (int half = 0; half < 2; half++) {
                int row = wm + mi * 16 + qr + half * 8;
                int col = wn + ni * 8 + qc;
                float v0 = 1.f / (1.f + __expf(-c[mi][ni][2 * half]));
                float v1 = 1.f / (1.f + __expf(-c[mi][ni][2 * half + 1]));
                c[mi][ni][2 * half] = v0;
                c[mi][ni][2 * half + 1] = v1;
                int r = row0 + row, cc = col0 + col;
                if (r < NN && cc < NN)
                    *(float2*)(out + (size_t)r * NN + cc) = make_float2(v0, v1);
            }
        }
    }
    if (diag) return;

    // mirror in two 64-row halves via 32KB staging (reuses fill smem)
    float* stag = (float*)smem;
#pragma unroll
    for (int hIdx = 0; hIdx < 2; hIdx++) {
        __syncthreads();
        if ((warp & 1) == hIdx) {
#pragma unroll
            for (int mi = 0; mi < 4; mi++) {
#pragma unroll
                for (int ni = 0; ni < 4; ni++) {
#pragma unroll
                    for (int half = 0; half < 2; half++) {
                        int row = wm + mi * 16 + qr + half * 8;  // global row in tile
                        int lrow = row & 63;
                        int col = wn + ni * 8 + qc;
                        int s = row & 31;
                        stag[lrow * 128 + (col ^ s)] = c[mi][ni][2 * half];
                        stag[lrow * 128 + ((col + 1) ^ s)] = c[mi][ni][2 * half + 1];
                    }
                }
            }
        }
        __syncthreads();
        for (int cc = warp; cc < 128; cc += 8) {
            int cgl = col0 + cc;
            if (cgl >= NN) continue;
            float* mrow = out + (size_t)cgl * NN + row0 + hIdx * 64;
#pragma unroll
            for (int ib = 0; ib < 64; ib += 32) {
                int i = ib + lane;
                int grow = hIdx * 64 + i;
                if (row0 + grow < NN)
                    mrow[i] = stag[i * 128 + (cc ^ (grow & 31))];
            }
        }
    }
}

// ---------------- launch ----------------
extern "C" void kernel_launch(void* const* d_in, const int* in_sizes, int n_in,
                              void* d_out, int out_size) {
    const float* x   = (const float*)d_in[0];
    const int*   ei  = (const int*)  d_in[1];
    const float* eps = (const float*)d_in[2];
    const float* w1l = (const float*)d_in[3];
    const float* b1l = (const float*)d_in[4];
    const float* w1r = (const float*)d_in[5];
    const float* b1r = (const float*)d_in[6];
    const float* a1  = (const float*)d_in[7];
    const float* bias1 = (const float*)d_in[8];
    const float* bn1_g = (const float*)d_in[9];
    const float* bn1_b = (const float*)d_in[10];
    const float* w2l = (const float*)d_in[11];
    const float* b2l = (const float*)d_in[12];
    const float* w2r = (const float*)d_in[13];
    const float* b2r = (const float*)d_in[14];
    const float* a2  = (const float*)d_in[15];
    const float* bias2 = (const float*)d_in[16];
    const float* w3l = (const float*)d_in[17];
    const float* b3l = (const float*)d_in[18];
    const float* w3r = (const float*)d_in[19];
    const float* b3r = (const float*)d_in[20];
    const float* a3  = (const float*)d_in[21];
    const float* bias3 = (const float*)d_in[22];
    const float* dw1 = (const float*)d_in[23];
    const float* db1 = (const float*)d_in[24];
    const float* dbn_g = (const float*)d_in[25];
    const float* dbn_b = (const float*)d_in[26];
    const float* dw2 = (const float*)d_in[27];
    const float* db2 = (const float*)d_in[28];
    float* out = (float*)d_out;

    float *p_h, *p_d, *p_b23;
    cudaGetSymbolAddress((void**)&p_h,   g_h);
    cudaGetSymbolAddress((void**)&p_d,   g_d);
    cudaGetSymbolAddress((void**)&p_b23, g_bias23);
    uint16_t *p_xl1h, *p_xr1h, *p_x23h, *p_w1lh, *p_w1rh, *p_w23h, *p_dw1h, *p_dw2h, *p_ebh, *p_ebl;
    cudaGetSymbolAddress((void**)&p_xl1h, g_xl1h);
    cudaGetSymbolAddress((void**)&p_xr1h, g_xr1h);
    cudaGetSymbolAddress((void**)&p_x23h, g_x23h);
    cudaGetSymbolAddress((void**)&p_w1lh, g_w1lh);
    cudaGetSymbolAddress((void**)&p_w1rh, g_w1rh);
    cudaGetSymbolAddress((void**)&p_w23h, g_w23h);
    cudaGetSymbolAddress((void**)&p_dw1h, g_dw1h);
    cudaGetSymbolAddress((void**)&p_dw2h, g_dw2h);
    cudaGetSymbolAddress((void**)&p_ebh,  g_ebh);
    cudaGetSymbolAddress((void**)&p_ebl,  g_ebl);

    cudaFuncSetAttribute(gram_hmma, cudaFuncAttributeMaxDynamicSharedMemorySize, G_SMEM);

    static cudaStream_t s_side = nullptr;
    static cudaEvent_t evA = nullptr, evB = nullptr, evC = nullptr, evD = nullptr;
    if (!s_side) {
        cudaStreamCreateWithFlags(&s_side, cudaStreamNonBlocking);
        cudaEventCreateWithFlags(&evA, cudaEventDisableTiming);
        cudaEventCreateWithFlags(&evB, cudaEventDisableTiming);
        cudaEventCreateWithFlags(&evC, cudaEventDisableTiming);
        cudaEventCreateWithFlags(&evD, cudaEventDisableTiming);
    }

    const int MT  = (NN + 127) / 128;   // 79
    const int MT64 = (NN + 63) / 64;    // 157

    // ---- fork: CSR build on side stream ----
    cudaEventRecord(evA, 0);
    cudaStreamWaitEvent(s_side, evA, 0);
    k_zero_counts<<<(NN + 255) / 256, 256, 0, s_side>>>();
    k_count_deg<<<(NE + 255) / 256, 256, 0, s_side>>>(ei);
    k_scan_deg<<<1, 1024, 0, s_side>>>();
    k_fill_list<<<(NE + 255) / 256, 256, 0, s_side>>>(ei);
    cudaEventRecord(evB, s_side);

    // ---- main: fused prep + layer-1 GEMM (fp16 output) ----
    k_prep<<<(P_TOT + 255) / 256, 256>>>(w1l, w1r, w2l, w2r, w3l, w3r, dw1, dw2,
                                         b2l, b2r, b3l, b3r);
    {
        TJobs j1 = {{ { p_w1lh, b1l, (float*)p_xl1h }, { p_w1rh, b1r, (float*)p_xr1h } }};
        gemmT64h<<<dim3(1, MT64, 2), 256>>>(x, j1, NN, NFEAT, H1);
    }
    cudaStreamWaitEvent(0, evB, 0);   // join CSR

    // ---- GAT layer 1 (fp16 gather, fused online softmax) -> BN stats ----
    gat1_fused<<<NN, 128>>>(p_xl1h, p_xr1h, a1, bias1, p_h);
    bn_stats<H1><<<H1, 256>>>(p_h);

    // ---- layers 2 & 3 packed GEMM (BN+ReLU fused, fp16 output) ----
    {
        TJobs j2 = {{ { p_w23h, p_b23, (float*)p_x23h }, {} }};
        gemmTh<<<dim3(2, MT, 1), 256>>>(p_h, j2, NN, H1, 256, bn1_g, bn1_b);
    }

    // ---- GAT layers 2+3 merged + fused reparameterize (fp16 gather) ----
    gat23_fused<<<NN, 128>>>(p_x23h, a2, bias2, a3, bias3, eps,
                             out + MU_OFF, out + LV_OFF, out + EMB_OFF);

    // ---- fork: decoder MLP on side stream, gram on main ----
    cudaEventRecord(evC, 0);
    cudaStreamWaitEvent(s_side, evC, 0);
    gemmP<<<dim3(2, MT, 1), 256, 0, s_side>>>(p_ebh, p_ebl, p_dw1h, db1, p_d,
                                              NN, NHID2, NHID1);
    bn_stats<NHID1><<<NHID1, 256, 0, s_side>>>(p_d);
    {
        TJobs jd = {{ { p_dw2h, db2, out + REX_OFF }, {} }};
        gemmT<<<dim3(4, MT, 1), 256, 0, s_side>>>(p_d, jd, NN, NHID1, NFEAT,
                                                  dbn_g, dbn_b);
    }
    cudaEventRecord(evD, s_side);

    gram_hmma<<<MT * (MT + 1) / 2, 256, G_SMEM>>>(p_ebh, out + READJ_OFF);

    cudaStreamWaitEvent(0, evD, 0);   // join decoder
}

// round 16
// speedup vs baseline: 1.2828x; 1.0811x over previous
#include <cuda_runtime.h>
#include <cuda_fp16.h>
#include <cstdint>
#include <math.h>

#define NN     10000
#define EE     320000
#define NE     (EE + NN)     // with self loops
#define NFEAT  512
#define NHID1  256
#define NHID2  64
#define H1     128           // 2*nhid2
#define NEG_SLOPE 0.2f
#define BN_EPS 1e-5f

// output layout (flattened tuple: emb, re_x, readj, mu, logvar)
#define EMB_OFF   ((size_t)0)
#define REX_OFF   ((size_t)NN * NHID2)
#define READJ_OFF (REX_OFF + (size_t)NN * NFEAT)
#define MU_OFF    (READJ_OFF + (size_t)NN * NN)
#define LV_OFF    (MU_OFF + (size_t)NN * NHID2)

typedef unsigned long long u64;

// ---------------- warp MMA helpers (baseline PTX, works on sm_103) --------
__device__ __forceinline__ uint32_t smem_u32(const void* p) {
    uint32_t a;
    asm("{ .reg .u64 t; cvta.to.shared.u64 t, %1; cvt.u32.u64 %0, t; }" : "=r"(a) : "l"(p));
    return a;
}
__device__ __forceinline__ void ldsm_x4(uint32_t& r0, uint32_t& r1, uint32_t& r2, uint32_t& r3, uint32_t addr) {
    asm volatile("ldmatrix.sync.aligned.m8n8.x4.shared.b16 {%0,%1,%2,%3}, [%4];"
                 : "=r"(r0), "=r"(r1), "=r"(r2), "=r"(r3) : "r"(addr));
}
__device__ __forceinline__ void ldsm_x2(uint32_t& r0, uint32_t& r1, uint32_t addr) {
    asm volatile("ldmatrix.sync.aligned.m8n8.x2.shared.b16 {%0,%1}, [%2];"
                 : "=r"(r0), "=r"(r1) : "r"(addr));
}
__device__ __forceinline__ void mma_f16(float* d, uint32_t a0, uint32_t a1, uint32_t a2, uint32_t a3,
                                        uint32_t b0, uint32_t b1) {
    asm volatile("mma.sync.aligned.m16n8k16.row.col.f32.f16.f16.f32 "
                 "{%0,%1,%2,%3}, {%4,%5,%6,%7}, {%8,%9}, {%0,%1,%2,%3};"
                 : "+f"(d[0]), "+f"(d[1]), "+f"(d[2]), "+f"(d[3])
                 : "r"(a0), "r"(a1), "r"(a2), "r"(a3), "r"(b0), "r"(b1));
}
__device__ __forceinline__ void f16split(float v, uint16_t& h, uint16_t& l) {
    __half hb = __float2half_rn(v);
    __half lb = __float2half_rn(v - __half2float(hb));
    h = __half_as_ushort(hb);
    l = __half_as_ushort(lb);
}
__device__ __forceinline__ uint16_t f16h(float v) {
    return __half_as_ushort(__float2half_rn(v));
}
__device__ __forceinline__ uint32_t f16x2(float a, float b) {
    __half2 h = __floats2half2_rn(a, b);
    return *(uint32_t*)&h;
}
__device__ __forceinline__ float4 h4_to_f4(uint2 u) {
    __half2 a = *(__half2*)&u.x;
    __half2 b = *(__half2*)&u.y;
    float2 fa = __half22float2(a);
    float2 fb = __half22float2(b);
    return make_float4(fa.x, fa.y, fb.x, fb.y);
}

// ---------------- scratch (device globals; no allocation allowed) ----------
__device__ uint16_t g_xl1h[NN * H1];    // fp16 layer-1 outputs (GAT1 only)
__device__ uint16_t g_xr1h[NN * H1];
__device__ float g_h  [NN * H1];
__device__ uint16_t g_x23h[NN * 256];   // fp16 packed: xl2|xr2|xl3|xr3
__device__ float g_d  [NN * NHID1];
__device__ int   g_deg[NN];
__device__ int   g_rowptr[NN + 1];
__device__ int   g_cursor[NN];
__device__ int   g_srclist[NE];
__device__ float g_mean[NHID1];
__device__ float g_rstd[NHID1];
__device__ float g_bias23[256];
// emb fp16 (gram + decoder GEMM)
__device__ uint16_t g_ebh[NN * NHID2];
// transposed fp16 weights [Nc][K]
__device__ uint16_t g_w1lh[H1 * NFEAT];
__device__ uint16_t g_w1rh[H1 * NFEAT];
__device__ uint16_t g_w23h[256 * H1];
__device__ uint16_t g_dw1h[NHID1 * NHID2];
__device__ uint16_t g_dw2h[NFEAT * NHID1];

// ---------------- CSR build ----------------
__global__ void k_zero_counts() {
    int i = blockIdx.x * blockDim.x + threadIdx.x;
    if (i < NN) { g_deg[i] = 0; g_cursor[i] = 0; }
}

__global__ void k_count_deg(const int* __restrict__ edge_index) {
    int i = blockIdx.x * blockDim.x + threadIdx.x;
    if (i >= NE) return;
    int tgt = (i < EE) ? edge_index[EE + i] : (i - EE);
    atomicAdd(&g_deg[tgt], 1);
}

__global__ void k_scan_deg() {
    __shared__ int wsum[32];
    __shared__ int sc;
    int tid = threadIdx.x, lane = tid & 31, w = tid >> 5;
    if (tid == 0) { sc = 0; g_rowptr[0] = 0; }
    __syncthreads();
    for (int base = 0; base < NN; base += 1024) {
        int i = base + tid;
        int v = (i < NN) ? g_deg[i] : 0;
        int x = v;
#pragma unroll
        for (int o = 1; o < 32; o <<= 1) {
            int t = __shfl_up_sync(0xffffffffu, x, o);
            if (lane >= o) x += t;
        }
        if (lane == 31) wsum[w] = x;
        __syncthreads();
        if (w == 0) {
            int y = wsum[lane];
#pragma unroll
            for (int o = 1; o < 32; o <<= 1) {
                int t = __shfl_up_sync(0xffffffffu, y, o);
                if (lane >= o) y += t;
            }
            wsum[lane] = y;
        }
        __syncthreads();
        int pre = (w > 0) ? wsum[w - 1] : 0;
        int c = sc;
        if (i < NN) g_rowptr[i + 1] = c + pre + x;
        int total = wsum[31];
        __syncthreads();
        if (tid == 0) sc = c + total;
        __syncthreads();
    }
}

__global__ void k_fill_list(const int* __restrict__ edge_index) {
    int i = blockIdx.x * blockDim.x + threadIdx.x;
    if (i >= NE) return;
    int src, tgt;
    if (i < EE) { src = edge_index[i]; tgt = edge_index[EE + i]; }
    else        { src = i - EE;        tgt = i - EE; }
    int pos = atomicAdd(&g_cursor[tgt], 1);
    g_srclist[g_rowptr[tgt] + pos] = src;
}

// ---------------- fused prep: all weight transposes + bias pack -----------
#define P_S01 (H1 * NFEAT)
#define P_S2  (256 * H1)
#define P_S3  (NHID1 * NHID2)
#define P_S4  (NFEAT * NHID1)
#define P_TOT (P_S01 + P_S2 + P_S3 + P_S4 + 256)

__global__ void k_prep(const float* __restrict__ w1l, const float* __restrict__ w1r,
                       const float* __restrict__ w2l, const float* __restrict__ w2r,
                       const float* __restrict__ w3l, const float* __restrict__ w3r,
                       const float* __restrict__ dw1, const float* __restrict__ dw2,
                       const float* __restrict__ b2l, const float* __restrict__ b2r,
                       const float* __restrict__ b3l, const float* __restrict__ b3r) {
    int i = blockIdx.x * blockDim.x + threadIdx.x;
    if (i < P_S01) {
        int n = i / NFEAT, k = i - n * NFEAT;
        g_w1lh[i] = f16h(w1l[(size_t)k * H1 + n]);
        g_w1rh[i] = f16h(w1r[(size_t)k * H1 + n]);
        return;
    }
    i -= P_S01;
    if (i < P_S2) {
        int np = i >> 7, k = i & 127;
        int jj = np >> 6, n = np & 63;
        const float* W = (jj == 0) ? w2l : (jj == 1) ? w2r : (jj == 2) ? w3l : w3r;
        g_w23h[i] = f16h(W[(size_t)k * 64 + n]);
        return;
    }
    i -= P_S2;
    if (i < P_S3) {
        int n = i / NHID2, k = i - n * NHID2;
        g_dw1h[i] = f16h(dw1[(size_t)k * NHID1 + n]);
        return;
    }
    i -= P_S3;
    if (i < P_S4) {
        int n = i / NHID1, k = i - n * NHID1;
        g_dw2h[i] = f16h(dw2[(size_t)k * NFEAT + n]);
        return;
    }
    i -= P_S4;
    if (i < 256) {
        int jj = i >> 6, n = i & 63;
        const float* b = (jj == 0) ? b2l : (jj == 1) ? b2r : (jj == 2) ? b3l : b3r;
        g_bias23[i] = b[n];
    }
}

// ---------------- GEMM job plumbing ----------------
struct TJob  { const uint16_t* Bh; const float* bias; float* C; };
struct TJobs { TJob j[2]; };

// ---------------- gemmT: fp16 SINGLE-pass HMMA GEMM, 128x128, fp32 out ----
__global__ __launch_bounds__(256)
void gemmT(const float* __restrict__ A, TJobs jobs, int M, int K, int Nc,
           const float* __restrict__ bnG, const float* __restrict__ bnB) {
    const TJob jb = jobs.j[blockIdx.z];
    __shared__ __align__(16) uint16_t Ah[128][40];
    __shared__ __align__(16) uint16_t Bh[128][40];
    int tid = threadIdx.x, lane = tid & 31, warp = tid >> 5;
    int row0 = blockIdx.y * 128, col0 = blockIdx.x * 128;
    int wm = (warp & 1) * 64, wn = (warp >> 1) * 32;
    int grp = lane >> 3, rl = lane & 7;
    float c[4][4][4];
#pragma unroll
    for (int mi = 0; mi < 4; mi++)
#pragma unroll
        for (int ni = 0; ni < 4; ni++)
#pragma unroll
            for (int e = 0; e < 4; e++) c[mi][ni][e] = 0.f;

    int ar = tid >> 1, kh = (tid & 1) * 16;
    int r = row0 + ar;
    bool va = r < M;

    for (int k0 = 0; k0 < K; k0 += 32) {
        const float* pa = A + (size_t)r * K + k0 + kh;
#pragma unroll
        for (int q = 0; q < 4; q++) {
            float4 v = va ? *(const float4*)(pa + q * 4) : make_float4(0.f, 0.f, 0.f, 0.f);
            if (bnG) {
                int ch = k0 + kh + q * 4;
                float4 mm = *(const float4*)(g_mean + ch);
                float4 rs = *(const float4*)(g_rstd + ch);
                float4 gg = *(const float4*)(bnG + ch);
                float4 bb = *(const float4*)(bnB + ch);
                v.x = fmaxf((v.x - mm.x) * rs.x * gg.x + bb.x, 0.f);
                v.y = fmaxf((v.y - mm.y) * rs.y * gg.y + bb.y, 0.f);
                v.z = fmaxf((v.z - mm.z) * rs.z * gg.z + bb.z, 0.f);
                v.w = fmaxf((v.w - mm.w) * rs.w * gg.w + bb.w, 0.f);
            }
            *(uint32_t*)&Ah[ar][kh + q * 4]     = f16x2(v.x, v.y);
            *(uint32_t*)&Ah[ar][kh + q * 4 + 2] = f16x2(v.z, v.w);
        }
        {
            const uint16_t* pbh = jb.Bh + (size_t)(col0 + ar) * K + k0 + kh;
            *(uint4*)&Bh[ar][kh]     = *(const uint4*)pbh;
            *(uint4*)&Bh[ar][kh + 8] = *(const uint4*)(pbh + 8);
        }
        __syncthreads();
#pragma unroll
        for (int k1 = 0; k1 < 32; k1 += 16) {
            uint32_t af[4][4], bf[4][2];
#pragma unroll
            for (int mi = 0; mi < 4; mi++) {
                int arow = wm + mi * 16 + (grp & 1) * 8 + rl;
                int acol = k1 + (grp >> 1) * 8;
                ldsm_x4(af[mi][0], af[mi][1], af[mi][2], af[mi][3],
                        smem_u32(&Ah[arow][acol]));
            }
#pragma unroll
            for (int ni = 0; ni < 4; ni++) {
                int brow = wn + ni * 8 + rl;
                int bcol = k1 + (grp & 1) * 8;
                ldsm_x2(bf[ni][0], bf[ni][1], smem_u32(&Bh[brow][bcol]));
            }
#pragma unroll
            for (int mi = 0; mi < 4; mi++)
#pragma unroll
                for (int ni = 0; ni < 4; ni++)
                    mma_f16(c[mi][ni], af[mi][0], af[mi][1], af[mi][2], af[mi][3],
                            bf[ni][0], bf[ni][1]);
        }
        __syncthreads();
    }
    int qr = lane >> 2, qc = 2 * (lane & 3);
#pragma unroll
    for (int mi = 0; mi < 4; mi++) {
#pragma unroll
        for (int half = 0; half < 2; half++) {
            int row = wm + mi * 16 + qr + half * 8;
            int rr = row0 + row;
            if (rr < M) {
                float* Crow = jb.C + (size_t)rr * Nc;
#pragma unroll
                for (int ni = 0; ni < 4; ni++) {
                    int cc = col0 + wn + ni * 8 + qc;
                    float2 p;
                    p.x = c[mi][ni][2 * half]     + __ldg(&jb.bias[cc]);
                    p.y = c[mi][ni][2 * half + 1] + __ldg(&jb.bias[cc + 1]);
                    *(float2*)&Crow[cc] = p;
                }
            }
        }
    }
}

// ---------------- gemmTh: same but fp16 OUTPUT (for x23) ------------------
__global__ __launch_bounds__(256)
void gemmTh(const float* __restrict__ A, TJobs jobs, int M, int K, int Nc,
            const float* __restrict__ bnG, const float* __restrict__ bnB) {
    const TJob jb = jobs.j[blockIdx.z];
    __shared__ __align__(16) uint16_t Ah[128][40];
    __shared__ __align__(16) uint16_t Bh[128][40];
    int tid = threadIdx.x, lane = tid & 31, warp = tid >> 5;
    int row0 = blockIdx.y * 128, col0 = blockIdx.x * 128;
    int wm = (warp & 1) * 64, wn = (warp >> 1) * 32;
    int grp = lane >> 3, rl = lane & 7;
    float c[4][4][4];
#pragma unroll
    for (int mi = 0; mi < 4; mi++)
#pragma unroll
        for (int ni = 0; ni < 4; ni++)
#pragma unroll
            for (int e = 0; e < 4; e++) c[mi][ni][e] = 0.f;

    int ar = tid >> 1, kh = (tid & 1) * 16;
    int r = row0 + ar;
    bool va = r < M;

    for (int k0 = 0; k0 < K; k0 += 32) {
        const float* pa = A + (size_t)r * K + k0 + kh;
#pragma unroll
        for (int q = 0; q < 4; q++) {
            float4 v = va ? *(const float4*)(pa + q * 4) : make_float4(0.f, 0.f, 0.f, 0.f);
            if (bnG) {
                int ch = k0 + kh + q * 4;
                float4 mm = *(const float4*)(g_mean + ch);
                float4 rs = *(const float4*)(g_rstd + ch);
                float4 gg = *(const float4*)(bnG + ch);
                float4 bb = *(const float4*)(bnB + ch);
                v.x = fmaxf((v.x - mm.x) * rs.x * gg.x + bb.x, 0.f);
                v.y = fmaxf((v.y - mm.y) * rs.y * gg.y + bb.y, 0.f);
                v.z = fmaxf((v.z - mm.z) * rs.z * gg.z + bb.z, 0.f);
                v.w = fmaxf((v.w - mm.w) * rs.w * gg.w + bb.w, 0.f);
            }
            *(uint32_t*)&Ah[ar][kh + q * 4]     = f16x2(v.x, v.y);
            *(uint32_t*)&Ah[ar][kh + q * 4 + 2] = f16x2(v.z, v.w);
        }
        {
            const uint16_t* pbh = jb.Bh + (size_t)(col0 + ar) * K + k0 + kh;
            *(uint4*)&Bh[ar][kh]     = *(const uint4*)pbh;
            *(uint4*)&Bh[ar][kh + 8] = *(const uint4*)(pbh + 8);
        }
        __syncthreads();
#pragma unroll
        for (int k1 = 0; k1 < 32; k1 += 16) {
            uint32_t af[4][4], bf[4][2];
#pragma unroll
            for (int mi = 0; mi < 4; mi++) {
                int arow = wm + mi * 16 + (grp & 1) * 8 + rl;
                int acol = k1 + (grp >> 1) * 8;
                ldsm_x4(af[mi][0], af[mi][1], af[mi][2], af[mi][3],
                        smem_u32(&Ah[arow][acol]));
            }
#pragma unroll
            for (int ni = 0; ni < 4; ni++) {
                int brow = wn + ni * 8 + rl;
                int bcol = k1 + (grp & 1) * 8;
                ldsm_x2(bf[ni][0], bf[ni][1], smem_u32(&Bh[brow][bcol]));
            }
#pragma unroll
            for (int mi = 0; mi < 4; mi++)
#pragma unroll
                for (int ni = 0; ni < 4; ni++)
                    mma_f16(c[mi][ni], af[mi][0], af[mi][1], af[mi][2], af[mi][3],
                            bf[ni][0], bf[ni][1]);
        }
        __syncthreads();
    }
    int qr = lane >> 2, qc = 2 * (lane & 3);
#pragma unroll
    for (int mi = 0; mi < 4; mi++) {
#pragma unroll
        for (int half = 0; half < 2; half++) {
            int row = wm + mi * 16 + qr + half * 8;
            int rr = row0 + row;
            if (rr < M) {
                uint16_t* Crow = (uint16_t*)jb.C + (size_t)rr * Nc;
#pragma unroll
                for (int ni = 0; ni < 4; ni++) {
                    int cc = col0 + wn + ni * 8 + qc;
                    *(uint32_t*)&Crow[cc] = f16x2(c[mi][ni][2 * half]     + __ldg(&jb.bias[cc]),
                                                  c[mi][ni][2 * half + 1] + __ldg(&jb.bias[cc + 1]));
                }
            }
        }
    }
}

// ---------------- gemmT64h: 64x128 tile, fp16 out, single pass ------------
__global__ __launch_bounds__(256)
void gemmT64h(const float* __restrict__ A, TJobs jobs, int M, int K, int Nc) {
    const TJob jb = jobs.j[blockIdx.z];
    __shared__ __align__(16) uint16_t Ah[64][40];
    __shared__ __align__(16) uint16_t Bh[128][40];
    int tid = threadIdx.x, lane = tid & 31, warp = tid >> 5;
    int row0 = blockIdx.y * 64, col0 = blockIdx.x * 128;
    int wm = (warp & 1) * 32, wn = (warp >> 1) * 32;
    int grp = lane >> 3, rl = lane & 7;
    float c[2][4][4];
#pragma unroll
    for (int mi = 0; mi < 2; mi++)
#pragma unroll
        for (int ni = 0; ni < 4; ni++)
#pragma unroll
            for (int e = 0; e < 4; e++) c[mi][ni][e] = 0.f;

    int ar = tid >> 2, ks = (tid & 3) * 8;
    int br = tid >> 1, kb = (tid & 1) * 16;
    int r = row0 + ar;
    bool va = r < M;

    for (int k0 = 0; k0 < K; k0 += 32) {
        const float* pa = A + (size_t)r * K + k0 + ks;
#pragma unroll
        for (int q = 0; q < 2; q++) {
            float4 v = va ? *(const float4*)(pa + q * 4) : make_float4(0.f, 0.f, 0.f, 0.f);
            *(uint32_t*)&Ah[ar][ks + q * 4]     = f16x2(v.x, v.y);
            *(uint32_t*)&Ah[ar][ks + q * 4 + 2] = f16x2(v.z, v.w);
        }
        {
            const uint16_t* pbh = jb.Bh + (size_t)(col0 + br) * K + k0 + kb;
            *(uint4*)&Bh[br][kb]     = *(const uint4*)pbh;
            *(uint4*)&Bh[br][kb + 8] = *(const uint4*)(pbh + 8);
        }
        __syncthreads();
#pragma unroll
        for (int k1 = 0; k1 < 32; k1 += 16) {
            uint32_t af[2][4], bf[4][2];
#pragma unroll
            for (int mi = 0; mi < 2; mi++) {
                int arow = wm + mi * 16 + (grp & 1) * 8 + rl;
                int acol = k1 + (grp >> 1) * 8;
                ldsm_x4(af[mi][0], af[mi][1], af[mi][2], af[mi][3],
                        smem_u32(&Ah[arow][acol]));
            }
#pragma unroll
            for (int ni = 0; ni < 4; ni++) {
                int brow = wn + ni * 8 + rl;
                int bcol = k1 + (grp & 1) * 8;
                ldsm_x2(bf[ni][0], bf[ni][1], smem_u32(&Bh[brow][bcol]));
            }
#pragma unroll
            for (int mi = 0; mi < 2; mi++)
#pragma unroll
                for (int ni = 0; ni < 4; ni++)
                    mma_f16(c[mi][ni], af[mi][0], af[mi][1], af[mi][2], af[mi][3],
                            bf[ni][0], bf[ni][1]);
        }
        __syncthreads();
    }
    int qr = lane >> 2, qc = 2 * (lane & 3);
#pragma unroll
    for (int mi = 0; mi < 2; mi++) {
#pragma unroll
        for (int half = 0; half < 2; half++) {
            int row = wm + mi * 16 + qr + half * 8;
            int rr = row0 + row;
            if (rr < M) {
                uint16_t* Crow = (uint16_t*)jb.C + (size_t)rr * Nc;
#pragma unroll
                for (int ni = 0; ni < 4; ni++) {
                    int cc = col0 + wn + ni * 8 + qc;
                    *(uint32_t*)&Crow[cc] = f16x2(c[mi][ni][2 * half]     + __ldg(&jb.bias[cc]),
                                                  c[mi][ni][2 * half + 1] + __ldg(&jb.bias[cc + 1]));
                }
            }
        }
    }
}

// ---------------- gemmP: fp16 A direct, 128x128 tile, single pass ---------
__global__ __launch_bounds__(256)
void gemmP(const uint16_t* __restrict__ Ahg,
           const uint16_t* __restrict__ Bhg, const float* __restrict__ bias,
           float* __restrict__ C, int M, int K, int Nc) {
    __shared__ __align__(16) uint16_t Ah[128][40];
    __shared__ __align__(16) uint16_t Bh[128][40];
    int tid = threadIdx.x, lane = tid & 31, warp = tid >> 5;
    int row0 = blockIdx.y * 128, col0 = blockIdx.x * 128;
    int wm = (warp & 1) * 64, wn = (warp >> 1) * 32;
    int grp = lane >> 3, rl = lane & 7;
    float c[4][4][4];
#pragma unroll
    for (int mi = 0; mi < 4; mi++)
#pragma unroll
        for (int ni = 0; ni < 4; ni++)
#pragma unroll
            for (int e = 0; e < 4; e++) c[mi][ni][e] = 0.f;

    int ar = tid >> 1, kh = (tid & 1) * 16;
    int r = row0 + ar;
    bool va = r < M;
    uint4 z4 = make_uint4(0, 0, 0, 0);

    for (int k0 = 0; k0 < K; k0 += 32) {
        {
            const uint16_t* ph = Ahg + (size_t)r * K + k0 + kh;
            *(uint4*)&Ah[ar][kh]     = va ? *(const uint4*)ph : z4;
            *(uint4*)&Ah[ar][kh + 8] = va ? *(const uint4*)(ph + 8) : z4;
        }
        {
            const uint16_t* pbh = Bhg + (size_t)(col0 + ar) * K + k0 + kh;
            *(uint4*)&Bh[ar][kh]     = *(const uint4*)pbh;
            *(uint4*)&Bh[ar][kh + 8] = *(const uint4*)(pbh + 8);
        }
        __syncthreads();
#pragma unroll
        for (int k1 = 0; k1 < 32; k1 += 16) {
            uint32_t af[4][4], bf[4][2];
#pragma unroll
            for (int mi = 0; mi < 4; mi++) {
                int arow = wm + mi * 16 + (grp & 1) * 8 + rl;
                int acol = k1 + (grp >> 1) * 8;
                ldsm_x4(af[mi][0], af[mi][1], af[mi][2], af[mi][3],
                        smem_u32(&Ah[arow][acol]));
            }
#pragma unroll
            for (int ni = 0; ni < 4; ni++) {
                int brow = wn + ni * 8 + rl;
                int bcol = k1 + (grp & 1) * 8;
                ldsm_x2(bf[ni][0], bf[ni][1], smem_u32(&Bh[brow][bcol]));
            }
#pragma unroll
            for (int mi = 0; mi < 4; mi++)
#pragma unroll
                for (int ni = 0; ni < 4; ni++)
                    mma_f16(c[mi][ni], af[mi][0], af[mi][1], af[mi][2], af[mi][3],
                            bf[ni][0], bf[ni][1]);
        }
        __syncthreads();
    }
    int qr = lane >> 2, qc = 2 * (lane & 3);
#pragma unroll
    for (int mi = 0; mi < 4; mi++) {
#pragma unroll
        for (int half = 0; half < 2; half++) {
            int row = wm + mi * 16 + qr + half * 8;
            int rr = row0 + row;
            if (rr < M) {
                float* Crow = C + (size_t)rr * Nc;
#pragma unroll
                for (int ni = 0; ni < 4; ni++) {
                    int cc = col0 + wn + ni * 8 + qc;
                    float2 p;
                    p.x = c[mi][ni][2 * half]     + __ldg(&bias[cc]);
                    p.y = c[mi][ni][2 * half + 1] + __ldg(&bias[cc + 1]);
                    *(float2*)&Crow[cc] = p;
                }
            }
        }
    }
}

// ---------------- GAT layer 1: fused online-softmax, fp16 operands --------
__global__ void gat1_fused(const uint16_t* __restrict__ xlh,
                           const uint16_t* __restrict__ xrh,
                           const float* __restrict__ att, const float* __restrict__ bias,
                           float* __restrict__ out) {
    int t = blockIdx.x;
    int tid = threadIdx.x, lane = tid & 31, warp = tid >> 5;

    __shared__ float4 s_xr4[32], s_att4[32];
    __shared__ float  s_m[4], s_s[4];
    __shared__ float4 s_acc[4][32];
    if (tid < 32) {
        uint2 u = *(const uint2*)(xrh + (size_t)t * H1 + tid * 4);
        s_xr4[tid]  = h4_to_f4(u);
        s_att4[tid] = *(const float4*)(att + tid * 4);
    }
    int beg = g_rowptr[t];
    int deg = g_rowptr[t + 1] - beg;
    __syncthreads();

    float4 xr4 = s_xr4[lane];
    float4 at4 = s_att4[lane];

    float m0 = -1e30f, z0 = 0.f;
    float m1 = -1e30f, z1 = 0.f;
    float4 a0 = make_float4(0.f, 0.f, 0.f, 0.f), a1 = a0;

    int j = warp;
    for (; j + 4 < deg; j += 8) {
        int sA = g_srclist[beg + j];
        int sB = g_srclist[beg + j + 4];
        float4 vA = h4_to_f4(*(const uint2*)(xlh + (size_t)sA * H1 + lane * 4));
        float4 vB = h4_to_f4(*(const uint2*)(xlh + (size_t)sB * H1 + lane * 4));
        float pA, pB;
        {
            float a = vA.x + xr4.x; a = fmaxf(a, NEG_SLOPE * a);
            float b = vA.y + xr4.y; b = fmaxf(b, NEG_SLOPE * b);
            float c = vA.z + xr4.z; c = fmaxf(c, NEG_SLOPE * c);
            float d = vA.w + xr4.w; d = fmaxf(d, NEG_SLOPE * d);
            pA = at4.x * a + at4.y * b + at4.z * c + at4.w * d;
            a = vB.x + xr4.x; a = fmaxf(a, NEG_SLOPE * a);
            b = vB.y + xr4.y; b = fmaxf(b, NEG_SLOPE * b);
            c = vB.z + xr4.z; c = fmaxf(c, NEG_SLOPE * c);
            d = vB.w + xr4.w; d = fmaxf(d, NEG_SLOPE * d);
            pB = at4.x * a + at4.y * b + at4.z * c + at4.w * d;
        }
#pragma unroll
        for (int o = 16; o; o >>= 1) {
            pA += __shfl_xor_sync(0xffffffffu, pA, o);
            pB += __shfl_xor_sync(0xffffffffu, pB, o);
        }
        float mn0 = fmaxf(m0, pA);
        float sc0 = __expf(m0 - mn0);
        float w0  = __expf(pA - mn0);
        z0 = z0 * sc0 + w0;
        a0.x = a0.x * sc0 + w0 * vA.x;
        a0.y = a0.y * sc0 + w0 * vA.y;
        a0.z = a0.z * sc0 + w0 * vA.z;
        a0.w = a0.w * sc0 + w0 * vA.w;
        m0 = mn0;
        float mn1 = fmaxf(m1, pB);
        float sc1 = __expf(m1 - mn1);
        float w1  = __expf(pB - mn1);
        z1 = z1 * sc1 + w1;
        a1.x = a1.x * sc1 + w1 * vB.x;
        a1.y = a1.y * sc1 + w1 * vB.y;
        a1.z = a1.z * sc1 + w1 * vB.z;
        a1.w = a1.w * sc1 + w1 * vB.w;
        m1 = mn1;
    }
    if (j < deg) {
        int sA = g_srclist[beg + j];
        float4 vA = h4_to_f4(*(const uint2*)(xlh + (size_t)sA * H1 + lane * 4));
        float a = vA.x + xr4.x; a = fmaxf(a, NEG_SLOPE * a);
        float b = vA.y + xr4.y; b = fmaxf(b, NEG_SLOPE * b);
        float c = vA.z + xr4.z; c = fmaxf(c, NEG_SLOPE * c);
        float d = vA.w + xr4.w; d = fmaxf(d, NEG_SLOPE * d);
        float pA = at4.x * a + at4.y * b + at4.z * c + at4.w * d;
#pragma unroll
        for (int o = 16; o; o >>= 1) pA += __shfl_xor_sync(0xffffffffu, pA, o);
        float mn0 = fmaxf(m0, pA);
        float sc0 = __expf(m0 - mn0);
        float w0  = __expf(pA - mn0);
        z0 = z0 * sc0 + w0;
        a0.x = a0.x * sc0 + w0 * vA.x;
        a0.y = a0.y * sc0 + w0 * vA.y;
        a0.z = a0.z * sc0 + w0 * vA.z;
        a0.w = a0.w * sc0 + w0 * vA.w;
        m0 = mn0;
    }
    {
        float M = fmaxf(m0, m1);
        float e0 = __expf(m0 - M), e1 = __expf(m1 - M);
        z0 = z0 * e0 + z1 * e1;
        a0.x = a0.x * e0 + a1.x * e1;
        a0.y = a0.y * e0 + a1.y * e1;
        a0.z = a0.z * e0 + a1.z * e1;
        a0.w = a0.w * e0 + a1.w * e1;
        m0 = M;
    }
    if (lane == 0) { s_m[warp] = m0; s_s[warp] = z0; }
    s_acc[warp][lane] = a0;
    __syncthreads();

    if (tid < 32) {
        float M = s_m[0];
#pragma unroll
        for (int g = 1; g < 4; g++) M = fmaxf(M, s_m[g]);
        float zt = 0.f;
        float4 at = make_float4(0.f, 0.f, 0.f, 0.f);
#pragma unroll
        for (int g = 0; g < 4; g++) {
            float f = __expf(s_m[g] - M);
            zt += s_s[g] * f;
            float4 q = s_acc[g][tid];
            at.x += q.x * f; at.y += q.y * f; at.z += q.z * f; at.w += q.w * f;
        }
        float inv = 1.f / zt;
        float4 b4 = *(const float4*)(bias + tid * 4);
        float4 o4;
        o4.x = at.x * inv + b4.x;
        o4.y = at.y * inv + b4.y;
        o4.z = at.z * inv + b4.z;
        o4.w = at.w * inv + b4.w;
        *(float4*)(out + (size_t)t * H1 + tid * 4) = o4;
    }
}

// ---------------- GAT layers 2+3 merged + reparam, fp16 x23 ---------------
__global__ void gat23_fused(const uint16_t* __restrict__ x23,
                            const float* __restrict__ a2, const float* __restrict__ bias2,
                            const float* __restrict__ a3, const float* __restrict__ bias3,
                            const float* __restrict__ eps,
                            float* __restrict__ mu, float* __restrict__ lv,
                            float* __restrict__ emb) {
    int t = blockIdx.x;
    int tid = threadIdx.x, lane = tid & 31, warp = tid >> 5;
    int half = lane >> 4, lg = lane & 15;

    __shared__ float4 s_xr4[2][16], s_att4[2][16];
    __shared__ float  s_m[2][4], s_s[2][4];
    __shared__ float4 s_acc[2][4][16];
    if (tid < 32) {
        int h = tid >> 4, q = tid & 15;
        s_xr4[h][q]  = h4_to_f4(*(const uint2*)(x23 + (size_t)t * 256 + h * 128 + 64 + q * 4));
        s_att4[h][q] = *(const float4*)((h ? a3 : a2) + q * 4);
    }
    int beg = g_rowptr[t];
    int deg = g_rowptr[t + 1] - beg;
    __syncthreads();

    float4 xr4 = s_xr4[half][lg];
    float4 at4 = s_att4[half][lg];
    int coff = half * 128 + lg * 4;

    float m0 = -1e30f, z0 = 0.f;
    float m1 = -1e30f, z1 = 0.f;
    float4 a0 = make_float4(0.f, 0.f, 0.f, 0.f), a1 = a0;

    int j = warp;
    for (; j + 4 < deg; j += 8) {
        int sA = g_srclist[beg + j];
        int sB = g_srclist[beg + j + 4];
        float4 vA = h4_to_f4(*(const uint2*)(x23 + (size_t)sA * 256 + coff));
        float4 vB = h4_to_f4(*(const uint2*)(x23 + (size_t)sB * 256 + coff));
        float pA, pB;
        {
            float a = vA.x + xr4.x; a = fmaxf(a, NEG_SLOPE * a);
            float b = vA.y + xr4.y; b = fmaxf(b, NEG_SLOPE * b);
            float c = vA.z + xr4.z; c = fmaxf(c, NEG_SLOPE * c);
            float d = vA.w + xr4.w; d = fmaxf(d, NEG_SLOPE * d);
            pA = at4.x * a + at4.y * b + at4.z * c + at4.w * d;
            a = vB.x + xr4.x; a = fmaxf(a, NEG_SLOPE * a);
            b = vB.y + xr4.y; b = fmaxf(b, NEG_SLOPE * b);
            c = vB.z + xr4.z; c = fmaxf(c, NEG_SLOPE * c);
            d = vB.w + xr4.w; d = fmaxf(d, NEG_SLOPE * d);
            pB = at4.x * a + at4.y * b + at4.z * c + at4.w * d;
        }
#pragma unroll
        for (int o = 8; o; o >>= 1) {
            pA += __shfl_xor_sync(0xffffffffu, pA, o);
            pB += __shfl_xor_sync(0xffffffffu, pB, o);
        }
        float mn0 = fmaxf(m0, pA);
        float sc0 = __expf(m0 - mn0);
        float w0  = __expf(pA - mn0);
        z0 = z0 * sc0 + w0;
        a0.x = a0.x * sc0 + w0 * vA.x;
        a0.y = a0.y * sc0 + w0 * vA.y;
        a0.z = a0.z * sc0 + w0 * vA.z;
        a0.w = a0.w * sc0 + w0 * vA.w;
        m0 = mn0;
        float mn1 = fmaxf(m1, pB);
        float sc1 = __expf(m1 - mn1);
        float w1  = __expf(pB - mn1);
        z1 = z1 * sc1 + w1;
        a1.x = a1.x * sc1 + w1 * vB.x;
        a1.y = a1.y * sc1 + w1 * vB.y;
        a1.z = a1.z * sc1 + w1 * vB.z;
        a1.w = a1.w * sc1 + w1 * vB.w;
        m1 = mn1;
    }
    if (j < deg) {
        int sA = g_srclist[beg + j];
        float4 vA = h4_to_f4(*(const uint2*)(x23 + (size_t)sA * 256 + coff));
        float a = vA.x + xr4.x; a = fmaxf(a, NEG_SLOPE * a);
        float b = vA.y + xr4.y; b = fmaxf(b, NEG_SLOPE * b);
        float c = vA.z + xr4.z; c = fmaxf(c, NEG_SLOPE * c);
        float d = vA.w + xr4.w; d = fmaxf(d, NEG_SLOPE * d);
        float pA = at4.x * a + at4.y * b + at4.z * c + at4.w * d;
#pragma unroll
        for (int o = 8; o; o >>= 1) pA += __shfl_xor_sync(0xffffffffu, pA, o);
        float mn0 = fmaxf(m0, pA);
        float sc0 = __expf(m0 - mn0);
        float w0  = __expf(pA - mn0);
        z0 = z0 * sc0 + w0;
        a0.x = a0.x * sc0 + w0 * vA.x;
        a0.y = a0.y * sc0 + w0 * vA.y;
        a0.z = a0.z * sc0 + w0 * vA.z;
        a0.w = a0.w * sc0 + w0 * vA.w;
        m0 = mn0;
    }
    {
        float M = fmaxf(m0, m1);
        float e0 = __expf(m0 - M), e1 = __expf(m1 - M);
        z0 = z0 * e0 + z1 * e1;
        a0.x = a0.x * e0 + a1.x * e1;
        a0.y = a0.y * e0 + a1.y * e1;
        a0.z = a0.z * e0 + a1.z * e1;
        a0.w = a0.w * e0 + a1.w * e1;
        m0 = M;
    }
    if (lg == 0) { s_m[half][warp] = m0; s_s[half][warp] = z0; }
    s_acc[half][warp][lg] = a0;
    __syncthreads();

    if (tid < 32) {
        int h = tid >> 4, q = tid & 15;
        float M = s_m[h][0];
#pragma unroll
        for (int g = 1; g < 4; g++) M = fmaxf(M, s_m[h][g]);
        float zt = 0.f;
        float4 at = make_float4(0.f, 0.f, 0.f, 0.f);
#pragma unroll
        for (int g = 0; g < 4; g++) {
            float f = __expf(s_m[h][g] - M);
            zt += s_s[h][g] * f;
            float4 qq = s_acc[h][g][q];
            at.x += qq.x * f; at.y += qq.y * f; at.z += qq.z * f; at.w += qq.w * f;
        }
        float inv = 1.f / zt;
        float4 b4 = *(const float4*)((h ? bias3 : bias2) + q * 4);
        float4 o4;
        o4.x = at.x * inv + b4.x;
        o4.y = at.y * inv + b4.y;
        o4.z = at.z * inv + b4.z;
        o4.w = at.w * inv + b4.w;
        float* op = h ? lv : mu;
        *(float4*)(op + (size_t)t * 64 + q * 4) = o4;
        s_att4[h][q] = o4;
        __syncwarp();
        if (h == 0) {
            float4 mu4 = s_att4[0][q];
            float4 lv4 = s_att4[1][q];
            float4 e4 = *(const float4*)(eps + (size_t)t * 64 + q * 4);
            float4 em;
            em.x = e4.x * __expf(lv4.x) + mu4.x;
            em.y = e4.y * __expf(lv4.y) + mu4.y;
            em.z = e4.z * __expf(lv4.z) + mu4.z;
            em.w = e4.w * __expf(lv4.w) + mu4.w;
            *(float4*)(emb + (size_t)t * 64 + q * 4) = em;
            ushort4 vh;
            vh.x = f16h(em.x); vh.y = f16h(em.y);
            vh.z = f16h(em.z); vh.w = f16h(em.w);
            *(ushort4*)(g_ebh + (size_t)t * 64 + q * 4) = vh;
        }
    }
}

// ---------------- batch norm stats ----------------
template <int C>
__global__ void bn_stats(const float* __restrict__ h) {
    int c = blockIdx.x;
    int tid = threadIdx.x;
    float s = 0.f, s2 = 0.f;
    for (int r = tid; r < NN; r += 256) {
        float v = h[(size_t)r * C + c];
        s += v; s2 += v * v;
    }
    __shared__ float sh[8], sh2[8];
#pragma unroll
    for (int o = 16; o; o >>= 1) {
        s  += __shfl_xor_sync(0xffffffffu, s,  o);
        s2 += __shfl_xor_sync(0xffffffffu, s2, o);
    }
    if ((tid & 31) == 0) { sh[tid >> 5] = s; sh2[tid >> 5] = s2; }
    __syncthreads();
    if (tid == 0) {
        float ts = 0.f, ts2 = 0.f;
        for (int w = 0; w < 8; w++) { ts += sh[w]; ts2 += sh2[w]; }
        float mean = ts / NN;
        float var = ts2 / NN - mean * mean;
        g_mean[c] = mean;
        g_rstd[c] = rsqrtf(var + BN_EPS);
    }
}

// ---------------- readj = sigmoid(emb @ emb^T), fp16 single-pass HMMA -----
#define GP 72
#define G_AHI 0
#define G_BHI (G_AHI + 128 * GP * 2)
#define G_SMEM (G_BHI + 128 * GP * 2)   // 36864
#define MTG 79

__global__ __launch_bounds__(256)
void gram_hmma(const uint16_t* __restrict__ Eh, float* __restrict__ out) {
    int bid = blockIdx.x;
    int by = (int)(0.5f * (2.f * MTG + 1.f) -
                   sqrtf((2.f * MTG + 1.f) * (2.f * MTG + 1.f) * 0.25f - 2.f * (float)bid));
    if (by < 0) by = 0;
    if (by > MTG - 1) by = MTG - 1;
    int start = by * MTG - (by * (by - 1)) / 2;
    while (start > bid) { by--; start = by * MTG - (by * (by - 1)) / 2; }
    while (bid >= start + (MTG - by)) { by++; start = by * MTG - (by * (by - 1)) / 2; }
    int bx = by + (bid - start);

    extern __shared__ __align__(16) char smem[];
    uint32_t sb = smem_u32(smem);
    int tid = threadIdx.x, lane = tid & 31, warp = tid >> 5;
    int row0 = by * 128, col0 = bx * 128;

    {
        int rrow = tid & 127;
        uint4 z = make_uint4(0, 0, 0, 0);
        uint32_t base = (tid < 128) ? G_AHI : G_BHI;
        int rr = ((tid < 128) ? row0 : col0) + rrow;
        bool vr = rr < NN;
        const uint4* ph = (const uint4*)(Eh + (size_t)rr * 64);
#pragma unroll
        for (int q = 0; q < 8; q++) {
            uint32_t off = base + (rrow * GP + q * 8) * 2;
            *(uint4*)(smem + off) = vr ? ph[q] : z;
        }
    }
    __syncthreads();

    int wm = (warp & 1) * 64;
    int wn = (warp >> 1) * 32;
    float c[4][4][4];
#pragma unroll
    for (int mi = 0; mi < 4; mi++)
#pragma unroll
        for (int ni = 0; ni < 4; ni++)
#pragma unroll
            for (int e = 0; e < 4; e++) c[mi][ni][e] = 0.f;

    int grp = lane >> 3, rl = lane & 7;
#pragma unroll
    for (int k0 = 0; k0 < 64; k0 += 16) {
        uint32_t af[4][4], bf[4][2];
#pragma unroll
        for (int mi = 0; mi < 4; mi++) {
            int arow = wm + mi * 16 + (grp & 1) * 8 + rl;
            int acol = k0 + (grp >> 1) * 8;
            ldsm_x4(af[mi][0], af[mi][1], af[mi][2], af[mi][3],
                    sb + G_AHI + (arow * GP + acol) * 2);
        }
#pragma unroll
        for (int ni = 0; ni < 4; ni++) {
            int brow = wn + ni * 8 + rl;
            int bcol = k0 + (grp & 1) * 8;
            ldsm_x2(bf[ni][0], bf[ni][1], sb + G_BHI + (brow * GP + bcol) * 2);
        }
#pragma unroll
        for (int mi = 0; mi < 4; mi++)
#pragma unroll
            for (int ni = 0; ni < 4; ni++)
                mma_f16(c[mi][ni], af[mi][0], af[mi][1], af[mi][2], af[mi][3],
                        bf[ni][0], bf[ni][1]);
    }
    __syncthreads();

    bool diag = (bx == by);
    int qr = lane >> 2, qc = 2 * (lane & 3);
#pragma unroll
    for (int mi = 0; mi < 4; mi++) {
#pragma unroll
        for (int ni = 0; ni < 4; ni++) {
#pragma unroll
            for (int half = 0; half < 2; half++) {
                int row = wm + mi * 16 + qr + half * 8;
                int col = wn + ni * 8 + qc;
                float v0 = 1.f / (1.f + __expf(-c[mi][ni][2 * half]));
                float v1 = 1.f / (1.f + __expf(-c[mi][ni][2 * half + 1]));
                c[mi][ni][2 * half] = v0;
                c[mi][ni][2 * half + 1] = v1;
                int r = row0 + row, cc = col0 + col;
                if (r < NN && cc < NN)
                    *(float2*)(out + (size_t)r * NN + cc) = make_float2(v0, v1);
            }
        }
    }
    if (diag) return;

    float* stag = (float*)smem;
#pragma unroll
    for (int hIdx = 0; hIdx < 2; hIdx++) {
        __syncthreads();
        if ((warp & 1) == hIdx) {
#pragma unroll
            for (int mi = 0; mi < 4; mi++) {
#pragma unroll
                for (int ni = 0; ni < 4; ni++) {
#pragma unroll
                    for (int half = 0; half < 2; half++) {
                        int row = wm + mi * 16 + qr + half * 8;
                        int lrow = row & 63;
                        int col = wn + ni * 8 + qc;
                        int s = row & 31;
                        stag[lrow * 128 + (col ^ s)] = c[mi][ni][2 * half];
                        stag[lrow * 128 + ((col + 1) ^ s)] = c[mi][ni][2 * half + 1];
                    }
                }
            }
        }
        __syncthreads();
        for (int cc = warp; cc < 128; cc += 8) {
            int cgl = col0 + cc;
            if (cgl >= NN) continue;
            float* mrow = out + (size_t)cgl * NN + row0 + hIdx * 64;
#pragma unroll
            for (int ib = 0; ib < 64; ib += 32) {
                int i = ib + lane;
                int grow = hIdx * 64 + i;
                if (row0 + grow < NN)
                    mrow[i] = stag[i * 128 + (cc ^ (grow & 31))];
            }
        }
    }
}

// ---------------- launch ----------------
extern "C" void kernel_launch(void* const* d_in, const int* in_sizes, int n_in,
                              void* d_out, int out_size) {
    const float* x   = (const float*)d_in[0];
    const int*   ei  = (const int*)  d_in[1];
    const float* eps = (const float*)d_in[2];
    const float* w1l = (const float*)d_in[3];
    const float* b1l = (const float*)d_in[4];
    const float* w1r = (const float*)d_in[5];
    const float* b1r = (const float*)d_in[6];
    const float* a1  = (const float*)d_in[7];
    const float* bias1 = (const float*)d_in[8];
    const float* bn1_g = (const float*)d_in[9];
    const float* bn1_b = (const float*)d_in[10];
    const float* w2l = (const float*)d_in[11];
    const float* b2l = (const float*)d_in[12];
    const float* w2r = (const float*)d_in[13];
    const float* b2r = (const float*)d_in[14];
    const float* a2  = (const float*)d_in[15];
    const float* bias2 = (const float*)d_in[16];
    const float* w3l = (const float*)d_in[17];
    const float* b3l = (const float*)d_in[18];
    const float* w3r = (const float*)d_in[19];
    const float* b3r = (const float*)d_in[20];
    const float* a3  = (const float*)d_in[21];
    const float* bias3 = (const float*)d_in[22];
    const float* dw1 = (const float*)d_in[23];
    const float* db1 = (const float*)d_in[24];
    const float* dbn_g = (const float*)d_in[25];
    const float* dbn_b = (const float*)d_in[26];
    const float* dw2 = (const float*)d_in[27];
    const float* db2 = (const float*)d_in[28];
    float* out = (float*)d_out;

    float *p_h, *p_d, *p_b23;
    cudaGetSymbolAddress((void**)&p_h,   g_h);
    cudaGetSymbolAddress((void**)&p_d,   g_d);
    cudaGetSymbolAddress((void**)&p_b23, g_bias23);
    uint16_t *p_xl1h, *p_xr1h, *p_x23h, *p_w1lh, *p_w1rh, *p_w23h, *p_dw1h, *p_dw2h, *p_ebh;
    cudaGetSymbolAddress((void**)&p_xl1h, g_xl1h);
    cudaGetSymbolAddress((void**)&p_xr1h, g_xr1h);
    cudaGetSymbolAddress((void**)&p_x23h, g_x23h);
    cudaGetSymbolAddress((void**)&p_w1lh, g_w1lh);
    cudaGetSymbolAddress((void**)&p_w1rh, g_w1rh);
    cudaGetSymbolAddress((void**)&p_w23h, g_w23h);
    cudaGetSymbolAddress((void**)&p_dw1h, g_dw1h);
    cudaGetSymbolAddress((void**)&p_dw2h, g_dw2h);
    cudaGetSymbolAddress((void**)&p_ebh,  g_ebh);

    cudaFuncSetAttribute(gram_hmma, cudaFuncAttributeMaxDynamicSharedMemorySize, G_SMEM);

    static cudaStream_t s_side = nullptr;
    static cudaEvent_t evA = nullptr, evB = nullptr, evC = nullptr, evD = nullptr;
    if (!s_side) {
        cudaStreamCreateWithFlags(&s_side, cudaStreamNonBlocking);
        cudaEventCreateWithFlags(&evA, cudaEventDisableTiming);
        cudaEventCreateWithFlags(&evB, cudaEventDisableTiming);
        cudaEventCreateWithFlags(&evC, cudaEventDisableTiming);
        cudaEventCreateWithFlags(&evD, cudaEventDisableTiming);
    }

    const int MT  = (NN + 127) / 128;   // 79
    const int MT64 = (NN + 63) / 64;    // 157

    // ---- fork: CSR build on side stream ----
    cudaEventRecord(evA, 0);
    cudaStreamWaitEvent(s_side, evA, 0);
    k_zero_counts<<<(NN + 255) / 256, 256, 0, s_side>>>();
    k_count_deg<<<(NE + 255) / 256, 256, 0, s_side>>>(ei);
    k_scan_deg<<<1, 1024, 0, s_side>>>();
    k_fill_list<<<(NE + 255) / 256, 256, 0, s_side>>>(ei);
    cudaEventRecord(evB, s_side);

    // ---- main: fused prep + layer-1 GEMM (fp16 output) ----
    k_prep<<<(P_TOT + 255) / 256, 256>>>(w1l, w1r, w2l, w2r, w3l, w3r, dw1, dw2,
                                         b2l, b2r, b3l, b3r);
    {
        TJobs j1 = {{ { p_w1lh, b1l, (float*)p_xl1h }, { p_w1rh, b1r, (float*)p_xr1h } }};
        gemmT64h<<<dim3(1, MT64, 2), 256>>>(x, j1, NN, NFEAT, H1);
    }
    cudaStreamWaitEvent(0, evB, 0);   // join CSR

    // ---- GAT layer 1 (fp16 gather, fused online softmax) -> BN stats ----
    gat1_fused<<<NN, 128>>>(p_xl1h, p_xr1h, a1, bias1, p_h);
    bn_stats<H1><<<H1, 256>>>(p_h);

    // ---- layers 2 & 3 packed GEMM (BN+ReLU fused, fp16 output) ----
    {
        TJobs j2 = {{ { p_w23h, p_b23, (float*)p_x23h }, {} }};
        gemmTh<<<dim3(2, MT, 1), 256>>>(p_h, j2, NN, H1, 256, bn1_g, bn1_b);
    }

    // ---- GAT layers 2+3 merged + fused reparameterize (fp16 gather) ----
    gat23_fused<<<NN, 128>>>(p_x23h, a2, bias2, a3, bias3, eps,
                             out + MU_OFF, out + LV_OFF, out + EMB_OFF);

    // ---- fork: decoder MLP on side stream, gram on main ----
    cudaEventRecord(evC, 0);
    cudaStreamWaitEvent(s_side, evC, 0);
    gemmP<<<dim3(2, MT, 1), 256, 0, s_side>>>(p_ebh, p_dw1h, db1, p_d,
                                              NN, NHID2, NHID1);
    bn_stats<NHID1><<<NHID1, 256, 0, s_side>>>(p_d);
    {
        TJobs jd = {{ { p_dw2h, db2, out + REX_OFF }, {} }};
        gemmT<<<dim3(4, MT, 1), 256, 0, s_side>>>(p_d, jd, NN, NHID1, NFEAT,
                                                  dbn_g, dbn_b);
    }
    cudaEventRecord(evD, s_side);

    gram_hmma<<<MT * (MT + 1) / 2, 256, G_SMEM>>>(p_ebh, out + READJ_OFF);

    cudaStreamWaitEvent(0, evD, 0);   // join decoder
}

// round 17
// speedup vs baseline: 1.2897x; 1.0054x over previous
#include <cuda_runtime.h>
#include <cuda_fp16.h>
#include <cstdint>
#include <math.h>

#define NN     10000
#define EE     320000
#define NE     (EE + NN)     // with self loops
#define NFEAT  512
#define NHID1  256
#define NHID2  64
#define H1     128           // 2*nhid2
#define NEG_SLOPE 0.2f
#define BN_EPS 1e-5f

// output layout (flattened tuple: emb, re_x, readj, mu, logvar)
#define EMB_OFF   ((size_t)0)
#define REX_OFF   ((size_t)NN * NHID2)
#define READJ_OFF (REX_OFF + (size_t)NN * NFEAT)
#define MU_OFF    (READJ_OFF + (size_t)NN * NN)
#define LV_OFF    (MU_OFF + (size_t)NN * NHID2)

typedef unsigned long long u64;

// ---------------- warp MMA helpers (baseline PTX, works on sm_103) --------
__device__ __forceinline__ uint32_t smem_u32(const void* p) {
    uint32_t a;
    asm("{ .reg .u64 t; cvta.to.shared.u64 t, %1; cvt.u32.u64 %0, t; }" : "=r"(a) : "l"(p));
    return a;
}
__device__ __forceinline__ void ldsm_x4(uint32_t& r0, uint32_t& r1, uint32_t& r2, uint32_t& r3, uint32_t addr) {
    asm volatile("ldmatrix.sync.aligned.m8n8.x4.shared.b16 {%0,%1,%2,%3}, [%4];"
                 : "=r"(r0), "=r"(r1), "=r"(r2), "=r"(r3) : "r"(addr));
}
__device__ __forceinline__ void ldsm_x2(uint32_t& r0, uint32_t& r1, uint32_t addr) {
    asm volatile("ldmatrix.sync.aligned.m8n8.x2.shared.b16 {%0,%1}, [%2];"
                 : "=r"(r0), "=r"(r1) : "r"(addr));
}
__device__ __forceinline__ void mma_f16(float* d, uint32_t a0, uint32_t a1, uint32_t a2, uint32_t a3,
                                        uint32_t b0, uint32_t b1) {
    asm volatile("mma.sync.aligned.m16n8k16.row.col.f32.f16.f16.f32 "
                 "{%0,%1,%2,%3}, {%4,%5,%6,%7}, {%8,%9}, {%0,%1,%2,%3};"
                 : "+f"(d[0]), "+f"(d[1]), "+f"(d[2]), "+f"(d[3])
                 : "r"(a0), "r"(a1), "r"(a2), "r"(a3), "r"(b0), "r"(b1));
}
__device__ __forceinline__ uint16_t f16h(float v) {
    return __half_as_ushort(__float2half_rn(v));
}
__device__ __forceinline__ uint32_t f16x2(float a, float b) {
    __half2 h = __floats2half2_rn(a, b);
    return *(uint32_t*)&h;
}
__device__ __forceinline__ float4 h4_to_f4(uint2 u) {
    __half2 a = *(__half2*)&u.x;
    __half2 b = *(__half2*)&u.y;
    float2 fa = __half22float2(a);
    float2 fb = __half22float2(b);
    return make_float4(fa.x, fa.y, fb.x, fb.y);
}

// ---------------- scratch (device globals; no allocation allowed) ----------
__device__ uint16_t g_xl1h[NN * H1];    // fp16 layer-1 outputs (GAT1 only)
__device__ uint16_t g_xr1h[NN * H1];
__device__ float g_h  [NN * H1];
__device__ uint16_t g_x23h[NN * 256];   // fp16 packed: xl2|xr2|xl3|xr3
__device__ float g_d  [NN * NHID1];
__device__ int   g_deg[NN];
__device__ int   g_rowptr[NN + 1];
__device__ int   g_cursor[NN];
__device__ int   g_srclist[NE];
__device__ float g_mean[NHID1];
__device__ float g_rstd[NHID1];
__device__ float g_bias23[256];
// emb fp16 (gram + decoder GEMM)
__device__ uint16_t g_ebh[NN * NHID2];
// transposed fp16 weights [Nc][K]
__device__ uint16_t g_w1lh[H1 * NFEAT];
__device__ uint16_t g_w1rh[H1 * NFEAT];
__device__ uint16_t g_w23h[256 * H1];
__device__ uint16_t g_dw1h[NHID1 * NHID2];
__device__ uint16_t g_dw2h[NFEAT * NHID1];

// ---------------- CSR build ----------------
__global__ void k_zero_counts() {
    int i = blockIdx.x * blockDim.x + threadIdx.x;
    if (i < NN) { g_deg[i] = 0; g_cursor[i] = 0; }
}

__global__ void k_count_deg(const int* __restrict__ edge_index) {
    int i = blockIdx.x * blockDim.x + threadIdx.x;
    if (i >= NE) return;
    int tgt = (i < EE) ? edge_index[EE + i] : (i - EE);
    atomicAdd(&g_deg[tgt], 1);
}

__global__ void k_scan_deg() {
    __shared__ int wsum[32];
    __shared__ int sc;
    int tid = threadIdx.x, lane = tid & 31, w = tid >> 5;
    if (tid == 0) { sc = 0; g_rowptr[0] = 0; }
    __syncthreads();
    for (int base = 0; base < NN; base += 1024) {
        int i = base + tid;
        int v = (i < NN) ? g_deg[i] : 0;
        int x = v;
#pragma unroll
        for (int o = 1; o < 32; o <<= 1) {
            int t = __shfl_up_sync(0xffffffffu, x, o);
            if (lane >= o) x += t;
        }
        if (lane == 31) wsum[w] = x;
        __syncthreads();
        if (w == 0) {
            int y = wsum[lane];
#pragma unroll
            for (int o = 1; o < 32; o <<= 1) {
                int t = __shfl_up_sync(0xffffffffu, y, o);
                if (lane >= o) y += t;
            }
            wsum[lane] = y;
        }
        __syncthreads();
        int pre = (w > 0) ? wsum[w - 1] : 0;
        int c = sc;
        if (i < NN) g_rowptr[i + 1] = c + pre + x;
        int total = wsum[31];
        __syncthreads();
        if (tid == 0) sc = c + total;
        __syncthreads();
    }
}

__global__ void k_fill_list(const int* __restrict__ edge_index) {
    int i = blockIdx.x * blockDim.x + threadIdx.x;
    if (i >= NE) return;
    int src, tgt;
    if (i < EE) { src = edge_index[i]; tgt = edge_index[EE + i]; }
    else        { src = i - EE;        tgt = i - EE; }
    int pos = atomicAdd(&g_cursor[tgt], 1);
    g_srclist[g_rowptr[tgt] + pos] = src;
}

// ---------------- fused prep: all weight transposes + bias pack -----------
#define P_S01 (H1 * NFEAT)
#define P_S2  (256 * H1)
#define P_S3  (NHID1 * NHID2)
#define P_S4  (NFEAT * NHID1)
#define P_TOT (P_S01 + P_S2 + P_S3 + P_S4 + 256)

__global__ void k_prep(const float* __restrict__ w1l, const float* __restrict__ w1r,
                       const float* __restrict__ w2l, const float* __restrict__ w2r,
                       const float* __restrict__ w3l, const float* __restrict__ w3r,
                       const float* __restrict__ dw1, const float* __restrict__ dw2,
                       const float* __restrict__ b2l, const float* __restrict__ b2r,
                       const float* __restrict__ b3l, const float* __restrict__ b3r) {
    int i = blockIdx.x * blockDim.x + threadIdx.x;
    if (i < P_S01) {
        int n = i / NFEAT, k = i - n * NFEAT;
        g_w1lh[i] = f16h(w1l[(size_t)k * H1 + n]);
        g_w1rh[i] = f16h(w1r[(size_t)k * H1 + n]);
        return;
    }
    i -= P_S01;
    if (i < P_S2) {
        int np = i >> 7, k = i & 127;
        int jj = np >> 6, n = np & 63;
        const float* W = (jj == 0) ? w2l : (jj == 1) ? w2r : (jj == 2) ? w3l : w3r;
        g_w23h[i] = f16h(W[(size_t)k * 64 + n]);
        return;
    }
    i -= P_S2;
    if (i < P_S3) {
        int n = i / NHID2, k = i - n * NHID2;
        g_dw1h[i] = f16h(dw1[(size_t)k * NHID1 + n]);
        return;
    }
    i -= P_S3;
    if (i < P_S4) {
        int n = i / NHID1, k = i - n * NHID1;
        g_dw2h[i] = f16h(dw2[(size_t)k * NFEAT + n]);
        return;
    }
    i -= P_S4;
    if (i < 256) {
        int jj = i >> 6, n = i & 63;
        const float* b = (jj == 0) ? b2l : (jj == 1) ? b2r : (jj == 2) ? b3l : b3r;
        g_bias23[i] = b[n];
    }
}

// ---------------- GEMM job plumbing ----------------
struct TJob  { const uint16_t* Bh; const float* bias; float* C; };
struct TJobs { TJob j[2]; };

// ---------------- gemmDual: shared-A dual-job GEMM, 64x128 tile, fp16 out -
// Computes BOTH jobs (same A) per block: A loaded/converted once, af
// fragments reused. K % 32 == 0, Nc == 128 (single col tile).
__global__ __launch_bounds__(256)
void gemmDual(const float* __restrict__ A, TJobs jobs, int M, int K) {
    const int Nc = 128;
    __shared__ __align__(16) uint16_t Ah[64][40];
    __shared__ __align__(16) uint16_t B0[128][40];
    __shared__ __align__(16) uint16_t B1[128][40];
    int tid = threadIdx.x, lane = tid & 31, warp = tid >> 5;
    int row0 = blockIdx.y * 64;
    int wm = (warp & 1) * 32, wn = (warp >> 1) * 32;
    int grp = lane >> 3, rl = lane & 7;
    float c0[2][4][4], c1[2][4][4];
#pragma unroll
    for (int mi = 0; mi < 2; mi++)
#pragma unroll
        for (int ni = 0; ni < 4; ni++)
#pragma unroll
            for (int e = 0; e < 4; e++) { c0[mi][ni][e] = 0.f; c1[mi][ni][e] = 0.f; }

    int ar = tid >> 2, ks = (tid & 3) * 8;
    int br = tid >> 1, kb = (tid & 1) * 16;
    int r = row0 + ar;
    bool va = r < M;

    for (int k0 = 0; k0 < K; k0 += 32) {
        const float* pa = A + (size_t)r * K + k0 + ks;
#pragma unroll
        for (int q = 0; q < 2; q++) {
            float4 v = va ? *(const float4*)(pa + q * 4) : make_float4(0.f, 0.f, 0.f, 0.f);
            *(uint32_t*)&Ah[ar][ks + q * 4]     = f16x2(v.x, v.y);
            *(uint32_t*)&Ah[ar][ks + q * 4 + 2] = f16x2(v.z, v.w);
        }
        {
            const uint16_t* pb0 = jobs.j[0].Bh + (size_t)br * K + k0 + kb;
            const uint16_t* pb1 = jobs.j[1].Bh + (size_t)br * K + k0 + kb;
            *(uint4*)&B0[br][kb]     = *(const uint4*)pb0;
            *(uint4*)&B0[br][kb + 8] = *(const uint4*)(pb0 + 8);
            *(uint4*)&B1[br][kb]     = *(const uint4*)pb1;
            *(uint4*)&B1[br][kb + 8] = *(const uint4*)(pb1 + 8);
        }
        __syncthreads();
#pragma unroll
        for (int k1 = 0; k1 < 32; k1 += 16) {
            uint32_t af[2][4], bf0[4][2], bf1[4][2];
#pragma unroll
            for (int mi = 0; mi < 2; mi++) {
                int arow = wm + mi * 16 + (grp & 1) * 8 + rl;
                int acol = k1 + (grp >> 1) * 8;
                ldsm_x4(af[mi][0], af[mi][1], af[mi][2], af[mi][3],
                        smem_u32(&Ah[arow][acol]));
            }
#pragma unroll
            for (int ni = 0; ni < 4; ni++) {
                int brow = wn + ni * 8 + rl;
                int bcol = k1 + (grp & 1) * 8;
                ldsm_x2(bf0[ni][0], bf0[ni][1], smem_u32(&B0[brow][bcol]));
                ldsm_x2(bf1[ni][0], bf1[ni][1], smem_u32(&B1[brow][bcol]));
            }
#pragma unroll
            for (int mi = 0; mi < 2; mi++)
#pragma unroll
                for (int ni = 0; ni < 4; ni++) {
                    mma_f16(c0[mi][ni], af[mi][0], af[mi][1], af[mi][2], af[mi][3],
                            bf0[ni][0], bf0[ni][1]);
                    mma_f16(c1[mi][ni], af[mi][0], af[mi][1], af[mi][2], af[mi][3],
                            bf1[ni][0], bf1[ni][1]);
                }
        }
        __syncthreads();
    }
    int qr = lane >> 2, qc = 2 * (lane & 3);
#pragma unroll
    for (int mi = 0; mi < 2; mi++) {
#pragma unroll
        for (int half = 0; half < 2; half++) {
            int row = wm + mi * 16 + qr + half * 8;
            int rr = row0 + row;
            if (rr < M) {
                uint16_t* C0 = (uint16_t*)jobs.j[0].C + (size_t)rr * Nc;
                uint16_t* C1 = (uint16_t*)jobs.j[1].C + (size_t)rr * Nc;
#pragma unroll
                for (int ni = 0; ni < 4; ni++) {
                    int cc = wn + ni * 8 + qc;
                    *(uint32_t*)&C0[cc] = f16x2(c0[mi][ni][2 * half]     + __ldg(&jobs.j[0].bias[cc]),
                                                c0[mi][ni][2 * half + 1] + __ldg(&jobs.j[0].bias[cc + 1]));
                    *(uint32_t*)&C1[cc] = f16x2(c1[mi][ni][2 * half]     + __ldg(&jobs.j[1].bias[cc]),
                                                c1[mi][ni][2 * half + 1] + __ldg(&jobs.j[1].bias[cc + 1]));
                }
            }
        }
    }
}

// ---------------- gemmT: fp16 single-pass HMMA GEMM, 128x128, fp32 out ----
__global__ __launch_bounds__(256)
void gemmT(const float* __restrict__ A, TJobs jobs, int M, int K, int Nc,
           const float* __restrict__ bnG, const float* __restrict__ bnB) {
    const TJob jb = jobs.j[blockIdx.z];
    __shared__ __align__(16) uint16_t Ah[128][40];
    __shared__ __align__(16) uint16_t Bh[128][40];
    int tid = threadIdx.x, lane = tid & 31, warp = tid >> 5;
    int row0 = blockIdx.y * 128, col0 = blockIdx.x * 128;
    int wm = (warp & 1) * 64, wn = (warp >> 1) * 32;
    int grp = lane >> 3, rl = lane & 7;
    float c[4][4][4];
#pragma unroll
    for (int mi = 0; mi < 4; mi++)
#pragma unroll
        for (int ni = 0; ni < 4; ni++)
#pragma unroll
            for (int e = 0; e < 4; e++) c[mi][ni][e] = 0.f;

    int ar = tid >> 1, kh = (tid & 1) * 16;
    int r = row0 + ar;
    bool va = r < M;

    for (int k0 = 0; k0 < K; k0 += 32) {
        const float* pa = A + (size_t)r * K + k0 + kh;
#pragma unroll
        for (int q = 0; q < 4; q++) {
            float4 v = va ? *(const float4*)(pa + q * 4) : make_float4(0.f, 0.f, 0.f, 0.f);
            if (bnG) {
                int ch = k0 + kh + q * 4;
                float4 mm = *(const float4*)(g_mean + ch);
                float4 rs = *(const float4*)(g_rstd + ch);
                float4 gg = *(const float4*)(bnG + ch);
                float4 bb = *(const float4*)(bnB + ch);
                v.x = fmaxf((v.x - mm.x) * rs.x * gg.x + bb.x, 0.f);
                v.y = fmaxf((v.y - mm.y) * rs.y * gg.y + bb.y, 0.f);
                v.z = fmaxf((v.z - mm.z) * rs.z * gg.z + bb.z, 0.f);
                v.w = fmaxf((v.w - mm.w) * rs.w * gg.w + bb.w, 0.f);
            }
            *(uint32_t*)&Ah[ar][kh + q * 4]     = f16x2(v.x, v.y);
            *(uint32_t*)&Ah[ar][kh + q * 4 + 2] = f16x2(v.z, v.w);
        }
        {
            const uint16_t* pbh = jb.Bh + (size_t)(col0 + ar) * K + k0 + kh;
            *(uint4*)&Bh[ar][kh]     = *(const uint4*)pbh;
            *(uint4*)&Bh[ar][kh + 8] = *(const uint4*)(pbh + 8);
        }
        __syncthreads();
#pragma unroll
        for (int k1 = 0; k1 < 32; k1 += 16) {
            uint32_t af[4][4], bf[4][2];
#pragma unroll
            for (int mi = 0; mi < 4; mi++) {
                int arow = wm + mi * 16 + (grp & 1) * 8 + rl;
                int acol = k1 + (grp >> 1) * 8;
                ldsm_x4(af[mi][0], af[mi][1], af[mi][2], af[mi][3],
                        smem_u32(&Ah[arow][acol]));
            }
#pragma unroll
            for (int ni = 0; ni < 4; ni++) {
                int brow = wn + ni * 8 + rl;
                int bcol = k1 + (grp & 1) * 8;
                ldsm_x2(bf[ni][0], bf[ni][1], smem_u32(&Bh[brow][bcol]));
            }
#pragma unroll
            for (int mi = 0; mi < 4; mi++)
#pragma unroll
                for (int ni = 0; ni < 4; ni++)
                    mma_f16(c[mi][ni], af[mi][0], af[mi][1], af[mi][2], af[mi][3],
                            bf[ni][0], bf[ni][1]);
        }
        __syncthreads();
    }
    int qr = lane >> 2, qc = 2 * (lane & 3);
#pragma unroll
    for (int mi = 0; mi < 4; mi++) {
#pragma unroll
        for (int half = 0; half < 2; half++) {
            int row = wm + mi * 16 + qr + half * 8;
            int rr = row0 + row;
            if (rr < M) {
                float* Crow = jb.C + (size_t)rr * Nc;
#pragma unroll
                for (int ni = 0; ni < 4; ni++) {
                    int cc = col0 + wn + ni * 8 + qc;
                    float2 p;
                    p.x = c[mi][ni][2 * half]     + __ldg(&jb.bias[cc]);
                    p.y = c[mi][ni][2 * half + 1] + __ldg(&jb.bias[cc + 1]);
                    *(float2*)&Crow[cc] = p;
                }
            }
        }
    }
}

// ---------------- gemmTh: same but fp16 OUTPUT (for x23) ------------------
__global__ __launch_bounds__(256)
void gemmTh(const float* __restrict__ A, TJobs jobs, int M, int K, int Nc,
            const float* __restrict__ bnG, const float* __restrict__ bnB) {
    const TJob jb = jobs.j[blockIdx.z];
    __shared__ __align__(16) uint16_t Ah[128][40];
    __shared__ __align__(16) uint16_t Bh[128][40];
    int tid = threadIdx.x, lane = tid & 31, warp = tid >> 5;
    int row0 = blockIdx.y * 128, col0 = blockIdx.x * 128;
    int wm = (warp & 1) * 64, wn = (warp >> 1) * 32;
    int grp = lane >> 3, rl = lane & 7;
    float c[4][4][4];
#pragma unroll
    for (int mi = 0; mi < 4; mi++)
#pragma unroll
        for (int ni = 0; ni < 4; ni++)
#pragma unroll
            for (int e = 0; e < 4; e++) c[mi][ni][e] = 0.f;

    int ar = tid >> 1, kh = (tid & 1) * 16;
    int r = row0 + ar;
    bool va = r < M;

    for (int k0 = 0; k0 < K; k0 += 32) {
        const float* pa = A + (size_t)r * K + k0 + kh;
#pragma unroll
        for (int q = 0; q < 4; q++) {
            float4 v = va ? *(const float4*)(pa + q * 4) : make_float4(0.f, 0.f, 0.f, 0.f);
            if (bnG) {
                int ch = k0 + kh + q * 4;
                float4 mm = *(const float4*)(g_mean + ch);
                float4 rs = *(const float4*)(g_rstd + ch);
                float4 gg = *(const float4*)(bnG + ch);
                float4 bb = *(const float4*)(bnB + ch);
                v.x = fmaxf((v.x - mm.x) * rs.x * gg.x + bb.x, 0.f);
                v.y = fmaxf((v.y - mm.y) * rs.y * gg.y + bb.y, 0.f);
                v.z = fmaxf((v.z - mm.z) * rs.z * gg.z + bb.z, 0.f);
                v.w = fmaxf((v.w - mm.w) * rs.w * gg.w + bb.w, 0.f);
            }
            *(uint32_t*)&Ah[ar][kh + q * 4]     = f16x2(v.x, v.y);
            *(uint32_t*)&Ah[ar][kh + q * 4 + 2] = f16x2(v.z, v.w);
        }
        {
            const uint16_t* pbh = jb.Bh + (size_t)(col0 + ar) * K + k0 + kh;
            *(uint4*)&Bh[ar][kh]     = *(const uint4*)pbh;
            *(uint4*)&Bh[ar][kh + 8] = *(const uint4*)(pbh + 8);
        }
        __syncthreads();
#pragma unroll
        for (int k1 = 0; k1 < 32; k1 += 16) {
            uint32_t af[4][4], bf[4][2];
#pragma unroll
            for (int mi = 0; mi < 4; mi++) {
                int arow = wm + mi * 16 + (grp & 1) * 8 + rl;
                int acol = k1 + (grp >> 1) * 8;
                ldsm_x4(af[mi][0], af[mi][1], af[mi][2], af[mi][3],
                        smem_u32(&Ah[arow][acol]));
            }
#pragma unroll
            for (int ni = 0; ni < 4; ni++) {
                int brow = wn + ni * 8 + rl;
                int bcol = k1 + (grp & 1) * 8;
                ldsm_x2(bf[ni][0], bf[ni][1], smem_u32(&Bh[brow][bcol]));
            }
#pragma unroll
            for (int mi = 0; mi < 4; mi++)
#pragma unroll
                for (int ni = 0; ni < 4; ni++)
                    mma_f16(c[mi][ni], af[mi][0], af[mi][1], af[mi][2], af[mi][3],
                            bf[ni][0], bf[ni][1]);
        }
        __syncthreads();
    }
    int qr = lane >> 2, qc = 2 * (lane & 3);
#pragma unroll
    for (int mi = 0; mi < 4; mi++) {
#pragma unroll
        for (int half = 0; half < 2; half++) {
            int row = wm + mi * 16 + qr + half * 8;
            int rr = row0 + row;
            if (rr < M) {
                uint16_t* Crow = (uint16_t*)jb.C + (size_t)rr * Nc;
#pragma unroll
                for (int ni = 0; ni < 4; ni++) {
                    int cc = col0 + wn + ni * 8 + qc;
                    *(uint32_t*)&Crow[cc] = f16x2(c[mi][ni][2 * half]     + __ldg(&jb.bias[cc]),
                                                  c[mi][ni][2 * half + 1] + __ldg(&jb.bias[cc + 1]));
                }
            }
        }
    }
}

// ---------------- gemmP: fp16 A direct, 128x128 tile, single pass ---------
__global__ __launch_bounds__(256)
void gemmP(const uint16_t* __restrict__ Ahg,
           const uint16_t* __restrict__ Bhg, const float* __restrict__ bias,
           float* __restrict__ C, int M, int K, int Nc) {
    __shared__ __align__(16) uint16_t Ah[128][40];
    __shared__ __align__(16) uint16_t Bh[128][40];
    int tid = threadIdx.x, lane = tid & 31, warp = tid >> 5;
    int row0 = blockIdx.y * 128, col0 = blockIdx.x * 128;
    int wm = (warp & 1) * 64, wn = (warp >> 1) * 32;
    int grp = lane >> 3, rl = lane & 7;
    float c[4][4][4];
#pragma unroll
    for (int mi = 0; mi < 4; mi++)
#pragma unroll
        for (int ni = 0; ni < 4; ni++)
#pragma unroll
            for (int e = 0; e < 4; e++) c[mi][ni][e] = 0.f;

    int ar = tid >> 1, kh = (tid & 1) * 16;
    int r = row0 + ar;
    bool va = r < M;
    uint4 z4 = make_uint4(0, 0, 0, 0);

    for (int k0 = 0; k0 < K; k0 += 32) {
        {
            const uint16_t* ph = Ahg + (size_t)r * K + k0 + kh;
            *(uint4*)&Ah[ar][kh]     = va ? *(const uint4*)ph : z4;
            *(uint4*)&Ah[ar][kh + 8] = va ? *(const uint4*)(ph + 8) : z4;
        }
        {
            const uint16_t* pbh = Bhg + (size_t)(col0 + ar) * K + k0 + kh;
            *(uint4*)&Bh[ar][kh]     = *(const uint4*)pbh;
            *(uint4*)&Bh[ar][kh + 8] = *(const uint4*)(pbh + 8);
        }
        __syncthreads();
#pragma unroll
        for (int k1 = 0; k1 < 32; k1 += 16) {
            uint32_t af[4][4], bf[4][2];
#pragma unroll
            for (int mi = 0; mi < 4; mi++) {
                int arow = wm + mi * 16 + (grp & 1) * 8 + rl;
                int acol = k1 + (grp >> 1) * 8;
                ldsm_x4(af[mi][0], af[mi][1], af[mi][2], af[mi][3],
                        smem_u32(&Ah[arow][acol]));
            }
#pragma unroll
            for (int ni = 0; ni < 4; ni++) {
                int brow = wn + ni * 8 + rl;
                int bcol = k1 + (grp & 1) * 8;
                ldsm_x2(bf[ni][0], bf[ni][1], smem_u32(&Bh[brow][bcol]));
            }
#pragma unroll
            for (int mi = 0; mi < 4; mi++)
#pragma unroll
                for (int ni = 0; ni < 4; ni++)
                    mma_f16(c[mi][ni], af[mi][0], af[mi][1], af[mi][2], af[mi][3],
                            bf[ni][0], bf[ni][1]);
        }
        __syncthreads();
    }
    int qr = lane >> 2, qc = 2 * (lane & 3);
#pragma unroll
    for (int mi = 0; mi < 4; mi++) {
#pragma unroll
        for (int half = 0; half < 2; half++) {
            int row = wm + mi * 16 + qr + half * 8;
            int rr = row0 + row;
            if (rr < M) {
                float* Crow = C + (size_t)rr * Nc;
#pragma unroll
                for (int ni = 0; ni < 4; ni++) {
                    int cc = col0 + wn + ni * 8 + qc;
                    float2 p;
                    p.x = c[mi][ni][2 * half]     + __ldg(&bias[cc]);
                    p.y = c[mi][ni][2 * half + 1] + __ldg(&bias[cc + 1]);
                    *(float2*)&Crow[cc] = p;
                }
            }
        }
    }
}

// ---------------- GAT layer 1: fused online-softmax, fp16 operands --------
__global__ void gat1_fused(const uint16_t* __restrict__ xlh,
                           const uint16_t* __restrict__ xrh,
                           const float* __restrict__ att, const float* __restrict__ bias,
                           float* __restrict__ out) {
    int t = blockIdx.x;
    int tid = threadIdx.x, lane = tid & 31, warp = tid >> 5;

    __shared__ float4 s_xr4[32], s_att4[32];
    __shared__ float  s_m[4], s_s[4];
    __shared__ float4 s_acc[4][32];
    if (tid < 32) {
        uint2 u = *(const uint2*)(xrh + (size_t)t * H1 + tid * 4);
        s_xr4[tid]  = h4_to_f4(u);
        s_att4[tid] = *(const float4*)(att + tid * 4);
    }
    int beg = g_rowptr[t];
    int deg = g_rowptr[t + 1] - beg;
    __syncthreads();

    float4 xr4 = s_xr4[lane];
    float4 at4 = s_att4[lane];

    float m0 = -1e30f, z0 = 0.f;
    float m1 = -1e30f, z1 = 0.f;
    float4 a0 = make_float4(0.f, 0.f, 0.f, 0.f), a1 = a0;

    int j = warp;
    for (; j + 4 < deg; j += 8) {
        int sA = g_srclist[beg + j];
        int sB = g_srclist[beg + j + 4];
        float4 vA = h4_to_f4(*(const uint2*)(xlh + (size_t)sA * H1 + lane * 4));
        float4 vB = h4_to_f4(*(const uint2*)(xlh + (size_t)sB * H1 + lane * 4));
        float pA, pB;
        {
            float a = vA.x + xr4.x; a = fmaxf(a, NEG_SLOPE * a);
            float b = vA.y + xr4.y; b = fmaxf(b, NEG_SLOPE * b);
            float c = vA.z + xr4.z; c = fmaxf(c, NEG_SLOPE * c);
            float d = vA.w + xr4.w; d = fmaxf(d, NEG_SLOPE * d);
            pA = at4.x * a + at4.y * b + at4.z * c + at4.w * d;
            a = vB.x + xr4.x; a = fmaxf(a, NEG_SLOPE * a);
            b = vB.y + xr4.y; b = fmaxf(b, NEG_SLOPE * b);
            c = vB.z + xr4.z; c = fmaxf(c, NEG_SLOPE * c);
            d = vB.w + xr4.w; d = fmaxf(d, NEG_SLOPE * d);
            pB = at4.x * a + at4.y * b + at4.z * c + at4.w * d;
        }
#pragma unroll
        for (int o = 16; o; o >>= 1) {
            pA += __shfl_xor_sync(0xffffffffu, pA, o);
            pB += __shfl_xor_sync(0xffffffffu, pB, o);
        }
        float mn0 = fmaxf(m0, pA);
        float sc0 = __expf(m0 - mn0);
        float w0  = __expf(pA - mn0);
        z0 = z0 * sc0 + w0;
        a0.x = a0.x * sc0 + w0 * vA.x;
        a0.y = a0.y * sc0 + w0 * vA.y;
        a0.z = a0.z * sc0 + w0 * vA.z;
        a0.w = a0.w * sc0 + w0 * vA.w;
        m0 = mn0;
        float mn1 = fmaxf(m1, pB);
        float sc1 = __expf(m1 - mn1);
        float w1  = __expf(pB - mn1);
        z1 = z1 * sc1 + w1;
        a1.x = a1.x * sc1 + w1 * vB.x;
        a1.y = a1.y * sc1 + w1 * vB.y;
        a1.z = a1.z * sc1 + w1 * vB.z;
        a1.w = a1.w * sc1 + w1 * vB.w;
        m1 = mn1;
    }
    if (j < deg) {
        int sA = g_srclist[beg + j];
        float4 vA = h4_to_f4(*(const uint2*)(xlh + (size_t)sA * H1 + lane * 4));
        float a = vA.x + xr4.x; a = fmaxf(a, NEG_SLOPE * a);
        float b = vA.y + xr4.y; b = fmaxf(b, NEG_SLOPE * b);
        float c = vA.z + xr4.z; c = fmaxf(c, NEG_SLOPE * c);
        float d = vA.w + xr4.w; d = fmaxf(d, NEG_SLOPE * d);
        float pA = at4.x * a + at4.y * b + at4.z * c + at4.w * d;
#pragma unroll
        for (int o = 16; o; o >>= 1) pA += __shfl_xor_sync(0xffffffffu, pA, o);
        float mn0 = fmaxf(m0, pA);
        float sc0 = __expf(m0 - mn0);
        float w0  = __expf(pA - mn0);
        z0 = z0 * sc0 + w0;
        a0.x = a0.x * sc0 + w0 * vA.x;
        a0.y = a0.y * sc0 + w0 * vA.y;
        a0.z = a0.z * sc0 + w0 * vA.z;
        a0.w = a0.w * sc0 + w0 * vA.w;
        m0 = mn0;
    }
    {
        float M = fmaxf(m0, m1);
        float e0 = __expf(m0 - M), e1 = __expf(m1 - M);
        z0 = z0 * e0 + z1 * e1;
        a0.x = a0.x * e0 + a1.x * e1;
        a0.y = a0.y * e0 + a1.y * e1;
        a0.z = a0.z * e0 + a1.z * e1;
        a0.w = a0.w * e0 + a1.w * e1;
        m0 = M;
    }
    if (lane == 0) { s_m[warp] = m0; s_s[warp] = z0; }
    s_acc[warp][lane] = a0;
    __syncthreads();

    if (tid < 32) {
        float M = s_m[0];
#pragma unroll
        for (int g = 1; g < 4; g++) M = fmaxf(M, s_m[g]);
        float zt = 0.f;
        float4 at = make_float4(0.f, 0.f, 0.f, 0.f);
#pragma unroll
        for (int g = 0; g < 4; g++) {
            float f = __expf(s_m[g] - M);
            zt += s_s[g] * f;
            float4 q = s_acc[g][tid];
            at.x += q.x * f; at.y += q.y * f; at.z += q.z * f; at.w += q.w * f;
        }
        float inv = 1.f / zt;
        float4 b4 = *(const float4*)(bias + tid * 4);
        float4 o4;
        o4.x = at.x * inv + b4.x;
        o4.y = at.y * inv + b4.y;
        o4.z = at.z * inv + b4.z;
        o4.w = at.w * inv + b4.w;
        *(float4*)(out + (size_t)t * H1 + tid * 4) = o4;
    }
}

// ---------------- GAT layers 2+3 merged + reparam, fp16 x23 ---------------
__global__ void gat23_fused(const uint16_t* __restrict__ x23,
                            const float* __restrict__ a2, const float* __restrict__ bias2,
                            const float* __restrict__ a3, const float* __restrict__ bias3,
                            const float* __restrict__ eps,
                            float* __restrict__ mu, float* __restrict__ lv,
                            float* __restrict__ emb) {
    int t = blockIdx.x;
    int tid = threadIdx.x, lane = tid & 31, warp = tid >> 5;
    int half = lane >> 4, lg = lane & 15;

    __shared__ float4 s_xr4[2][16], s_att4[2][16];
    __shared__ float  s_m[2][4], s_s[2][4];
    __shared__ float4 s_acc[2][4][16];
    if (tid < 32) {
        int h = tid >> 4, q = tid & 15;
        s_xr4[h][q]  = h4_to_f4(*(const uint2*)(x23 + (size_t)t * 256 + h * 128 + 64 + q * 4));
        s_att4[h][q] = *(const float4*)((h ? a3 : a2) + q * 4);
    }
    int beg = g_rowptr[t];
    int deg = g_rowptr[t + 1] - beg;
    __syncthreads();

    float4 xr4 = s_xr4[half][lg];
    float4 at4 = s_att4[half][lg];
    int coff = half * 128 + lg * 4;

    float m0 = -1e30f, z0 = 0.f;
    float m1 = -1e30f, z1 = 0.f;
    float4 a0 = make_float4(0.f, 0.f, 0.f, 0.f), a1 = a0;

    int j = warp;
    for (; j + 4 < deg; j += 8) {
        int sA = g_srclist[beg + j];
        int sB = g_srclist[beg + j + 4];
        float4 vA = h4_to_f4(*(const uint2*)(x23 + (size_t)sA * 256 + coff));
        float4 vB = h4_to_f4(*(const uint2*)(x23 + (size_t)sB * 256 + coff));
        float pA, pB;
        {
            float a = vA.x + xr4.x; a = fmaxf(a, NEG_SLOPE * a);
            float b = vA.y + xr4.y; b = fmaxf(b, NEG_SLOPE * b);
            float c = vA.z + xr4.z; c = fmaxf(c, NEG_SLOPE * c);
            float d = vA.w + xr4.w; d = fmaxf(d, NEG_SLOPE * d);
            pA = at4.x * a + at4.y * b + at4.z * c + at4.w * d;
            a = vB.x + xr4.x; a = fmaxf(a, NEG_SLOPE * a);
            b = vB.y + xr4.y; b = fmaxf(b, NEG_SLOPE * b);
            c = vB.z + xr4.z; c = fmaxf(c, NEG_SLOPE * c);
            d = vB.w + xr4.w; d = fmaxf(d, NEG_SLOPE * d);
            pB = at4.x * a + at4.y * b + at4.z * c + at4.w * d;
        }
#pragma unroll
        for (int o = 8; o; o >>= 1) {
            pA += __shfl_xor_sync(0xffffffffu, pA, o);
            pB += __shfl_xor_sync(0xffffffffu, pB, o);
        }
        float mn0 = fmaxf(m0, pA);
        float sc0 = __expf(m0 - mn0);
        float w0  = __expf(pA - mn0);
        z0 = z0 * sc0 + w0;
        a0.x = a0.x * sc0 + w0 * vA.x;
        a0.y = a0.y * sc0 + w0 * vA.y;
        a0.z = a0.z * sc0 + w0 * vA.z;
        a0.w = a0.w * sc0 + w0 * vA.w;
        m0 = mn0;
        float mn1 = fmaxf(m1, pB);
        float sc1 = __expf(m1 - mn1);
        float w1  = __expf(pB - mn1);
        z1 = z1 * sc1 + w1;
        a1.x = a1.x * sc1 + w1 * vB.x;
        a1.y = a1.y * sc1 + w1 * vB.y;
        a1.z = a1.z * sc1 + w1 * vB.z;
        a1.w = a1.w * sc1 + w1 * vB.w;
        m1 = mn1;
    }
    if (j < deg) {
        int sA = g_srclist[beg + j];
        float4 vA = h4_to_f4(*(const uint2*)(x23 + (size_t)sA * 256 + coff));
        float a = vA.x + xr4.x; a = fmaxf(a, NEG_SLOPE * a);
        float b = vA.y + xr4.y; b = fmaxf(b, NEG_SLOPE * b);
        float c = vA.z + xr4.z; c = fmaxf(c, NEG_SLOPE * c);
        float d = vA.w + xr4.w; d = fmaxf(d, NEG_SLOPE * d);
        float pA = at4.x * a + at4.y * b + at4.z * c + at4.w * d;
#pragma unroll
        for (int o = 8; o; o >>= 1) pA += __shfl_xor_sync(0xffffffffu, pA, o);
        float mn0 = fmaxf(m0, pA);
        float sc0 = __expf(m0 - mn0);
        float w0  = __expf(pA - mn0);
        z0 = z0 * sc0 + w0;
        a0.x = a0.x * sc0 + w0 * vA.x;
        a0.y = a0.y * sc0 + w0 * vA.y;
        a0.z = a0.z * sc0 + w0 * vA.z;
        a0.w = a0.w * sc0 + w0 * vA.w;
        m0 = mn0;
    }
    {
        float M = fmaxf(m0, m1);
        float e0 = __expf(m0 - M), e1 = __expf(m1 - M);
        z0 = z0 * e0 + z1 * e1;
        a0.x = a0.x * e0 + a1.x * e1;
        a0.y = a0.y * e0 + a1.y * e1;
        a0.z = a0.z * e0 + a1.z * e1;
        a0.w = a0.w * e0 + a1.w * e1;
        m0 = M;
    }
    if (lg == 0) { s_m[half][warp] = m0; s_s[half][warp] = z0; }
    s_acc[half][warp][lg] = a0;
    __syncthreads();

    if (tid < 32) {
        int h = tid >> 4, q = tid & 15;
        float M = s_m[h][0];
#pragma unroll
        for (int g = 1; g < 4; g++) M = fmaxf(M, s_m[h][g]);
        float zt = 0.f;
        float4 at = make_float4(0.f, 0.f, 0.f, 0.f);
#pragma unroll
        for (int g = 0; g < 4; g++) {
            float f = __expf(s_m[h][g] - M);
            zt += s_s[h][g] * f;
            float4 qq = s_acc[h][g][q];
            at.x += qq.x * f; at.y += qq.y * f; at.z += qq.z * f; at.w += qq.w * f;
        }
        float inv = 1.f / zt;
        float4 b4 = *(const float4*)((h ? bias3 : bias2) + q * 4);
        float4 o4;
        o4.x = at.x * inv + b4.x;
        o4.y = at.y * inv + b4.y;
        o4.z = at.z * inv + b4.z;
        o4.w = at.w * inv + b4.w;
        float* op = h ? lv : mu;
        *(float4*)(op + (size_t)t * 64 + q * 4) = o4;
        s_att4[h][q] = o4;
        __syncwarp();
        if (h == 0) {
            float4 mu4 = s_att4[0][q];
            float4 lv4 = s_att4[1][q];
            float4 e4 = *(const float4*)(eps + (size_t)t * 64 + q * 4);
            float4 em;
            em.x = e4.x * __expf(lv4.x) + mu4.x;
            em.y = e4.y * __expf(lv4.y) + mu4.y;
            em.z = e4.z * __expf(lv4.z) + mu4.z;
            em.w = e4.w * __expf(lv4.w) + mu4.w;
            *(float4*)(emb + (size_t)t * 64 + q * 4) = em;
            ushort4 vh;
            vh.x = f16h(em.x); vh.y = f16h(em.y);
            vh.z = f16h(em.z); vh.w = f16h(em.w);
            *(ushort4*)(g_ebh + (size_t)t * 64 + q * 4) = vh;
        }
    }
}

// ---------------- batch norm stats ----------------
template <int C>
__global__ void bn_stats(const float* __restrict__ h) {
    int c = blockIdx.x;
    int tid = threadIdx.x;
    float s = 0.f, s2 = 0.f;
    for (int r = tid; r < NN; r += 256) {
        float v = h[(size_t)r * C + c];
        s += v; s2 += v * v;
    }
    __shared__ float sh[8], sh2[8];
#pragma unroll
    for (int o = 16; o; o >>= 1) {
        s  += __shfl_xor_sync(0xffffffffu, s,  o);
        s2 += __shfl_xor_sync(0xffffffffu, s2, o);
    }
    if ((tid & 31) == 0) { sh[tid >> 5] = s; sh2[tid >> 5] = s2; }
    __syncthreads();
    if (tid == 0) {
        float ts = 0.f, ts2 = 0.f;
        for (int w = 0; w < 8; w++) { ts += sh[w]; ts2 += sh2[w]; }
        float mean = ts / NN;
        float var = ts2 / NN - mean * mean;
        g_mean[c] = mean;
        g_rstd[c] = rsqrtf(var + BN_EPS);
    }
}

// ---------------- readj = sigmoid(emb @ emb^T), fp16 single-pass HMMA -----
#define GP 72
#define G_AHI 0
#define G_BHI (G_AHI + 128 * GP * 2)
#define G_SMEM (G_BHI + 128 * GP * 2)   // 36864
#define MTG 79

__global__ __launch_bounds__(256)
void gram_hmma(const uint16_t* __restrict__ Eh, float* __restrict__ out) {
    int bid = blockIdx.x;
    int by = (int)(0.5f * (2.f * MTG + 1.f) -
                   sqrtf((2.f * MTG + 1.f) * (2.f * MTG + 1.f) * 0.25f - 2.f * (float)bid));
    if (by < 0) by = 0;
    if (by > MTG - 1) by = MTG - 1;
    int start = by * MTG - (by * (by - 1)) / 2;
    while (start > bid) { by--; start = by * MTG - (by * (by - 1)) / 2; }
    while (bid >= start + (MTG - by)) { by++; start = by * MTG - (by * (by - 1)) / 2; }
    int bx = by + (bid - start);

    extern __shared__ __align__(16) char smem[];
    uint32_t sb = smem_u32(smem);
    int tid = threadIdx.x, lane = tid & 31, warp = tid >> 5;
    int row0 = by * 128, col0 = bx * 128;

    {
        int rrow = tid & 127;
        uint4 z = make_uint4(0, 0, 0, 0);
        uint32_t base = (tid < 128) ? G_AHI : G_BHI;
        int rr = ((tid < 128) ? row0 : col0) + rrow;
        bool vr = rr < NN;
        const uint4* ph = (const uint4*)(Eh + (size_t)rr * 64);
#pragma unroll
        for (int q = 0; q < 8; q++) {
            uint32_t off = base + (rrow * GP + q * 8) * 2;
            *(uint4*)(smem + off) = vr ? ph[q] : z;
        }
    }
    __syncthreads();

    int wm = (warp & 1) * 64;
    int wn = (warp >> 1) * 32;
    float c[4][4][4];
#pragma unroll
    for (int mi = 0; mi < 4; mi++)
#pragma unroll
        for (int ni = 0; ni < 4; ni++)
#pragma unroll
            for (int e = 0; e < 4; e++) c[mi][ni][e] = 0.f;

    int grp = lane >> 3, rl = lane & 7;
#pragma unroll
    for (int k0 = 0; k0 < 64; k0 += 16) {
        uint32_t af[4][4], bf[4][2];
#pragma unroll
        for (int mi = 0; mi < 4; mi++) {
            int arow = wm + mi * 16 + (grp & 1) * 8 + rl;
            int acol = k0 + (grp >> 1) * 8;
            ldsm_x4(af[mi][0], af[mi][1], af[mi][2], af[mi][3],
                    sb + G_AHI + (arow * GP + acol) * 2);
        }
#pragma unroll
        for (int ni = 0; ni < 4; ni++) {
            int brow = wn + ni * 8 + rl;
            int bcol = k0 + (grp & 1) * 8;
            ldsm_x2(bf[ni][0], bf[ni][1], sb + G_BHI + (brow * GP + bcol) * 2);
        }
#pragma unroll
        for (int mi = 0; mi < 4; mi++)
#pragma unroll
            for (int ni = 0; ni < 4; ni++)
                mma_f16(c[mi][ni], af[mi][0], af[mi][1], af[mi][2], af[mi][3],
                        bf[ni][0], bf[ni][1]);
    }
    __syncthreads();

    bool diag = (bx == by);
    int qr = lane >> 2, qc = 2 * (lane & 3);
#pragma unroll
    for (int mi = 0; mi < 4; mi++) {
#pragma unroll
        for (int ni = 0; ni < 4; ni++) {
#pragma unroll
            for (int half = 0; half < 2; half++) {
                int row = wm + mi * 16 + qr + half * 8;
                int col = wn + ni * 8 + qc;
                float v0 = 1.f / (1.f + __expf(-c[mi][ni][2 * half]));
                float v1 = 1.f / (1.f + __expf(-c[mi][ni][2 * half + 1]));
                c[mi][ni][2 * half] = v0;
                c[mi][ni][2 * half + 1] = v1;
                int r = row0 + row, cc = col0 + col;
                if (r < NN && cc < NN)
                    *(float2*)(out + (size_t)r * NN + cc) = make_float2(v0, v1);
            }
        }
    }
    if (diag) return;

    float* stag = (float*)smem;
#pragma unroll
    for (int hIdx = 0; hIdx < 2; hIdx++) {
        __syncthreads();
        if ((warp & 1) == hIdx) {
#pragma unroll
            for (int mi = 0; mi < 4; mi++) {
#pragma unroll
                for (int ni = 0; ni < 4; ni++) {
#pragma unroll
                    for (int half = 0; half < 2; half++) {
                        int row = wm + mi * 16 + qr + half * 8;
                        int lrow = row & 63;
                        int col = wn + ni * 8 + qc;
                        int s = row & 31;
                        stag[lrow * 128 + (col ^ s)] = c[mi][ni][2 * half];
                        stag[lrow * 128 + ((col + 1) ^ s)] = c[mi][ni][2 * half + 1];
                    }
                }
            }
        }
        __syncthreads();
        for (int cc = warp; cc < 128; cc += 8) {
            int cgl = col0 + cc;
            if (cgl >= NN) continue;
            float* mrow = out + (size_t)cgl * NN + row0 + hIdx * 64;
#pragma unroll
            for (int ib = 0; ib < 64; ib += 32) {
                int i = ib + lane;
                int grow = hIdx * 64 + i;
                if (row0 + grow < NN)
                    mrow[i] = stag[i * 128 + (cc ^ (grow & 31))];
            }
        }
    }
}

// ---------------- launch ----------------
extern "C" void kernel_launch(void* const* d_in, const int* in_sizes, int n_in,
                              void* d_out, int out_size) {
    const float* x   = (const float*)d_in[0];
    const int*   ei  = (const int*)  d_in[1];
    const float* eps = (const float*)d_in[2];
    const float* w1l = (const float*)d_in[3];
    const float* b1l = (const float*)d_in[4];
    const float* w1r = (const float*)d_in[5];
    const float* b1r = (const float*)d_in[6];
    const float* a1  = (const float*)d_in[7];
    const float* bias1 = (const float*)d_in[8];
    const float* bn1_g = (const float*)d_in[9];
    const float* bn1_b = (const float*)d_in[10];
    const float* w2l = (const float*)d_in[11];
    const float* b2l = (const float*)d_in[12];
    const float* w2r = (const float*)d_in[13];
    const float* b2r = (const float*)d_in[14];
    const float* a2  = (const float*)d_in[15];
    const float* bias2 = (const float*)d_in[16];
    const float* w3l = (const float*)d_in[17];
    const float* b3l = (const float*)d_in[18];
    const float* w3r = (const float*)d_in[19];
    const float* b3r = (const float*)d_in[20];
    const float* a3  = (const float*)d_in[21];
    const float* bias3 = (const float*)d_in[22];
    const float* dw1 = (const float*)d_in[23];
    const float* db1 = (const float*)d_in[24];
    const float* dbn_g = (const float*)d_in[25];
    const float* dbn_b = (const float*)d_in[26];
    const float* dw2 = (const float*)d_in[27];
    const float* db2 = (const float*)d_in[28];
    float* out = (float*)d_out;

    float *p_h, *p_d, *p_b23;
    cudaGetSymbolAddress((void**)&p_h,   g_h);
    cudaGetSymbolAddress((void**)&p_d,   g_d);
    cudaGetSymbolAddress((void**)&p_b23, g_bias23);
    uint16_t *p_xl1h, *p_xr1h, *p_x23h, *p_w1lh, *p_w1rh, *p_w23h, *p_dw1h, *p_dw2h, *p_ebh;
    cudaGetSymbolAddress((void**)&p_xl1h, g_xl1h);
    cudaGetSymbolAddress((void**)&p_xr1h, g_xr1h);
    cudaGetSymbolAddress((void**)&p_x23h, g_x23h);
    cudaGetSymbolAddress((void**)&p_w1lh, g_w1lh);
    cudaGetSymbolAddress((void**)&p_w1rh, g_w1rh);
    cudaGetSymbolAddress((void**)&p_w23h, g_w23h);
    cudaGetSymbolAddress((void**)&p_dw1h, g_dw1h);
    cudaGetSymbolAddress((void**)&p_dw2h, g_dw2h);
    cudaGetSymbolAddress((void**)&p_ebh,  g_ebh);

    cudaFuncSetAttribute(gram_hmma, cudaFuncAttributeMaxDynamicSharedMemorySize, G_SMEM);

    static cudaStream_t s_side = nullptr;
    static cudaEvent_t evA = nullptr, evB = nullptr, evC = nullptr, evD = nullptr;
    if (!s_side) {
        cudaStreamCreateWithFlags(&s_side, cudaStreamNonBlocking);
        cudaEventCreateWithFlags(&evA, cudaEventDisableTiming);
        cudaEventCreateWithFlags(&evB, cudaEventDisableTiming);
        cudaEventCreateWithFlags(&evC, cudaEventDisableTiming);
        cudaEventCreateWithFlags(&evD, cudaEventDisableTiming);
    }

    const int MT  = (NN + 127) / 128;   // 79
    const int MT64 = (NN + 63) / 64;    // 157

    // ---- fork: CSR build on side stream ----
    cudaEventRecord(evA, 0);
    cudaStreamWaitEvent(s_side, evA, 0);
    k_zero_counts<<<(NN + 255) / 256, 256, 0, s_side>>>();
    k_count_deg<<<(NE + 255) / 256, 256, 0, s_side>>>(ei);
    k_scan_deg<<<1, 1024, 0, s_side>>>();
    k_fill_list<<<(NE + 255) / 256, 256, 0, s_side>>>(ei);
    cudaEventRecord(evB, s_side);

    // ---- main: fused prep + dual-job layer-1 GEMM (shared A, fp16 out) ----
    k_prep<<<(P_TOT + 255) / 256, 256>>>(w1l, w1r, w2l, w2r, w3l, w3r, dw1, dw2,
                                         b2l, b2r, b3l, b3r);
    {
        TJobs j1 = {{ { p_w1lh, b1l, (float*)p_xl1h }, { p_w1rh, b1r, (float*)p_xr1h } }};
        gemmDual<<<dim3(1, MT64, 1), 256>>>(x, j1, NN, NFEAT);
    }
    cudaStreamWaitEvent(0, evB, 0);   // join CSR

    // ---- GAT layer 1 (fp16 gather, fused online softmax) -> BN stats ----
    gat1_fused<<<NN, 128>>>(p_xl1h, p_xr1h, a1, bias1, p_h);
    bn_stats<H1><<<H1, 256>>>(p_h);

    // ---- layers 2 & 3 packed GEMM (BN+ReLU fused, fp16 output) ----
    {
        TJobs j2 = {{ { p_w23h, p_b23, (float*)p_x23h }, {} }};
        gemmTh<<<dim3(2, MT, 1), 256>>>(p_h, j2, NN, H1, 256, bn1_g, bn1_b);
    }

    // ---- GAT layers 2+3 merged + fused reparameterize (fp16 gather) ----
    gat23_fused<<<NN, 128>>>(p_x23h, a2, bias2, a3, bias3, eps,
                             out + MU_OFF, out + LV_OFF, out + EMB_OFF);

    // ---- fork: decoder MLP on side stream, gram on main ----
    cudaEventRecord(evC, 0);
    cudaStreamWaitEvent(s_side, evC, 0);
    gemmP<<<dim3(2, MT, 1), 256, 0, s_side>>>(p_ebh, p_dw1h, db1, p_d,
                                              NN, NHID2, NHID1);
    bn_stats<NHID1><<<NHID1, 256, 0, s_side>>>(p_d);
    {
        TJobs jd = {{ { p_dw2h, db2, out + REX_OFF }, {} }};
        gemmT<<<dim3(4, MT, 1), 256, 0, s_side>>>(p_d, jd, NN, NHID1, NFEAT,
                                                  dbn_g, dbn_b);
    }
    cudaEventRecord(evD, s_side);

    gram_hmma<<<MT * (MT + 1) / 2, 256, G_SMEM>>>(p_ebh, out + READJ_OFF);

    cudaStreamWaitEvent(0, evD, 0);   // join decoder
}